// round 1
// baseline (speedup 1.0000x reference)
#include <cuda_runtime.h>
#include <math.h>

#define SQ    2048
#define HID   4096
#define NH    32
#define NKV   8
#define HD    128
#define QDIM  (NH*HD)    // 4096
#define KVDIM (NKV*HD)   // 1024

// ---------------- scratch (static device allocation, allowed) ----------------
__device__ float g_Q[SQ * QDIM];    // 32 MB
__device__ float g_K[SQ * KVDIM];   // 8 MB
__device__ float g_V[SQ * KVDIM];   // 8 MB
__device__ float g_AO[SQ * QDIM];   // 32 MB

// ---------------- SIMT SGEMM: C[M,N] = A[M,K] @ B[K,N], all row-major --------
// 128x128 block tile, BK=8, 256 threads, 8x8 per-thread tile.
// Requires M%128==0, N%128==0, K%8==0 (true for all shapes here).
__global__ __launch_bounds__(256) void sgemm128(
    const float* __restrict__ A, const float* __restrict__ B,
    float* __restrict__ C, int M, int N, int K)
{
    __shared__ float As[8][128];
    __shared__ float Bs[8][128];

    const int tid = threadIdx.x;
    const int bx = blockIdx.x, by = blockIdx.y;

    const int arow = tid >> 1;          // 0..127
    const int acol = (tid & 1) * 4;     // 0 or 4
    const int brow = tid >> 5;          // 0..7
    const int bcol = (tid & 31) * 4;    // 0..124
    const int ty = tid >> 4;            // 0..15
    const int tx = tid & 15;            // 0..15

    const float* Ag = A + (size_t)(by * 128 + arow) * K + acol;
    const float* Bg = B + (size_t)brow * N + bx * 128 + bcol;

    float acc[8][8];
#pragma unroll
    for (int i = 0; i < 8; ++i)
#pragma unroll
        for (int j = 0; j < 8; ++j) acc[i][j] = 0.f;

    for (int k0 = 0; k0 < K; k0 += 8) {
        float4 a4 = *(const float4*)(Ag + k0);
        float4 b4 = *(const float4*)(Bg + (size_t)k0 * N);
        As[acol + 0][arow] = a4.x;
        As[acol + 1][arow] = a4.y;
        As[acol + 2][arow] = a4.z;
        As[acol + 3][arow] = a4.w;
        *(float4*)&Bs[brow][bcol] = b4;
        __syncthreads();

#pragma unroll
        for (int k = 0; k < 8; ++k) {
            float ra[8], rb[8];
            *(float4*)&ra[0] = *(const float4*)&As[k][ty * 8];
            *(float4*)&ra[4] = *(const float4*)&As[k][ty * 8 + 4];
            *(float4*)&rb[0] = *(const float4*)&Bs[k][tx * 8];
            *(float4*)&rb[4] = *(const float4*)&Bs[k][tx * 8 + 4];
#pragma unroll
            for (int i = 0; i < 8; ++i)
#pragma unroll
                for (int j = 0; j < 8; ++j)
                    acc[i][j] += ra[i] * rb[j];
        }
        __syncthreads();
    }

    float* Cg = C + (size_t)(by * 128 + ty * 8) * N + bx * 128 + tx * 8;
#pragma unroll
    for (int i = 0; i < 8; ++i) {
        *(float4*)(Cg + (size_t)i * N)     = make_float4(acc[i][0], acc[i][1], acc[i][2], acc[i][3]);
        *(float4*)(Cg + (size_t)i * N + 4) = make_float4(acc[i][4], acc[i][5], acc[i][6], acc[i][7]);
    }
}

// ---------------- RoPE (in-place on Q and K) ----------------
__global__ __launch_bounds__(256) void rope_kernel(
    float* __restrict__ Q, float* __restrict__ K, const int* __restrict__ pos_ids)
{
    const int s = blockIdx.x;
    __shared__ float cs[64], sn[64];
    if (threadIdx.x < 64) {
        // inv_freq = 10000^(-i/64), computed exactly in double; angle rounded to
        // fp32 before sincos (matches reference's fp32 product rounding).
        double invf = exp(-(double)threadIdx.x * (9.210340371976184 / 64.0));
        float ang = (float)((double)pos_ids[s] * invf);
        float c, si;
        sincosf(ang, &si, &c);
        cs[threadIdx.x] = c;
        sn[threadIdx.x] = si;
    }
    __syncthreads();

    // Q: 32 heads * 64 pairs = 2048 pairs
#pragma unroll
    for (int it = 0; it < 8; ++it) {
        int pp = threadIdx.x + it * 256;
        int head = pp >> 6, i = pp & 63;
        float* b = Q + (size_t)s * QDIM + head * HD + i;
        float x0 = b[0], x1 = b[64];
        float c = cs[i], si = sn[i];
        b[0]  = x0 * c - x1 * si;
        b[64] = x1 * c + x0 * si;
    }
    // K: 8 heads * 64 pairs = 512 pairs
#pragma unroll
    for (int it = 0; it < 2; ++it) {
        int pp = threadIdx.x + it * 256;
        int head = pp >> 6, i = pp & 63;
        float* b = K + (size_t)s * KVDIM + head * HD + i;
        float x0 = b[0], x1 = b[64];
        float c = cs[i], si = sn[i];
        b[0]  = x0 * c - x1 * si;
        b[64] = x1 * c + x0 * si;
    }
}

// ---------------- fused causal flash attention ----------------
// grid = (32 q-tiles, 32 heads), 256 threads.
// Per thread: 4 q-rows x 4 score-cols (S phase), 4 q-rows x 8 d-cols (PV phase).
// K tile stored transposed with a 16B-group XOR swizzle (conflict-light both
// for the transpose stores and the float4 score reads).
__global__ __launch_bounds__(256, 2) void attn_kernel(
    const float* __restrict__ Q, const float* __restrict__ Kg,
    const float* __restrict__ Vg, const float* __restrict__ mask,
    float* __restrict__ AO)
{
    extern __shared__ float smbuf[];
    float* Qs  = smbuf;          // [64][132]  = 8448 floats
    float* KVb = smbuf + 8448;   // KT swz [128][64] (8192) or V [64][132] (8448)
    float* Ps  = smbuf + 16896;  // [64][68]   = 4352 floats

    const int tid = threadIdx.x;
    const int h   = blockIdx.y;
    const int qt  = blockIdx.x;
    const int q0  = qt * 64;
    const int kh  = h >> 2;                 // GQA: jnp.repeat -> kv head = h/4
    const float scale = 0.08838834764831845f;  // 1/sqrt(128)

    // load Q tile, pre-scaled
#pragma unroll
    for (int it = 0; it < 8; ++it) {
        int id = tid + it * 256;            // 2048 float4
        int r  = id >> 5;
        int c4 = (id & 31) << 2;
        float4 q4 = *(const float4*)(Q + (size_t)(q0 + r) * QDIM + h * HD + c4);
        q4.x *= scale; q4.y *= scale; q4.z *= scale; q4.w *= scale;
        *(float4*)(Qs + r * 132 + c4) = q4;
    }

    const int rg = tid >> 4;
    const int cg = tid & 15;
    const int rr = rg << 2;
    const int dc = cg << 3;

    float m[4], l[4], O[4][8];
#pragma unroll
    for (int i = 0; i < 4; ++i) {
        m[i] = -1e30f; l[i] = 0.f;
#pragma unroll
        for (int j = 0; j < 8; ++j) O[i][j] = 0.f;
    }

    for (int kt = 0; kt <= qt; ++kt) {
        const int k0 = kt * 64;

        // ---- load K tile transposed + swizzled: KT(d,j) at d*64 + 4*((j>>2)^((d>>2)&15)) + (j&3)
#pragma unroll
        for (int it = 0; it < 8; ++it) {
            int id = tid + it * 256;
            int j  = id >> 5;
            int d4 = (id & 31) << 2;
            float4 k4 = *(const float4*)(Kg + (size_t)(k0 + j) * KVDIM + kh * HD + d4);
            int xg = (((j >> 2) ^ (id & 15)) << 2) + (j & 3);
            KVb[(d4 + 0) * 64 + xg] = k4.x;
            KVb[(d4 + 1) * 64 + xg] = k4.y;
            KVb[(d4 + 2) * 64 + xg] = k4.z;
            KVb[(d4 + 3) * 64 + xg] = k4.w;
        }
        __syncthreads();

        // ---- scores initialized from the additive mask (covers causal + scale via pre-scaled Q)
        float s[4][4];
#pragma unroll
        for (int i = 0; i < 4; ++i)
#pragma unroll
            for (int j = 0; j < 4; ++j)
                s[i][j] = mask[(size_t)(q0 + rr + i) * SQ + k0 + (cg << 2) + j];

        const float* q0p = Qs + (rr + 0) * 132;
        const float* q1p = Qs + (rr + 1) * 132;
        const float* q2p = Qs + (rr + 2) * 132;
        const float* q3p = Qs + (rr + 3) * 132;

#pragma unroll 8
        for (int d4 = 0; d4 < 128; d4 += 4) {
            int g = (((d4 >> 2) & 15) ^ cg) << 2;
#pragma unroll
            for (int dd = 0; dd < 4; ++dd) {
                int d = d4 + dd;
                float4 kv = *(const float4*)(KVb + d * 64 + g);
                float qv0 = q0p[d], qv1 = q1p[d], qv2 = q2p[d], qv3 = q3p[d];
                s[0][0] += qv0 * kv.x; s[0][1] += qv0 * kv.y; s[0][2] += qv0 * kv.z; s[0][3] += qv0 * kv.w;
                s[1][0] += qv1 * kv.x; s[1][1] += qv1 * kv.y; s[1][2] += qv1 * kv.z; s[1][3] += qv1 * kv.w;
                s[2][0] += qv2 * kv.x; s[2][1] += qv2 * kv.y; s[2][2] += qv2 * kv.z; s[2][3] += qv2 * kv.w;
                s[3][0] += qv3 * kv.x; s[3][1] += qv3 * kv.y; s[3][2] += qv3 * kv.z; s[3][3] += qv3 * kv.w;
            }
        }

        // ---- online softmax (row stats across the 16 cg-threads of each rg group)
#pragma unroll
        for (int i = 0; i < 4; ++i) {
            float v = fmaxf(fmaxf(s[i][0], s[i][1]), fmaxf(s[i][2], s[i][3]));
            v = fmaxf(v, __shfl_xor_sync(0xffffffffu, v, 1));
            v = fmaxf(v, __shfl_xor_sync(0xffffffffu, v, 2));
            v = fmaxf(v, __shfl_xor_sync(0xffffffffu, v, 4));
            v = fmaxf(v, __shfl_xor_sync(0xffffffffu, v, 8));
            float nm = fmaxf(m[i], v);
            float c  = __expf(m[i] - nm);
            m[i] = nm;
            float rs = 0.f;
#pragma unroll
            for (int j = 0; j < 4; ++j) { s[i][j] = __expf(s[i][j] - nm); rs += s[i][j]; }
            rs += __shfl_xor_sync(0xffffffffu, rs, 1);
            rs += __shfl_xor_sync(0xffffffffu, rs, 2);
            rs += __shfl_xor_sync(0xffffffffu, rs, 4);
            rs += __shfl_xor_sync(0xffffffffu, rs, 8);
            l[i] = l[i] * c + rs;
#pragma unroll
            for (int j = 0; j < 8; ++j) O[i][j] *= c;
        }

        // ---- write P to smem
#pragma unroll
        for (int i = 0; i < 4; ++i)
#pragma unroll
            for (int j = 0; j < 4; ++j)
                Ps[(rr + i) * 68 + (cg << 2) + j] = s[i][j];
        __syncthreads();

        // ---- load V tile (natural layout) into the same buffer
#pragma unroll
        for (int it = 0; it < 8; ++it) {
            int id = tid + it * 256;
            int r  = id >> 5;
            int c4 = (id & 31) << 2;
            *(float4*)(KVb + r * 132 + c4) =
                *(const float4*)(Vg + (size_t)(k0 + r) * KVDIM + kh * HD + c4);
        }
        __syncthreads();

        // ---- O += P @ V
#pragma unroll 4
        for (int k = 0; k < 64; ++k) {
            float4 v0 = *(const float4*)(KVb + k * 132 + dc);
            float4 v1 = *(const float4*)(KVb + k * 132 + dc + 4);
#pragma unroll
            for (int i = 0; i < 4; ++i) {
                float p = Ps[(rr + i) * 68 + k];
                O[i][0] += p * v0.x; O[i][1] += p * v0.y; O[i][2] += p * v0.z; O[i][3] += p * v0.w;
                O[i][4] += p * v1.x; O[i][5] += p * v1.y; O[i][6] += p * v1.z; O[i][7] += p * v1.w;
            }
        }
        __syncthreads();
    }

    // ---- normalize and write out, layout (s, h*128 + d)
#pragma unroll
    for (int i = 0; i < 4; ++i) {
        float inv = 1.f / l[i];
        float* op = AO + (size_t)(q0 + rr + i) * QDIM + h * HD + dc;
        *(float4*)op       = make_float4(O[i][0]*inv, O[i][1]*inv, O[i][2]*inv, O[i][3]*inv);
        *(float4*)(op + 4) = make_float4(O[i][4]*inv, O[i][5]*inv, O[i][6]*inv, O[i][7]*inv);
    }
}

// ---------------- launch ----------------
extern "C" void kernel_launch(void* const* d_in, const int* in_sizes, int n_in,
                              void* d_out, int out_size)
{
    const float* hs   = (const float*)d_in[0];
    const float* mask = (const float*)d_in[1];
    const int*   pos  = (const int*)d_in[2];
    const float* Wq   = (const float*)d_in[3];
    const float* Wk   = (const float*)d_in[4];
    const float* Wv   = (const float*)d_in[5];
    const float* Wo   = (const float*)d_in[6];
    float* out = (float*)d_out;

    float *qp, *kp, *vp, *aop;
    cudaGetSymbolAddress((void**)&qp,  g_Q);
    cudaGetSymbolAddress((void**)&kp,  g_K);
    cudaGetSymbolAddress((void**)&vp,  g_V);
    cudaGetSymbolAddress((void**)&aop, g_AO);

    const size_t attn_smem = (8448 + 8448 + 4352) * sizeof(float);  // 84992 B
    cudaFuncSetAttribute(attn_kernel, cudaFuncAttributeMaxDynamicSharedMemorySize,
                         (int)attn_smem);

    // QKV projections
    sgemm128<<<dim3(QDIM / 128, SQ / 128), 256>>>(hs, Wq, qp, SQ, QDIM, HID);
    sgemm128<<<dim3(KVDIM / 128, SQ / 128), 256>>>(hs, Wk, kp, SQ, KVDIM, HID);
    sgemm128<<<dim3(KVDIM / 128, SQ / 128), 256>>>(hs, Wv, vp, SQ, KVDIM, HID);

    // RoPE in place
    rope_kernel<<<SQ, 256>>>(qp, kp, pos);

    // fused causal attention
    attn_kernel<<<dim3(SQ / 64, NH), 256, attn_smem>>>(qp, kp, vp, mask, aop);

    // output projection straight to d_out
    sgemm128<<<dim3(HID / 128, SQ / 128), 256>>>(aop, Wo, out, SQ, HID, QDIM);
}

// round 3
// speedup vs baseline: 2.0619x; 2.0619x over previous
#include <cuda_runtime.h>
#include <cuda_bf16.h>
#include <math.h>
#include <cstdint>

#define SQ    2048
#define HID   4096
#define NH    32
#define NKV   8
#define HD    128
#define QDIM  (NH*HD)    // 4096
#define KVDIM (NKV*HD)   // 1024

// ---------------- scratch (static device allocations) ----------------
__device__ float g_Q [SQ * QDIM];
__device__ float g_K [SQ * KVDIM];
__device__ float g_V [SQ * KVDIM];
__device__ float g_AO[SQ * QDIM];

__device__ __nv_bfloat16 g_Ah [SQ * HID];
__device__ __nv_bfloat16 g_Al [SQ * HID];
__device__ __nv_bfloat16 g_AOh[SQ * QDIM];
__device__ __nv_bfloat16 g_AOl[SQ * QDIM];

__device__ __nv_bfloat16 g_WqTh[QDIM * HID];
__device__ __nv_bfloat16 g_WqTl[QDIM * HID];
__device__ __nv_bfloat16 g_WkTh[KVDIM * HID];
__device__ __nv_bfloat16 g_WkTl[KVDIM * HID];
__device__ __nv_bfloat16 g_WvTh[KVDIM * HID];
__device__ __nv_bfloat16 g_WvTl[KVDIM * HID];
__device__ __nv_bfloat16 g_WoTh[HID * QDIM];
__device__ __nv_bfloat16 g_WoTl[HID * QDIM];

// ---------------- PTX helpers (sm_80-era instructions only) ----------------
__device__ __forceinline__ uint32_t smem_u32(const void* p) {
    uint32_t a;
    asm("{ .reg .u64 t; cvta.to.shared.u64 t, %1; cvt.u32.u64 %0, t; }" : "=r"(a) : "l"(p));
    return a;
}

__device__ __forceinline__ void cpa16(uint32_t dst, const void* src) {
    asm volatile("cp.async.cg.shared.global [%0], [%1], 16;" :: "r"(dst), "l"(src) : "memory");
}
#define CP_COMMIT() asm volatile("cp.async.commit_group;" ::: "memory")
#define CP_WAIT1()  asm volatile("cp.async.wait_group 1;" ::: "memory")
#define CP_WAIT0()  asm volatile("cp.async.wait_group 0;" ::: "memory")

__device__ __forceinline__ void ldsm_x4(uint32_t& r0, uint32_t& r1, uint32_t& r2, uint32_t& r3,
                                        uint32_t addr) {
    asm volatile("ldmatrix.sync.aligned.m8n8.x4.shared.b16 {%0,%1,%2,%3}, [%4];"
                 : "=r"(r0), "=r"(r1), "=r"(r2), "=r"(r3) : "r"(addr));
}

__device__ __forceinline__ void mma_bf16(float& d0, float& d1, float& d2, float& d3,
                                         uint32_t a0, uint32_t a1, uint32_t a2, uint32_t a3,
                                         uint32_t b0, uint32_t b1) {
    asm volatile("mma.sync.aligned.m16n8k16.row.col.f32.bf16.bf16.f32 "
                 "{%0,%1,%2,%3}, {%4,%5,%6,%7}, {%8,%9}, {%0,%1,%2,%3};"
                 : "+f"(d0), "+f"(d1), "+f"(d2), "+f"(d3)
                 : "r"(a0), "r"(a1), "r"(a2), "r"(a3), "r"(b0), "r"(b1));
}

// ---------------- fp32 -> bf16 hi/lo split (elementwise) ----------------
__global__ __launch_bounds__(256) void split_plain(
    const float* __restrict__ X, __nv_bfloat16* __restrict__ H,
    __nv_bfloat16* __restrict__ L, int n2)
{
    int i = blockIdx.x * 256 + threadIdx.x;
    if (i >= n2) return;
    float2 a = ((const float2*)X)[i];
    __nv_bfloat16 hx = __float2bfloat16(a.x);
    __nv_bfloat16 hy = __float2bfloat16(a.y);
    __nv_bfloat162 h; h.x = hx; h.y = hy;
    __nv_bfloat162 l;
    l.x = __float2bfloat16(a.x - __bfloat162float(hx));
    l.y = __float2bfloat16(a.y - __bfloat162float(hy));
    ((__nv_bfloat162*)H)[i] = h;
    ((__nv_bfloat162*)L)[i] = l;
}

// ---------------- fp32 W[K,N] -> bf16 hi/lo transposed [N,K] ----------------
__global__ __launch_bounds__(256) void split_transpose(
    const float* __restrict__ W, __nv_bfloat16* __restrict__ HT,
    __nv_bfloat16* __restrict__ LT, int K, int N)
{
    __shared__ float t[32][33];
    int n0 = blockIdx.x * 32, k0 = blockIdx.y * 32;
    int tx = threadIdx.x & 31, ty = threadIdx.x >> 5;  // 32 x 8
#pragma unroll
    for (int i = 0; i < 4; ++i) {
        int ky = ty + i * 8;
        t[ky][tx] = W[(size_t)(k0 + ky) * N + n0 + tx];
    }
    __syncthreads();
#pragma unroll
    for (int i = 0; i < 4; ++i) {
        int ny = ty + i * 8;
        float a = t[tx][ny];
        __nv_bfloat16 h = __float2bfloat16(a);
        float r = a - __bfloat162float(h);
        HT[(size_t)(n0 + ny) * K + k0 + tx] = h;
        LT[(size_t)(n0 + ny) * K + k0 + tx] = __float2bfloat16(r);
    }
}

// ---------------- HMMA bf16x3 GEMM ----------------
// C[M,N] fp32 = (Ah+Al)[M,K] @ (Bh+Bl)[N,K]^T  (Al*Bl dropped)
// CTA tile 128x128, 8 warps (warp tile 64x32), k-chunk 32, 3-stage cp.async.
// SMEM tile layout: bf16 [128][32], 16B groups XOR-swizzled: c8' = c8 ^ ((r>>1)&3)
#define SWZ_OFF(r, c8) ((r) * 64 + (((c8) ^ (((r) >> 1) & 3)) << 4))

__global__ __launch_bounds__(256, 1) void gemm_hmma_x3(
    const __nv_bfloat16* __restrict__ Ah, const __nv_bfloat16* __restrict__ Al,
    const __nv_bfloat16* __restrict__ Bh, const __nv_bfloat16* __restrict__ Bl,
    float* __restrict__ C, int M, int N, int K)
{
    extern __shared__ char smem[];
    constexpr int TILE  = 128 * 32 * 2;   // 8192 B per matrix
    constexpr int STAGE = 4 * TILE;       // Ah, Al, Bh, Bl = 32 KB
    const uint32_t sb = smem_u32(smem);

    const int tid  = threadIdx.x;
    const int wid  = tid >> 5;
    const int lane = tid & 31;
    const int m0 = blockIdx.y * 128;
    const int n0 = blockIdx.x * 128;
    const int wm = (wid >> 2) * 64;      // warp m offset in tile (0 or 64)
    const int wn = (wid & 3) * 32;       // warp n offset in tile (0..96)
    const int nk = K >> 5;               // number of 32-wide k chunks

    // per-lane ldmatrix address components
    const int rl = lane & 15;
    const int ch = lane >> 4;

    float acc[4][4][4];
#pragma unroll
    for (int i = 0; i < 4; ++i)
#pragma unroll
        for (int j = 0; j < 4; ++j)
#pragma unroll
            for (int q = 0; q < 4; ++q) acc[i][j][q] = 0.f;

    // stage loader: 16B cp.async x8 per thread
    auto load_stage = [&](int c, int s) {
        const int kb = c * 32;
        const uint32_t st = sb + s * STAGE;
#pragma unroll
        for (int i = 0; i < 2; ++i) {
            int id = tid + i * 256;
            int r = id >> 2, c8 = id & 3;
            uint32_t off = SWZ_OFF(r, c8);
            cpa16(st + off,            Ah + (size_t)(m0 + r) * K + kb + c8 * 8);
            cpa16(st + TILE + off,     Al + (size_t)(m0 + r) * K + kb + c8 * 8);
            cpa16(st + 2 * TILE + off, Bh + (size_t)(n0 + r) * K + kb + c8 * 8);
            cpa16(st + 3 * TILE + off, Bl + (size_t)(n0 + r) * K + kb + c8 * 8);
        }
        CP_COMMIT();
    };

    load_stage(0, 0);
    if (nk > 1) load_stage(1, 1);

    for (int c = 0; c < nk; ++c) {
        if (c + 1 < nk) { CP_WAIT1(); } else { CP_WAIT0(); }
        __syncthreads();
        if (c + 2 < nk) load_stage(c + 2, (c + 2) % 3);

        const uint32_t st = sb + (c % 3) * STAGE;
#pragma unroll
        for (int ks = 0; ks < 2; ++ks) {
            uint32_t ahf[4][4], alf[4][4], bhf[2][4], blf[2][4];
#pragma unroll
            for (int mt = 0; mt < 4; ++mt) {
                int r = wm + mt * 16 + rl;
                int c8 = 2 * ks + ch;
                uint32_t off = SWZ_OFF(r, c8);
                ldsm_x4(ahf[mt][0], ahf[mt][1], ahf[mt][2], ahf[mt][3], st + off);
                ldsm_x4(alf[mt][0], alf[mt][1], alf[mt][2], alf[mt][3], st + TILE + off);
            }
#pragma unroll
            for (int np = 0; np < 2; ++np) {
                int r = wn + np * 16 + rl;
                int c8 = 2 * ks + ch;
                uint32_t off = SWZ_OFF(r, c8);
                ldsm_x4(bhf[np][0], bhf[np][1], bhf[np][2], bhf[np][3], st + 2 * TILE + off);
                ldsm_x4(blf[np][0], blf[np][1], blf[np][2], blf[np][3], st + 3 * TILE + off);
            }
#pragma unroll
            for (int mt = 0; mt < 4; ++mt) {
#pragma unroll
                for (int nt = 0; nt < 4; ++nt) {
                    const int np = nt >> 1, sel = nt & 1;
                    float* d = acc[mt][nt];
                    // hi*hi
                    mma_bf16(d[0], d[1], d[2], d[3],
                             ahf[mt][0], ahf[mt][1], ahf[mt][2], ahf[mt][3],
                             bhf[np][sel], bhf[np][2 + sel]);
                    // hi*lo
                    mma_bf16(d[0], d[1], d[2], d[3],
                             ahf[mt][0], ahf[mt][1], ahf[mt][2], ahf[mt][3],
                             blf[np][sel], blf[np][2 + sel]);
                    // lo*hi
                    mma_bf16(d[0], d[1], d[2], d[3],
                             alf[mt][0], alf[mt][1], alf[mt][2], alf[mt][3],
                             bhf[np][sel], bhf[np][2 + sel]);
                }
            }
        }
        __syncthreads();
    }

    // epilogue: direct stores (acc layout: row = lane>>2 (+8), col = (lane&3)*2)
#pragma unroll
    for (int mt = 0; mt < 4; ++mt) {
#pragma unroll
        for (int nt = 0; nt < 4; ++nt) {
            int rg = m0 + wm + mt * 16 + (lane >> 2);
            int cg = n0 + wn + nt * 8 + (lane & 3) * 2;
            float* d = acc[mt][nt];
            *(float2*)(C + (size_t)rg * N + cg)       = make_float2(d[0], d[1]);
            *(float2*)(C + (size_t)(rg + 8) * N + cg) = make_float2(d[2], d[3]);
        }
    }
}

// ---------------- RoPE (in-place on Q and K) ----------------
__global__ __launch_bounds__(256) void rope_kernel(
    float* __restrict__ Q, float* __restrict__ K, const int* __restrict__ pos_ids)
{
    const int s = blockIdx.x;
    __shared__ float cs[64], sn[64];
    if (threadIdx.x < 64) {
        double invf = exp(-(double)threadIdx.x * (9.210340371976184 / 64.0));
        float ang = (float)((double)pos_ids[s] * invf);
        float c, si;
        sincosf(ang, &si, &c);
        cs[threadIdx.x] = c;
        sn[threadIdx.x] = si;
    }
    __syncthreads();
#pragma unroll
    for (int it = 0; it < 8; ++it) {
        int pp = threadIdx.x + it * 256;
        int head = pp >> 6, i = pp & 63;
        float* b = Q + (size_t)s * QDIM + head * HD + i;
        float x0 = b[0], x1 = b[64];
        float c = cs[i], si = sn[i];
        b[0]  = x0 * c - x1 * si;
        b[64] = x1 * c + x0 * si;
    }
#pragma unroll
    for (int it = 0; it < 2; ++it) {
        int pp = threadIdx.x + it * 256;
        int head = pp >> 6, i = pp & 63;
        float* b = K + (size_t)s * KVDIM + head * HD + i;
        float x0 = b[0], x1 = b[64];
        float c = cs[i], si = sn[i];
        b[0]  = x0 * c - x1 * si;
        b[64] = x1 * c + x0 * si;
    }
}

// ---------------- fused causal flash attention (SIMT fp32) ----------------
__global__ __launch_bounds__(256, 2) void attn_kernel(
    const float* __restrict__ Q, const float* __restrict__ Kg,
    const float* __restrict__ Vg, const float* __restrict__ mask,
    float* __restrict__ AO)
{
    extern __shared__ float smbuf[];
    float* Qs  = smbuf;
    float* KVb = smbuf + 8448;
    float* Ps  = smbuf + 16896;

    const int tid = threadIdx.x;
    const int h   = blockIdx.y;
    const int qt  = blockIdx.x;
    const int q0  = qt * 64;
    const int kh  = h >> 2;
    const float scale = 0.08838834764831845f;

#pragma unroll
    for (int it = 0; it < 8; ++it) {
        int id = tid + it * 256;
        int r  = id >> 5;
        int c4 = (id & 31) << 2;
        float4 q4 = *(const float4*)(Q + (size_t)(q0 + r) * QDIM + h * HD + c4);
        q4.x *= scale; q4.y *= scale; q4.z *= scale; q4.w *= scale;
        *(float4*)(Qs + r * 132 + c4) = q4;
    }

    const int rg = tid >> 4;
    const int cg = tid & 15;
    const int rr = rg << 2;
    const int dc = cg << 3;

    float m[4], l[4], O[4][8];
#pragma unroll
    for (int i = 0; i < 4; ++i) {
        m[i] = -1e30f; l[i] = 0.f;
#pragma unroll
        for (int j = 0; j < 8; ++j) O[i][j] = 0.f;
    }

    for (int kt = 0; kt <= qt; ++kt) {
        const int k0 = kt * 64;
#pragma unroll
        for (int it = 0; it < 8; ++it) {
            int id = tid + it * 256;
            int j  = id >> 5;
            int d4 = (id & 31) << 2;
            float4 k4 = *(const float4*)(Kg + (size_t)(k0 + j) * KVDIM + kh * HD + d4);
            int xg = (((j >> 2) ^ (id & 15)) << 2) + (j & 3);
            KVb[(d4 + 0) * 64 + xg] = k4.x;
            KVb[(d4 + 1) * 64 + xg] = k4.y;
            KVb[(d4 + 2) * 64 + xg] = k4.z;
            KVb[(d4 + 3) * 64 + xg] = k4.w;
        }
        __syncthreads();

        float s[4][4];
#pragma unroll
        for (int i = 0; i < 4; ++i)
#pragma unroll
            for (int j = 0; j < 4; ++j)
                s[i][j] = mask[(size_t)(q0 + rr + i) * SQ + k0 + (cg << 2) + j];

        const float* q0p = Qs + (rr + 0) * 132;
        const float* q1p = Qs + (rr + 1) * 132;
        const float* q2p = Qs + (rr + 2) * 132;
        const float* q3p = Qs + (rr + 3) * 132;

#pragma unroll 8
        for (int d4 = 0; d4 < 128; d4 += 4) {
            int g = (((d4 >> 2) & 15) ^ cg) << 2;
#pragma unroll
            for (int dd = 0; dd < 4; ++dd) {
                int d = d4 + dd;
                float4 kv = *(const float4*)(KVb + d * 64 + g);
                float qv0 = q0p[d], qv1 = q1p[d], qv2 = q2p[d], qv3 = q3p[d];
                s[0][0] += qv0 * kv.x; s[0][1] += qv0 * kv.y; s[0][2] += qv0 * kv.z; s[0][3] += qv0 * kv.w;
                s[1][0] += qv1 * kv.x; s[1][1] += qv1 * kv.y; s[1][2] += qv1 * kv.z; s[1][3] += qv1 * kv.w;
                s[2][0] += qv2 * kv.x; s[2][1] += qv2 * kv.y; s[2][2] += qv2 * kv.z; s[2][3] += qv2 * kv.w;
                s[3][0] += qv3 * kv.x; s[3][1] += qv3 * kv.y; s[3][2] += qv3 * kv.z; s[3][3] += qv3 * kv.w;
            }
        }

#pragma unroll
        for (int i = 0; i < 4; ++i) {
            float v = fmaxf(fmaxf(s[i][0], s[i][1]), fmaxf(s[i][2], s[i][3]));
            v = fmaxf(v, __shfl_xor_sync(0xffffffffu, v, 1));
            v = fmaxf(v, __shfl_xor_sync(0xffffffffu, v, 2));
            v = fmaxf(v, __shfl_xor_sync(0xffffffffu, v, 4));
            v = fmaxf(v, __shfl_xor_sync(0xffffffffu, v, 8));
            float nm = fmaxf(m[i], v);
            float c  = __expf(m[i] - nm);
            m[i] = nm;
            float rs = 0.f;
#pragma unroll
            for (int j = 0; j < 4; ++j) { s[i][j] = __expf(s[i][j] - nm); rs += s[i][j]; }
            rs += __shfl_xor_sync(0xffffffffu, rs, 1);
            rs += __shfl_xor_sync(0xffffffffu, rs, 2);
            rs += __shfl_xor_sync(0xffffffffu, rs, 4);
            rs += __shfl_xor_sync(0xffffffffu, rs, 8);
            l[i] = l[i] * c + rs;
#pragma unroll
            for (int j = 0; j < 8; ++j) O[i][j] *= c;
        }

#pragma unroll
        for (int i = 0; i < 4; ++i)
#pragma unroll
            for (int j = 0; j < 4; ++j)
                Ps[(rr + i) * 68 + (cg << 2) + j] = s[i][j];
        __syncthreads();

#pragma unroll
        for (int it = 0; it < 8; ++it) {
            int id = tid + it * 256;
            int r  = id >> 5;
            int c4 = (id & 31) << 2;
            *(float4*)(KVb + r * 132 + c4) =
                *(const float4*)(Vg + (size_t)(k0 + r) * KVDIM + kh * HD + c4);
        }
        __syncthreads();

#pragma unroll 4
        for (int k = 0; k < 64; ++k) {
            float4 v0 = *(const float4*)(KVb + k * 132 + dc);
            float4 v1 = *(const float4*)(KVb + k * 132 + dc + 4);
#pragma unroll
            for (int i = 0; i < 4; ++i) {
                float p = Ps[(rr + i) * 68 + k];
                O[i][0] += p * v0.x; O[i][1] += p * v0.y; O[i][2] += p * v0.z; O[i][3] += p * v0.w;
                O[i][4] += p * v1.x; O[i][5] += p * v1.y; O[i][6] += p * v1.z; O[i][7] += p * v1.w;
            }
        }
        __syncthreads();
    }

#pragma unroll
    for (int i = 0; i < 4; ++i) {
        float inv = 1.f / l[i];
        float* op = AO + (size_t)(q0 + rr + i) * QDIM + h * HD + dc;
        *(float4*)op       = make_float4(O[i][0]*inv, O[i][1]*inv, O[i][2]*inv, O[i][3]*inv);
        *(float4*)(op + 4) = make_float4(O[i][4]*inv, O[i][5]*inv, O[i][6]*inv, O[i][7]*inv);
    }
}

// ---------------- launch ----------------
extern "C" void kernel_launch(void* const* d_in, const int* in_sizes, int n_in,
                              void* d_out, int out_size)
{
    const float* hs   = (const float*)d_in[0];
    const float* mask = (const float*)d_in[1];
    const int*   pos  = (const int*)d_in[2];
    const float* Wq   = (const float*)d_in[3];
    const float* Wk   = (const float*)d_in[4];
    const float* Wv   = (const float*)d_in[5];
    const float* Wo   = (const float*)d_in[6];
    float* out = (float*)d_out;

    float *qp, *kp, *vp, *aop;
    __nv_bfloat16 *ah, *al, *aoh, *aol;
    __nv_bfloat16 *wqh, *wql, *wkh, *wkl, *wvh, *wvl, *woh, *wol;
    cudaGetSymbolAddress((void**)&qp,  g_Q);
    cudaGetSymbolAddress((void**)&kp,  g_K);
    cudaGetSymbolAddress((void**)&vp,  g_V);
    cudaGetSymbolAddress((void**)&aop, g_AO);
    cudaGetSymbolAddress((void**)&ah,  g_Ah);
    cudaGetSymbolAddress((void**)&al,  g_Al);
    cudaGetSymbolAddress((void**)&aoh, g_AOh);
    cudaGetSymbolAddress((void**)&aol, g_AOl);
    cudaGetSymbolAddress((void**)&wqh, g_WqTh);
    cudaGetSymbolAddress((void**)&wql, g_WqTl);
    cudaGetSymbolAddress((void**)&wkh, g_WkTh);
    cudaGetSymbolAddress((void**)&wkl, g_WkTl);
    cudaGetSymbolAddress((void**)&wvh, g_WvTh);
    cudaGetSymbolAddress((void**)&wvl, g_WvTl);
    cudaGetSymbolAddress((void**)&woh, g_WoTh);
    cudaGetSymbolAddress((void**)&wol, g_WoTl);

    const size_t attn_smem = (8448 + 8448 + 4352) * sizeof(float);
    cudaFuncSetAttribute(attn_kernel, cudaFuncAttributeMaxDynamicSharedMemorySize, (int)attn_smem);

    const int gemm_smem = 3 * 4 * 128 * 32 * 2;  // 98304 B
    cudaFuncSetAttribute(gemm_hmma_x3, cudaFuncAttributeMaxDynamicSharedMemorySize, gemm_smem);

    // split activations + weights
    split_plain<<<(SQ * HID / 2 + 255) / 256, 256>>>(hs, ah, al, SQ * HID / 2);
    split_transpose<<<dim3(QDIM / 32,  HID / 32), 256>>>(Wq, wqh, wql, HID, QDIM);
    split_transpose<<<dim3(KVDIM / 32, HID / 32), 256>>>(Wk, wkh, wkl, HID, KVDIM);
    split_transpose<<<dim3(KVDIM / 32, HID / 32), 256>>>(Wv, wvh, wvl, HID, KVDIM);
    split_transpose<<<dim3(HID / 32,  QDIM / 32), 256>>>(Wo, woh, wol, QDIM, HID);

    // QKV projections (HMMA bf16x3)
    gemm_hmma_x3<<<dim3(QDIM / 128,  SQ / 128), 256, gemm_smem>>>(ah, al, wqh, wql, qp, SQ, QDIM,  HID);
    gemm_hmma_x3<<<dim3(KVDIM / 128, SQ / 128), 256, gemm_smem>>>(ah, al, wkh, wkl, kp, SQ, KVDIM, HID);
    gemm_hmma_x3<<<dim3(KVDIM / 128, SQ / 128), 256, gemm_smem>>>(ah, al, wvh, wvl, vp, SQ, KVDIM, HID);

    // RoPE
    rope_kernel<<<SQ, 256>>>(qp, kp, pos);

    // attention
    attn_kernel<<<dim3(SQ / 64, NH), 256, attn_smem>>>(qp, kp, vp, mask, aop);

    // output projection
    split_plain<<<(SQ * QDIM / 2 + 255) / 256, 256>>>(aop, aoh, aol, SQ * QDIM / 2);
    gemm_hmma_x3<<<dim3(HID / 128, SQ / 128), 256, gemm_smem>>>(aoh, aol, woh, wol, out, SQ, HID, QDIM);
}

// round 4
// speedup vs baseline: 3.0317x; 1.4704x over previous
#include <cuda_runtime.h>
#include <cuda_bf16.h>
#include <math.h>
#include <cstdint>

#define SQ    2048
#define HID   4096
#define NH    32
#define NKV   8
#define HD    128
#define QDIM  (NH*HD)    // 4096
#define KVDIM (NKV*HD)   // 1024

// ---------------- scratch (static device allocations) ----------------
__device__ float g_Q [SQ * QDIM];
__device__ float g_K [SQ * KVDIM];
__device__ float g_V [SQ * KVDIM];

__device__ __nv_bfloat16 g_Ah [SQ * HID];
__device__ __nv_bfloat16 g_Al [SQ * HID];
__device__ __nv_bfloat16 g_AOh[SQ * QDIM];
__device__ __nv_bfloat16 g_AOl[SQ * QDIM];

__device__ __nv_bfloat16 g_Qh[SQ * QDIM];
__device__ __nv_bfloat16 g_Ql[SQ * QDIM];
__device__ __nv_bfloat16 g_Kh[SQ * KVDIM];
__device__ __nv_bfloat16 g_Kl[SQ * KVDIM];
__device__ __nv_bfloat16 g_Vh[SQ * KVDIM];
__device__ __nv_bfloat16 g_Vl[SQ * KVDIM];

__device__ __nv_bfloat16 g_WqTh[QDIM * HID];
__device__ __nv_bfloat16 g_WqTl[QDIM * HID];
__device__ __nv_bfloat16 g_WkTh[KVDIM * HID];
__device__ __nv_bfloat16 g_WkTl[KVDIM * HID];
__device__ __nv_bfloat16 g_WvTh[KVDIM * HID];
__device__ __nv_bfloat16 g_WvTl[KVDIM * HID];
__device__ __nv_bfloat16 g_WoTh[HID * QDIM];
__device__ __nv_bfloat16 g_WoTl[HID * QDIM];

// ---------------- PTX helpers (sm_80-era instructions only) ----------------
__device__ __forceinline__ uint32_t smem_u32(const void* p) {
    uint32_t a;
    asm("{ .reg .u64 t; cvta.to.shared.u64 t, %1; cvt.u32.u64 %0, t; }" : "=r"(a) : "l"(p));
    return a;
}

__device__ __forceinline__ void cpa16(uint32_t dst, const void* src) {
    asm volatile("cp.async.cg.shared.global [%0], [%1], 16;" :: "r"(dst), "l"(src) : "memory");
}
#define CP_COMMIT() asm volatile("cp.async.commit_group;" ::: "memory")
#define CP_WAIT1()  asm volatile("cp.async.wait_group 1;" ::: "memory")
#define CP_WAIT0()  asm volatile("cp.async.wait_group 0;" ::: "memory")

__device__ __forceinline__ void ldsm_x4(uint32_t& r0, uint32_t& r1, uint32_t& r2, uint32_t& r3,
                                        uint32_t addr) {
    asm volatile("ldmatrix.sync.aligned.m8n8.x4.shared.b16 {%0,%1,%2,%3}, [%4];"
                 : "=r"(r0), "=r"(r1), "=r"(r2), "=r"(r3) : "r"(addr));
}
__device__ __forceinline__ void ldsm_x4_t(uint32_t& r0, uint32_t& r1, uint32_t& r2, uint32_t& r3,
                                          uint32_t addr) {
    asm volatile("ldmatrix.sync.aligned.m8n8.x4.trans.shared.b16 {%0,%1,%2,%3}, [%4];"
                 : "=r"(r0), "=r"(r1), "=r"(r2), "=r"(r3) : "r"(addr));
}

__device__ __forceinline__ void mma_bf16(float& d0, float& d1, float& d2, float& d3,
                                         uint32_t a0, uint32_t a1, uint32_t a2, uint32_t a3,
                                         uint32_t b0, uint32_t b1) {
    asm volatile("mma.sync.aligned.m16n8k16.row.col.f32.bf16.bf16.f32 "
                 "{%0,%1,%2,%3}, {%4,%5,%6,%7}, {%8,%9}, {%0,%1,%2,%3};"
                 : "+f"(d0), "+f"(d1), "+f"(d2), "+f"(d3)
                 : "r"(a0), "r"(a1), "r"(a2), "r"(a3), "r"(b0), "r"(b1));
}

__device__ __forceinline__ void split2(float v, __nv_bfloat16& h, __nv_bfloat16& l) {
    h = __float2bfloat16(v);
    l = __float2bfloat16(v - __bfloat162float(h));
}

// ---------------- fp32 -> bf16 hi/lo split (elementwise) ----------------
__global__ __launch_bounds__(256) void split_plain(
    const float* __restrict__ X, __nv_bfloat16* __restrict__ H,
    __nv_bfloat16* __restrict__ L, int n2)
{
    int i = blockIdx.x * 256 + threadIdx.x;
    if (i >= n2) return;
    float2 a = ((const float2*)X)[i];
    __nv_bfloat162 h, l;
    split2(a.x, h.x, l.x);
    split2(a.y, h.y, l.y);
    ((__nv_bfloat162*)H)[i] = h;
    ((__nv_bfloat162*)L)[i] = l;
}

// ---------------- fp32 W[K,N] -> bf16 hi/lo transposed [N,K] ----------------
__global__ __launch_bounds__(256) void split_transpose(
    const float* __restrict__ W, __nv_bfloat16* __restrict__ HT,
    __nv_bfloat16* __restrict__ LT, int K, int N)
{
    __shared__ float t[32][33];
    int n0 = blockIdx.x * 32, k0 = blockIdx.y * 32;
    int tx = threadIdx.x & 31, ty = threadIdx.x >> 5;
#pragma unroll
    for (int i = 0; i < 4; ++i) {
        int ky = ty + i * 8;
        t[ky][tx] = W[(size_t)(k0 + ky) * N + n0 + tx];
    }
    __syncthreads();
#pragma unroll
    for (int i = 0; i < 4; ++i) {
        int ny = ty + i * 8;
        float a = t[tx][ny];
        __nv_bfloat16 h, l;
        split2(a, h, l);
        HT[(size_t)(n0 + ny) * K + k0 + tx] = h;
        LT[(size_t)(n0 + ny) * K + k0 + tx] = l;
    }
}

// ---------------- HMMA bf16x3 GEMM ----------------
#define SWZ_OFF(r, c8) ((r) * 64 + (((c8) ^ (((r) >> 1) & 3)) << 4))

__global__ __launch_bounds__(256, 1) void gemm_hmma_x3(
    const __nv_bfloat16* __restrict__ Ah, const __nv_bfloat16* __restrict__ Al,
    const __nv_bfloat16* __restrict__ Bh, const __nv_bfloat16* __restrict__ Bl,
    float* __restrict__ C, int M, int N, int K)
{
    extern __shared__ char smem[];
    constexpr int TILE  = 128 * 32 * 2;
    constexpr int STAGE = 4 * TILE;
    const uint32_t sb = smem_u32(smem);

    const int tid  = threadIdx.x;
    const int wid  = tid >> 5;
    const int lane = tid & 31;
    const int m0 = blockIdx.y * 128;
    const int n0 = blockIdx.x * 128;
    const int wm = (wid >> 2) * 64;
    const int wn = (wid & 3) * 32;
    const int nk = K >> 5;

    const int rl = lane & 15;
    const int ch = lane >> 4;

    float acc[4][4][4];
#pragma unroll
    for (int i = 0; i < 4; ++i)
#pragma unroll
        for (int j = 0; j < 4; ++j)
#pragma unroll
            for (int q = 0; q < 4; ++q) acc[i][j][q] = 0.f;

    auto load_stage = [&](int c, int s) {
        const int kb = c * 32;
        const uint32_t st = sb + s * STAGE;
#pragma unroll
        for (int i = 0; i < 2; ++i) {
            int id = tid + i * 256;
            int r = id >> 2, c8 = id & 3;
            uint32_t off = SWZ_OFF(r, c8);
            cpa16(st + off,            Ah + (size_t)(m0 + r) * K + kb + c8 * 8);
            cpa16(st + TILE + off,     Al + (size_t)(m0 + r) * K + kb + c8 * 8);
            cpa16(st + 2 * TILE + off, Bh + (size_t)(n0 + r) * K + kb + c8 * 8);
            cpa16(st + 3 * TILE + off, Bl + (size_t)(n0 + r) * K + kb + c8 * 8);
        }
        CP_COMMIT();
    };

    load_stage(0, 0);
    if (nk > 1) load_stage(1, 1);

    for (int c = 0; c < nk; ++c) {
        if (c + 1 < nk) { CP_WAIT1(); } else { CP_WAIT0(); }
        __syncthreads();
        if (c + 2 < nk) load_stage(c + 2, (c + 2) % 3);

        const uint32_t st = sb + (c % 3) * STAGE;
#pragma unroll
        for (int ks = 0; ks < 2; ++ks) {
            uint32_t ahf[4][4], alf[4][4], bhf[2][4], blf[2][4];
#pragma unroll
            for (int mt = 0; mt < 4; ++mt) {
                int r = wm + mt * 16 + rl;
                int c8 = 2 * ks + ch;
                uint32_t off = SWZ_OFF(r, c8);
                ldsm_x4(ahf[mt][0], ahf[mt][1], ahf[mt][2], ahf[mt][3], st + off);
                ldsm_x4(alf[mt][0], alf[mt][1], alf[mt][2], alf[mt][3], st + TILE + off);
            }
#pragma unroll
            for (int np = 0; np < 2; ++np) {
                int r = wn + np * 16 + rl;
                int c8 = 2 * ks + ch;
                uint32_t off = SWZ_OFF(r, c8);
                ldsm_x4(bhf[np][0], bhf[np][1], bhf[np][2], bhf[np][3], st + 2 * TILE + off);
                ldsm_x4(blf[np][0], blf[np][1], blf[np][2], blf[np][3], st + 3 * TILE + off);
            }
#pragma unroll
            for (int mt = 0; mt < 4; ++mt) {
#pragma unroll
                for (int nt = 0; nt < 4; ++nt) {
                    const int np = nt >> 1, sel = nt & 1;
                    float* d = acc[mt][nt];
                    mma_bf16(d[0], d[1], d[2], d[3],
                             ahf[mt][0], ahf[mt][1], ahf[mt][2], ahf[mt][3],
                             bhf[np][sel], bhf[np][2 + sel]);
                    mma_bf16(d[0], d[1], d[2], d[3],
                             ahf[mt][0], ahf[mt][1], ahf[mt][2], ahf[mt][3],
                             blf[np][sel], blf[np][2 + sel]);
                    mma_bf16(d[0], d[1], d[2], d[3],
                             alf[mt][0], alf[mt][1], alf[mt][2], alf[mt][3],
                             bhf[np][sel], bhf[np][2 + sel]);
                }
            }
        }
        __syncthreads();
    }

#pragma unroll
    for (int mt = 0; mt < 4; ++mt) {
#pragma unroll
        for (int nt = 0; nt < 4; ++nt) {
            int rg = m0 + wm + mt * 16 + (lane >> 2);
            int cg = n0 + wn + nt * 8 + (lane & 3) * 2;
            float* d = acc[mt][nt];
            *(float2*)(C + (size_t)rg * N + cg)       = make_float2(d[0], d[1]);
            *(float2*)(C + (size_t)(rg + 8) * N + cg) = make_float2(d[2], d[3]);
        }
    }
}

// ---------------- RoPE + pre-scale + bf16 hi/lo split ----------------
__global__ __launch_bounds__(256) void rope_split(
    const float* __restrict__ Q, const float* __restrict__ K,
    const int* __restrict__ pos_ids,
    __nv_bfloat16* __restrict__ Qh, __nv_bfloat16* __restrict__ Ql,
    __nv_bfloat16* __restrict__ Kh, __nv_bfloat16* __restrict__ Kl)
{
    const int s = blockIdx.x;
    const float scale = 0.08838834764831845f;  // 1/sqrt(128)
    __shared__ float cs[64], sn[64];
    if (threadIdx.x < 64) {
        double invf = exp(-(double)threadIdx.x * (9.210340371976184 / 64.0));
        float ang = (float)((double)pos_ids[s] * invf);
        float c, si;
        sincosf(ang, &si, &c);
        cs[threadIdx.x] = c;
        sn[threadIdx.x] = si;
    }
    __syncthreads();
#pragma unroll
    for (int it = 0; it < 8; ++it) {
        int pp = threadIdx.x + it * 256;
        int head = pp >> 6, i = pp & 63;
        size_t b = (size_t)s * QDIM + head * HD + i;
        float x0 = Q[b], x1 = Q[b + 64];
        float c = cs[i], si = sn[i];
        float y0 = (x0 * c - x1 * si) * scale;
        float y1 = (x1 * c + x0 * si) * scale;
        __nv_bfloat16 h, l;
        split2(y0, h, l); Qh[b] = h;      Ql[b] = l;
        split2(y1, h, l); Qh[b + 64] = h; Ql[b + 64] = l;
    }
#pragma unroll
    for (int it = 0; it < 2; ++it) {
        int pp = threadIdx.x + it * 256;
        int head = pp >> 6, i = pp & 63;
        size_t b = (size_t)s * KVDIM + head * HD + i;
        float x0 = K[b], x1 = K[b + 64];
        float c = cs[i], si = sn[i];
        float y0 = x0 * c - x1 * si;
        float y1 = x1 * c + x0 * si;
        __nv_bfloat16 h, l;
        split2(y0, h, l); Kh[b] = h;      Kl[b] = l;
        split2(y1, h, l); Kh[b + 64] = h; Kl[b + 64] = l;
    }
}

// ---------------- HMMA flash attention (causal, x3 compensated) ----------------
// grid (16, 32): blockIdx.x -> q-block (reversed for load balance), blockIdx.y -> head.
// CTA: 128 q-rows, 8 warps of m16. K-tiles of 64, K/V hi/lo double-buffered cp.async.
// Smem row = 256B (128 bf16); 16B-group swizzle: g' = g ^ (row & 7).
#define ASWZ(row, g) ((row) * 256 + (((g) ^ ((row) & 7)) << 4))

__global__ __launch_bounds__(256) void attn_hmma(
    const __nv_bfloat16* __restrict__ Qh, const __nv_bfloat16* __restrict__ Ql,
    const __nv_bfloat16* __restrict__ Kh, const __nv_bfloat16* __restrict__ Kl,
    const __nv_bfloat16* __restrict__ Vh, const __nv_bfloat16* __restrict__ Vl,
    __nv_bfloat16* __restrict__ AOh, __nv_bfloat16* __restrict__ AOl)
{
    extern __shared__ char sm[];
    const uint32_t sb = smem_u32(sm);
    constexpr int MTILE = 64 * 128 * 2;     // 16 KB per matrix
    constexpr int STAGE = 4 * MTILE;        // 64 KB

    const int tid = threadIdx.x, wid = tid >> 5, lane = tid & 31;
    const int h  = blockIdx.y, kh = h >> 2;
    const int bq = gridDim.x - 1 - blockIdx.x;
    const int q0 = bq * 128;
    const int wr = wid * 16;
    const int r  = lane >> 2, c2 = (lane & 3) * 2;
    const int rl = lane & 15, chh = lane >> 4;

    // Q fragments (hi/lo), resident in registers
    uint32_t qfh[8][4], qfl[8][4];
    {
        const int row0 = q0 + wr + r;
#pragma unroll
        for (int ks = 0; ks < 8; ++ks) {
            int k2 = ks * 16 + c2;
            size_t b00 = (size_t)row0 * QDIM + h * HD + k2;
            size_t b10 = b00 + (size_t)8 * QDIM;
            qfh[ks][0] = *(const uint32_t*)(Qh + b00);
            qfh[ks][1] = *(const uint32_t*)(Qh + b10);
            qfh[ks][2] = *(const uint32_t*)(Qh + b00 + 8);
            qfh[ks][3] = *(const uint32_t*)(Qh + b10 + 8);
            qfl[ks][0] = *(const uint32_t*)(Ql + b00);
            qfl[ks][1] = *(const uint32_t*)(Ql + b10);
            qfl[ks][2] = *(const uint32_t*)(Ql + b00 + 8);
            qfl[ks][3] = *(const uint32_t*)(Ql + b10 + 8);
        }
    }

    float o[16][4];
#pragma unroll
    for (int i = 0; i < 16; ++i)
#pragma unroll
        for (int q = 0; q < 4; ++q) o[i][q] = 0.f;
    float m1 = -1e30f, m2 = -1e30f, l1 = 0.f, l2 = 0.f;

    const int ntiles = 2 * bq + 2;

    auto load_kv = [&](int kt, int s) {
        const int k0 = kt * 64;
        const uint32_t st = sb + s * STAGE;
#pragma unroll
        for (int i = 0; i < 4; ++i) {
            int id = tid + i * 256;
            int rw = id >> 4, g = id & 15;
            uint32_t off = ASWZ(rw, g);
            size_t src = (size_t)(k0 + rw) * KVDIM + kh * HD + g * 8;
            cpa16(st + off,             Kh + src);
            cpa16(st + MTILE + off,     Kl + src);
            cpa16(st + 2 * MTILE + off, Vh + src);
            cpa16(st + 3 * MTILE + off, Vl + src);
        }
        CP_COMMIT();
    };

    load_kv(0, 0);

    for (int kt = 0; kt < ntiles; ++kt) {
        if (kt + 1 < ntiles) { load_kv(kt + 1, (kt + 1) & 1); CP_WAIT1(); }
        else                 { CP_WAIT0(); }
        __syncthreads();

        const uint32_t st = sb + (kt & 1) * STAGE;
        const int k0 = kt * 64;

        // ---- S = Q @ K^T (x3)
        float sacc[8][4];
#pragma unroll
        for (int i = 0; i < 8; ++i)
#pragma unroll
            for (int q = 0; q < 4; ++q) sacc[i][q] = 0.f;

#pragma unroll
        for (int ks = 0; ks < 8; ++ks) {
            uint32_t kbh[4][4], kbl[4][4];
#pragma unroll
            for (int np = 0; np < 4; ++np) {
                int row = np * 16 + rl;
                int g = 2 * ks + chh;
                uint32_t off = ASWZ(row, g);
                ldsm_x4(kbh[np][0], kbh[np][1], kbh[np][2], kbh[np][3], st + off);
                ldsm_x4(kbl[np][0], kbl[np][1], kbl[np][2], kbl[np][3], st + MTILE + off);
            }
#pragma unroll
            for (int nt = 0; nt < 8; ++nt) {
                const int np = nt >> 1, sel = nt & 1;
                float* d = sacc[nt];
                mma_bf16(d[0], d[1], d[2], d[3],
                         qfh[ks][0], qfh[ks][1], qfh[ks][2], qfh[ks][3],
                         kbh[np][sel], kbh[np][2 + sel]);
                mma_bf16(d[0], d[1], d[2], d[3],
                         qfh[ks][0], qfh[ks][1], qfh[ks][2], qfh[ks][3],
                         kbl[np][sel], kbl[np][2 + sel]);
                mma_bf16(d[0], d[1], d[2], d[3],
                         qfl[ks][0], qfl[ks][1], qfl[ks][2], qfl[ks][3],
                         kbh[np][sel], kbh[np][2 + sel]);
            }
        }

        // ---- analytic causal mask (only the last two tiles can cross the diagonal)
        if (k0 + 63 > q0 + wr) {
            const int row1 = q0 + wr + r, row2 = row1 + 8;
#pragma unroll
            for (int nt = 0; nt < 8; ++nt) {
                int col = k0 + nt * 8 + c2;
                if (col     > row1) sacc[nt][0] = -1e30f;
                if (col + 1 > row1) sacc[nt][1] = -1e30f;
                if (col     > row2) sacc[nt][2] = -1e30f;
                if (col + 1 > row2) sacc[nt][3] = -1e30f;
            }
        }

        // ---- online softmax
        float mx1 = -1e30f, mx2 = -1e30f;
#pragma unroll
        for (int nt = 0; nt < 8; ++nt) {
            mx1 = fmaxf(mx1, fmaxf(sacc[nt][0], sacc[nt][1]));
            mx2 = fmaxf(mx2, fmaxf(sacc[nt][2], sacc[nt][3]));
        }
        mx1 = fmaxf(mx1, __shfl_xor_sync(0xffffffffu, mx1, 1));
        mx1 = fmaxf(mx1, __shfl_xor_sync(0xffffffffu, mx1, 2));
        mx2 = fmaxf(mx2, __shfl_xor_sync(0xffffffffu, mx2, 1));
        mx2 = fmaxf(mx2, __shfl_xor_sync(0xffffffffu, mx2, 2));
        float nm1 = fmaxf(m1, mx1), nm2 = fmaxf(m2, mx2);
        float cf1 = __expf(m1 - nm1), cf2 = __expf(m2 - nm2);
        m1 = nm1; m2 = nm2;

        float ls1 = 0.f, ls2 = 0.f;
#pragma unroll
        for (int nt = 0; nt < 8; ++nt) {
            sacc[nt][0] = __expf(sacc[nt][0] - nm1);
            sacc[nt][1] = __expf(sacc[nt][1] - nm1);
            sacc[nt][2] = __expf(sacc[nt][2] - nm2);
            sacc[nt][3] = __expf(sacc[nt][3] - nm2);
            ls1 += sacc[nt][0] + sacc[nt][1];
            ls2 += sacc[nt][2] + sacc[nt][3];
        }
        ls1 += __shfl_xor_sync(0xffffffffu, ls1, 1);
        ls1 += __shfl_xor_sync(0xffffffffu, ls1, 2);
        ls2 += __shfl_xor_sync(0xffffffffu, ls2, 1);
        ls2 += __shfl_xor_sync(0xffffffffu, ls2, 2);
        l1 = l1 * cf1 + ls1;
        l2 = l2 * cf2 + ls2;
#pragma unroll
        for (int dt = 0; dt < 16; ++dt) {
            o[dt][0] *= cf1; o[dt][1] *= cf1;
            o[dt][2] *= cf2; o[dt][3] *= cf2;
        }

        // ---- O += P @ V (x3), V via ldmatrix.trans
#pragma unroll
        for (int s = 0; s < 4; ++s) {
            uint32_t aph[4], apl[4];
#pragma unroll
            for (int half = 0; half < 2; ++half) {      // half 0: nt=2s, half 1: nt=2s+1
                const float* sv = sacc[2 * s + half];
                __nv_bfloat162 h01, l01, h23, l23;
                split2(sv[0], h01.x, l01.x);
                split2(sv[1], h01.y, l01.y);
                split2(sv[2], h23.x, l23.x);
                split2(sv[3], h23.y, l23.y);
                aph[2 * half + 0] = *(uint32_t*)&h01;
                aph[2 * half + 1] = *(uint32_t*)&h23;
                apl[2 * half + 0] = *(uint32_t*)&l01;
                apl[2 * half + 1] = *(uint32_t*)&l23;
            }
            // reorder: a0=(r,k0-7)=half0 pair lo, a1=(r+8,k0-7)=half0 hi, a2/a3=half1
            uint32_t a0 = aph[0], a1 = aph[1], a2 = aph[2], a3 = aph[3];
            uint32_t b0 = apl[0], b1 = apl[1], b2 = apl[2], b3 = apl[3];
#pragma unroll
            for (int dg = 0; dg < 8; ++dg) {
                int row = s * 16 + rl;
                int g = 2 * dg + chh;
                uint32_t off = ASWZ(row, g);
                uint32_t vh4[4], vl4[4];
                ldsm_x4_t(vh4[0], vh4[1], vh4[2], vh4[3], st + 2 * MTILE + off);
                ldsm_x4_t(vl4[0], vl4[1], vl4[2], vl4[3], st + 3 * MTILE + off);
                float* d0 = o[2 * dg];
                float* d1 = o[2 * dg + 1];
                mma_bf16(d0[0], d0[1], d0[2], d0[3], a0, a1, a2, a3, vh4[0], vh4[1]);
                mma_bf16(d0[0], d0[1], d0[2], d0[3], a0, a1, a2, a3, vl4[0], vl4[1]);
                mma_bf16(d0[0], d0[1], d0[2], d0[3], b0, b1, b2, b3, vh4[0], vh4[1]);
                mma_bf16(d1[0], d1[1], d1[2], d1[3], a0, a1, a2, a3, vh4[2], vh4[3]);
                mma_bf16(d1[0], d1[1], d1[2], d1[3], a0, a1, a2, a3, vl4[2], vl4[3]);
                mma_bf16(d1[0], d1[1], d1[2], d1[3], b0, b1, b2, b3, vh4[2], vh4[3]);
            }
        }
        __syncthreads();
    }

    // ---- epilogue: normalize, split to bf16 hi/lo, store
    const float inv1 = 1.f / l1, inv2 = 1.f / l2;
    const int row1 = q0 + wr + r;
#pragma unroll
    for (int dt = 0; dt < 16; ++dt) {
        size_t c0 = (size_t)row1 * QDIM + h * HD + dt * 8 + c2;
        size_t c1 = c0 + (size_t)8 * QDIM;
        __nv_bfloat162 h01, l01;
        split2(o[dt][0] * inv1, h01.x, l01.x);
        split2(o[dt][1] * inv1, h01.y, l01.y);
        *(__nv_bfloat162*)(AOh + c0) = h01;
        *(__nv_bfloat162*)(AOl + c0) = l01;
        split2(o[dt][2] * inv2, h01.x, l01.x);
        split2(o[dt][3] * inv2, h01.y, l01.y);
        *(__nv_bfloat162*)(AOh + c1) = h01;
        *(__nv_bfloat162*)(AOl + c1) = l01;
    }
}

// ---------------- launch ----------------
extern "C" void kernel_launch(void* const* d_in, const int* in_sizes, int n_in,
                              void* d_out, int out_size)
{
    const float* hs   = (const float*)d_in[0];
    const int*   pos  = (const int*)d_in[2];
    const float* Wq   = (const float*)d_in[3];
    const float* Wk   = (const float*)d_in[4];
    const float* Wv   = (const float*)d_in[5];
    const float* Wo   = (const float*)d_in[6];
    float* out = (float*)d_out;

    float *qp, *kp, *vp;
    __nv_bfloat16 *ah, *al, *aoh, *aol, *qhp, *qlp, *khp, *klp, *vhp, *vlp;
    __nv_bfloat16 *wqh, *wql, *wkh, *wkl, *wvh, *wvl, *woh, *wol;
    cudaGetSymbolAddress((void**)&qp,  g_Q);
    cudaGetSymbolAddress((void**)&kp,  g_K);
    cudaGetSymbolAddress((void**)&vp,  g_V);
    cudaGetSymbolAddress((void**)&ah,  g_Ah);
    cudaGetSymbolAddress((void**)&al,  g_Al);
    cudaGetSymbolAddress((void**)&aoh, g_AOh);
    cudaGetSymbolAddress((void**)&aol, g_AOl);
    cudaGetSymbolAddress((void**)&qhp, g_Qh);
    cudaGetSymbolAddress((void**)&qlp, g_Ql);
    cudaGetSymbolAddress((void**)&khp, g_Kh);
    cudaGetSymbolAddress((void**)&klp, g_Kl);
    cudaGetSymbolAddress((void**)&vhp, g_Vh);
    cudaGetSymbolAddress((void**)&vlp, g_Vl);
    cudaGetSymbolAddress((void**)&wqh, g_WqTh);
    cudaGetSymbolAddress((void**)&wql, g_WqTl);
    cudaGetSymbolAddress((void**)&wkh, g_WkTh);
    cudaGetSymbolAddress((void**)&wkl, g_WkTl);
    cudaGetSymbolAddress((void**)&wvh, g_WvTh);
    cudaGetSymbolAddress((void**)&wvl, g_WvTl);
    cudaGetSymbolAddress((void**)&woh, g_WoTh);
    cudaGetSymbolAddress((void**)&wol, g_WoTl);

    const int gemm_smem = 3 * 4 * 128 * 32 * 2;   // 98304
    cudaFuncSetAttribute(gemm_hmma_x3, cudaFuncAttributeMaxDynamicSharedMemorySize, gemm_smem);
    const int attn_smem = 2 * 4 * 64 * 128 * 2;   // 131072
    cudaFuncSetAttribute(attn_hmma, cudaFuncAttributeMaxDynamicSharedMemorySize, attn_smem);

    // splits
    split_plain<<<(SQ * HID / 2 + 255) / 256, 256>>>(hs, ah, al, SQ * HID / 2);
    split_transpose<<<dim3(QDIM / 32,  HID / 32), 256>>>(Wq, wqh, wql, HID, QDIM);
    split_transpose<<<dim3(KVDIM / 32, HID / 32), 256>>>(Wk, wkh, wkl, HID, KVDIM);
    split_transpose<<<dim3(KVDIM / 32, HID / 32), 256>>>(Wv, wvh, wvl, HID, KVDIM);
    split_transpose<<<dim3(HID / 32,  QDIM / 32), 256>>>(Wo, woh, wol, QDIM, HID);

    // QKV projections
    gemm_hmma_x3<<<dim3(QDIM / 128,  SQ / 128), 256, gemm_smem>>>(ah, al, wqh, wql, qp, SQ, QDIM,  HID);
    gemm_hmma_x3<<<dim3(KVDIM / 128, SQ / 128), 256, gemm_smem>>>(ah, al, wkh, wkl, kp, SQ, KVDIM, HID);
    gemm_hmma_x3<<<dim3(KVDIM / 128, SQ / 128), 256, gemm_smem>>>(ah, al, wvh, wvl, vp, SQ, KVDIM, HID);

    // RoPE + split Q/K; split V
    rope_split<<<SQ, 256>>>(qp, kp, pos, qhp, qlp, khp, klp);
    split_plain<<<(SQ * KVDIM / 2 + 255) / 256, 256>>>(vp, vhp, vlp, SQ * KVDIM / 2);

    // attention (HMMA)
    attn_hmma<<<dim3(SQ / 128, NH), 256, attn_smem>>>(qhp, qlp, khp, klp, vhp, vlp, aoh, aol);

    // output projection
    gemm_hmma_x3<<<dim3(HID / 128, SQ / 128), 256, gemm_smem>>>(aoh, aol, woh, wol, out, SQ, HID, QDIM);
}

// round 5
// speedup vs baseline: 4.2758x; 1.4104x over previous
#include <cuda_runtime.h>
#include <cuda_fp16.h>
#include <math.h>
#include <cstdint>

#define SQ    2048
#define HID   4096
#define NH    32
#define NKV   8
#define HD    128
#define QDIM  (NH*HD)    // 4096
#define KVDIM (NKV*HD)   // 1024

// ---------------- scratch (static device allocations) ----------------
__device__ float g_Q [SQ * QDIM];
__device__ float g_K [SQ * KVDIM];
__device__ float g_V [SQ * KVDIM];

__device__ __half g_Ah [SQ * HID];
__device__ __half g_Al [SQ * HID];
__device__ __half g_AOh[SQ * QDIM];
__device__ __half g_AOl[SQ * QDIM];

__device__ __half g_Qh[SQ * QDIM];
__device__ __half g_Ql[SQ * QDIM];
__device__ __half g_Kh[SQ * KVDIM];
__device__ __half g_Vh[SQ * KVDIM];

__device__ __half g_WqT[QDIM * HID];
__device__ __half g_WkT[KVDIM * HID];
__device__ __half g_WvT[KVDIM * HID];
__device__ __half g_WoT[HID * QDIM];

// ---------------- PTX helpers (sm_80-era instructions only) ----------------
__device__ __forceinline__ uint32_t smem_u32(const void* p) {
    uint32_t a;
    asm("{ .reg .u64 t; cvta.to.shared.u64 t, %1; cvt.u32.u64 %0, t; }" : "=r"(a) : "l"(p));
    return a;
}

__device__ __forceinline__ void cpa16(uint32_t dst, const void* src) {
    asm volatile("cp.async.cg.shared.global [%0], [%1], 16;" :: "r"(dst), "l"(src) : "memory");
}
#define CP_COMMIT() asm volatile("cp.async.commit_group;" ::: "memory")
#define CP_WAIT1()  asm volatile("cp.async.wait_group 1;" ::: "memory")
#define CP_WAIT0()  asm volatile("cp.async.wait_group 0;" ::: "memory")

__device__ __forceinline__ void ldsm_x4(uint32_t& r0, uint32_t& r1, uint32_t& r2, uint32_t& r3,
                                        uint32_t addr) {
    asm volatile("ldmatrix.sync.aligned.m8n8.x4.shared.b16 {%0,%1,%2,%3}, [%4];"
                 : "=r"(r0), "=r"(r1), "=r"(r2), "=r"(r3) : "r"(addr));
}
__device__ __forceinline__ void ldsm_x4_t(uint32_t& r0, uint32_t& r1, uint32_t& r2, uint32_t& r3,
                                          uint32_t addr) {
    asm volatile("ldmatrix.sync.aligned.m8n8.x4.trans.shared.b16 {%0,%1,%2,%3}, [%4];"
                 : "=r"(r0), "=r"(r1), "=r"(r2), "=r"(r3) : "r"(addr));
}

__device__ __forceinline__ void mma_f16(float& d0, float& d1, float& d2, float& d3,
                                        uint32_t a0, uint32_t a1, uint32_t a2, uint32_t a3,
                                        uint32_t b0, uint32_t b1) {
    asm volatile("mma.sync.aligned.m16n8k16.row.col.f32.f16.f16.f32 "
                 "{%0,%1,%2,%3}, {%4,%5,%6,%7}, {%8,%9}, {%0,%1,%2,%3};"
                 : "+f"(d0), "+f"(d1), "+f"(d2), "+f"(d3)
                 : "r"(a0), "r"(a1), "r"(a2), "r"(a3), "r"(b0), "r"(b1));
}

__device__ __forceinline__ void split2h(float v, __half& h, __half& l) {
    h = __float2half_rn(v);
    l = __float2half_rn(v - __half2float(h));
}

// ---------------- fp32 -> fp16 hi/lo split (elementwise) ----------------
__global__ __launch_bounds__(256) void split_plain_h(
    const float* __restrict__ X, __half* __restrict__ H,
    __half* __restrict__ L, int n2)
{
    int i = blockIdx.x * 256 + threadIdx.x;
    if (i >= n2) return;
    float2 a = ((const float2*)X)[i];
    __half2 h, l;
    split2h(a.x, h.x, l.x);
    split2h(a.y, h.y, l.y);
    ((__half2*)H)[i] = h;
    ((__half2*)L)[i] = l;
}

// ---------------- fp32 -> fp16 convert (elementwise) ----------------
__global__ __launch_bounds__(256) void conv_h(
    const float* __restrict__ X, __half* __restrict__ H, int n2)
{
    int i = blockIdx.x * 256 + threadIdx.x;
    if (i >= n2) return;
    float2 a = ((const float2*)X)[i];
    __half2 h;
    h.x = __float2half_rn(a.x);
    h.y = __float2half_rn(a.y);
    ((__half2*)H)[i] = h;
}

// ---------------- fp32 W[K,N] -> fp16 transposed [N,K] ----------------
__global__ __launch_bounds__(256) void transpose_h(
    const float* __restrict__ W, __half* __restrict__ HT, int K, int N)
{
    __shared__ float t[32][33];
    int n0 = blockIdx.x * 32, k0 = blockIdx.y * 32;
    int tx = threadIdx.x & 31, ty = threadIdx.x >> 5;
#pragma unroll
    for (int i = 0; i < 4; ++i) {
        int ky = ty + i * 8;
        t[ky][tx] = W[(size_t)(k0 + ky) * N + n0 + tx];
    }
    __syncthreads();
#pragma unroll
    for (int i = 0; i < 4; ++i) {
        int ny = ty + i * 8;
        HT[(size_t)(n0 + ny) * K + k0 + tx] = __float2half_rn(t[tx][ny]);
    }
}

// ---------------- HMMA fp16 x2 GEMM ----------------
// C[M,N] fp32 = (Ah+Al)[M,K] @ B[N,K]^T   (error = A*Bl ~ 2^-12)
// CTA tile 128x128, 8 warps (warp tile 64x32), k-chunk 32, 3-stage cp.async.
#define SWZ_OFF(r, c8) ((r) * 64 + (((c8) ^ (((r) >> 1) & 3)) << 4))

__global__ __launch_bounds__(256, 1) void gemm_hmma_h2(
    const __half* __restrict__ Ah, const __half* __restrict__ Al,
    const __half* __restrict__ B,
    float* __restrict__ C, int M, int N, int K)
{
    extern __shared__ char smem[];
    constexpr int TILE  = 128 * 32 * 2;   // 8 KB
    constexpr int STAGE = 3 * TILE;       // Ah, Al, B = 24 KB
    const uint32_t sb = smem_u32(smem);

    const int tid  = threadIdx.x;
    const int wid  = tid >> 5;
    const int lane = tid & 31;
    const int m0 = blockIdx.y * 128;
    const int n0 = blockIdx.x * 128;
    const int wm = (wid >> 2) * 64;
    const int wn = (wid & 3) * 32;
    const int nk = K >> 5;

    const int rl = lane & 15;
    const int ch = lane >> 4;

    float acc[4][4][4];
#pragma unroll
    for (int i = 0; i < 4; ++i)
#pragma unroll
        for (int j = 0; j < 4; ++j)
#pragma unroll
            for (int q = 0; q < 4; ++q) acc[i][j][q] = 0.f;

    auto load_stage = [&](int c, int s) {
        const int kb = c * 32;
        const uint32_t st = sb + s * STAGE;
#pragma unroll
        for (int i = 0; i < 2; ++i) {
            int id = tid + i * 256;
            int r = id >> 2, c8 = id & 3;
            uint32_t off = SWZ_OFF(r, c8);
            cpa16(st + off,            Ah + (size_t)(m0 + r) * K + kb + c8 * 8);
            cpa16(st + TILE + off,     Al + (size_t)(m0 + r) * K + kb + c8 * 8);
            cpa16(st + 2 * TILE + off, B  + (size_t)(n0 + r) * K + kb + c8 * 8);
        }
        CP_COMMIT();
    };

    load_stage(0, 0);
    if (nk > 1) load_stage(1, 1);

    for (int c = 0; c < nk; ++c) {
        if (c + 1 < nk) { CP_WAIT1(); } else { CP_WAIT0(); }
        __syncthreads();
        if (c + 2 < nk) load_stage(c + 2, (c + 2) % 3);

        const uint32_t st = sb + (c % 3) * STAGE;
#pragma unroll
        for (int ks = 0; ks < 2; ++ks) {
            uint32_t ahf[4][4], alf[4][4], bf[2][4];
#pragma unroll
            for (int mt = 0; mt < 4; ++mt) {
                int r = wm + mt * 16 + rl;
                int c8 = 2 * ks + ch;
                uint32_t off = SWZ_OFF(r, c8);
                ldsm_x4(ahf[mt][0], ahf[mt][1], ahf[mt][2], ahf[mt][3], st + off);
                ldsm_x4(alf[mt][0], alf[mt][1], alf[mt][2], alf[mt][3], st + TILE + off);
            }
#pragma unroll
            for (int np = 0; np < 2; ++np) {
                int r = wn + np * 16 + rl;
                int c8 = 2 * ks + ch;
                uint32_t off = SWZ_OFF(r, c8);
                ldsm_x4(bf[np][0], bf[np][1], bf[np][2], bf[np][3], st + 2 * TILE + off);
            }
#pragma unroll
            for (int mt = 0; mt < 4; ++mt) {
#pragma unroll
                for (int nt = 0; nt < 4; ++nt) {
                    const int np = nt >> 1, sel = nt & 1;
                    float* d = acc[mt][nt];
                    mma_f16(d[0], d[1], d[2], d[3],
                            ahf[mt][0], ahf[mt][1], ahf[mt][2], ahf[mt][3],
                            bf[np][sel], bf[np][2 + sel]);
                    mma_f16(d[0], d[1], d[2], d[3],
                            alf[mt][0], alf[mt][1], alf[mt][2], alf[mt][3],
                            bf[np][sel], bf[np][2 + sel]);
                }
            }
        }
        __syncthreads();
    }

#pragma unroll
    for (int mt = 0; mt < 4; ++mt) {
#pragma unroll
        for (int nt = 0; nt < 4; ++nt) {
            int rg = m0 + wm + mt * 16 + (lane >> 2);
            int cg = n0 + wn + nt * 8 + (lane & 3) * 2;
            float* d = acc[mt][nt];
            *(float2*)(C + (size_t)rg * N + cg)       = make_float2(d[0], d[1]);
            *(float2*)(C + (size_t)(rg + 8) * N + cg) = make_float2(d[2], d[3]);
        }
    }
}

// ---------------- RoPE + pre-scale + fp16 split ----------------
// Q -> Qh/Ql (hi/lo), K -> Kh (single fp16)
__global__ __launch_bounds__(256) void rope_split(
    const float* __restrict__ Q, const float* __restrict__ K,
    const int* __restrict__ pos_ids,
    __half* __restrict__ Qh, __half* __restrict__ Ql, __half* __restrict__ Kh)
{
    const int s = blockIdx.x;
    const float scale = 0.08838834764831845f;  // 1/sqrt(128)
    __shared__ float cs[64], sn[64];
    if (threadIdx.x < 64) {
        double invf = exp(-(double)threadIdx.x * (9.210340371976184 / 64.0));
        float ang = (float)((double)pos_ids[s] * invf);
        float c, si;
        sincosf(ang, &si, &c);
        cs[threadIdx.x] = c;
        sn[threadIdx.x] = si;
    }
    __syncthreads();
#pragma unroll
    for (int it = 0; it < 8; ++it) {
        int pp = threadIdx.x + it * 256;
        int head = pp >> 6, i = pp & 63;
        size_t b = (size_t)s * QDIM + head * HD + i;
        float x0 = Q[b], x1 = Q[b + 64];
        float c = cs[i], si = sn[i];
        float y0 = (x0 * c - x1 * si) * scale;
        float y1 = (x1 * c + x0 * si) * scale;
        __half h, l;
        split2h(y0, h, l); Qh[b] = h;      Ql[b] = l;
        split2h(y1, h, l); Qh[b + 64] = h; Ql[b + 64] = l;
    }
#pragma unroll
    for (int it = 0; it < 2; ++it) {
        int pp = threadIdx.x + it * 256;
        int head = pp >> 6, i = pp & 63;
        size_t b = (size_t)s * KVDIM + head * HD + i;
        float x0 = K[b], x1 = K[b + 64];
        float c = cs[i], si = sn[i];
        Kh[b]      = __float2half_rn(x0 * c - x1 * si);
        Kh[b + 64] = __float2half_rn(x1 * c + x0 * si);
    }
}

// ---------------- HMMA flash attention (causal, fp16 x2) ----------------
// grid (16, 32): blockIdx.x -> q-block (reversed), blockIdx.y -> head.
// CTA: 128 q-rows, 8 warps of m16. K-tiles of 64, K/V single fp16 double-buffered.
// Smem row = 256B (128 fp16); 16B-group swizzle: g' = g ^ (row & 7).
#define ASWZ(row, g) ((row) * 256 + (((g) ^ ((row) & 7)) << 4))

__global__ __launch_bounds__(256) void attn_hmma(
    const __half* __restrict__ Qh, const __half* __restrict__ Ql,
    const __half* __restrict__ Kh, const __half* __restrict__ Vh,
    __half* __restrict__ AOh, __half* __restrict__ AOl)
{
    extern __shared__ char sm[];
    const uint32_t sb = smem_u32(sm);
    constexpr int MTILE = 64 * 128 * 2;     // 16 KB per matrix
    constexpr int STAGE = 2 * MTILE;        // K + V = 32 KB

    const int tid = threadIdx.x, wid = tid >> 5, lane = tid & 31;
    const int h  = blockIdx.y, kh = h >> 2;
    const int bq = gridDim.x - 1 - blockIdx.x;
    const int q0 = bq * 128;
    const int wr = wid * 16;
    const int r  = lane >> 2, c2 = (lane & 3) * 2;
    const int rl = lane & 15, chh = lane >> 4;

    // Q fragments (hi/lo), resident in registers
    uint32_t qfh[8][4], qfl[8][4];
    {
        const int row0 = q0 + wr + r;
#pragma unroll
        for (int ks = 0; ks < 8; ++ks) {
            int k2 = ks * 16 + c2;
            size_t b00 = (size_t)row0 * QDIM + h * HD + k2;
            size_t b10 = b00 + (size_t)8 * QDIM;
            qfh[ks][0] = *(const uint32_t*)(Qh + b00);
            qfh[ks][1] = *(const uint32_t*)(Qh + b10);
            qfh[ks][2] = *(const uint32_t*)(Qh + b00 + 8);
            qfh[ks][3] = *(const uint32_t*)(Qh + b10 + 8);
            qfl[ks][0] = *(const uint32_t*)(Ql + b00);
            qfl[ks][1] = *(const uint32_t*)(Ql + b10);
            qfl[ks][2] = *(const uint32_t*)(Ql + b00 + 8);
            qfl[ks][3] = *(const uint32_t*)(Ql + b10 + 8);
        }
    }

    float o[16][4];
#pragma unroll
    for (int i = 0; i < 16; ++i)
#pragma unroll
        for (int q = 0; q < 4; ++q) o[i][q] = 0.f;
    float m1 = -1e30f, m2 = -1e30f, l1 = 0.f, l2 = 0.f;

    const int ntiles = 2 * bq + 2;

    auto load_kv = [&](int kt, int s) {
        const int k0 = kt * 64;
        const uint32_t st = sb + s * STAGE;
#pragma unroll
        for (int i = 0; i < 4; ++i) {
            int id = tid + i * 256;
            int rw = id >> 4, g = id & 15;
            uint32_t off = ASWZ(rw, g);
            size_t src = (size_t)(k0 + rw) * KVDIM + kh * HD + g * 8;
            cpa16(st + off,         Kh + src);
            cpa16(st + MTILE + off, Vh + src);
        }
        CP_COMMIT();
    };

    load_kv(0, 0);

    for (int kt = 0; kt < ntiles; ++kt) {
        if (kt + 1 < ntiles) { load_kv(kt + 1, (kt + 1) & 1); CP_WAIT1(); }
        else                 { CP_WAIT0(); }
        __syncthreads();

        const uint32_t st = sb + (kt & 1) * STAGE;
        const int k0 = kt * 64;

        // ---- S = Q @ K^T (x2: Qh*K + Ql*K)
        float sacc[8][4];
#pragma unroll
        for (int i = 0; i < 8; ++i)
#pragma unroll
            for (int q = 0; q < 4; ++q) sacc[i][q] = 0.f;

#pragma unroll
        for (int ks = 0; ks < 8; ++ks) {
            uint32_t kb[4][4];
#pragma unroll
            for (int np = 0; np < 4; ++np) {
                int row = np * 16 + rl;
                int g = 2 * ks + chh;
                uint32_t off = ASWZ(row, g);
                ldsm_x4(kb[np][0], kb[np][1], kb[np][2], kb[np][3], st + off);
            }
#pragma unroll
            for (int nt = 0; nt < 8; ++nt) {
                const int np = nt >> 1, sel = nt & 1;
                float* d = sacc[nt];
                mma_f16(d[0], d[1], d[2], d[3],
                        qfh[ks][0], qfh[ks][1], qfh[ks][2], qfh[ks][3],
                        kb[np][sel], kb[np][2 + sel]);
                mma_f16(d[0], d[1], d[2], d[3],
                        qfl[ks][0], qfl[ks][1], qfl[ks][2], qfl[ks][3],
                        kb[np][sel], kb[np][2 + sel]);
            }
        }

        // ---- analytic causal mask
        if (k0 + 63 > q0 + wr) {
            const int row1 = q0 + wr + r, row2 = row1 + 8;
#pragma unroll
            for (int nt = 0; nt < 8; ++nt) {
                int col = k0 + nt * 8 + c2;
                if (col     > row1) sacc[nt][0] = -1e30f;
                if (col + 1 > row1) sacc[nt][1] = -1e30f;
                if (col     > row2) sacc[nt][2] = -1e30f;
                if (col + 1 > row2) sacc[nt][3] = -1e30f;
            }
        }

        // ---- online softmax
        float mx1 = -1e30f, mx2 = -1e30f;
#pragma unroll
        for (int nt = 0; nt < 8; ++nt) {
            mx1 = fmaxf(mx1, fmaxf(sacc[nt][0], sacc[nt][1]));
            mx2 = fmaxf(mx2, fmaxf(sacc[nt][2], sacc[nt][3]));
        }
        mx1 = fmaxf(mx1, __shfl_xor_sync(0xffffffffu, mx1, 1));
        mx1 = fmaxf(mx1, __shfl_xor_sync(0xffffffffu, mx1, 2));
        mx2 = fmaxf(mx2, __shfl_xor_sync(0xffffffffu, mx2, 1));
        mx2 = fmaxf(mx2, __shfl_xor_sync(0xffffffffu, mx2, 2));
        float nm1 = fmaxf(m1, mx1), nm2 = fmaxf(m2, mx2);
        float cf1 = __expf(m1 - nm1), cf2 = __expf(m2 - nm2);
        m1 = nm1; m2 = nm2;

        float ls1 = 0.f, ls2 = 0.f;
#pragma unroll
        for (int nt = 0; nt < 8; ++nt) {
            sacc[nt][0] = __expf(sacc[nt][0] - nm1);
            sacc[nt][1] = __expf(sacc[nt][1] - nm1);
            sacc[nt][2] = __expf(sacc[nt][2] - nm2);
            sacc[nt][3] = __expf(sacc[nt][3] - nm2);
            ls1 += sacc[nt][0] + sacc[nt][1];
            ls2 += sacc[nt][2] + sacc[nt][3];
        }
        ls1 += __shfl_xor_sync(0xffffffffu, ls1, 1);
        ls1 += __shfl_xor_sync(0xffffffffu, ls1, 2);
        ls2 += __shfl_xor_sync(0xffffffffu, ls2, 1);
        ls2 += __shfl_xor_sync(0xffffffffu, ls2, 2);
        l1 = l1 * cf1 + ls1;
        l2 = l2 * cf2 + ls2;
#pragma unroll
        for (int dt = 0; dt < 16; ++dt) {
            o[dt][0] *= cf1; o[dt][1] *= cf1;
            o[dt][2] *= cf2; o[dt][3] *= cf2;
        }

        // ---- O += P @ V (x2: Ph*V + Pl*V), V via ldmatrix.trans
#pragma unroll
        for (int s = 0; s < 4; ++s) {
            uint32_t aph[4], apl[4];
#pragma unroll
            for (int half = 0; half < 2; ++half) {
                const float* sv = sacc[2 * s + half];
                __half2 h01, l01, h23, l23;
                split2h(sv[0], h01.x, l01.x);
                split2h(sv[1], h01.y, l01.y);
                split2h(sv[2], h23.x, l23.x);
                split2h(sv[3], h23.y, l23.y);
                aph[2 * half + 0] = *(uint32_t*)&h01;
                aph[2 * half + 1] = *(uint32_t*)&h23;
                apl[2 * half + 0] = *(uint32_t*)&l01;
                apl[2 * half + 1] = *(uint32_t*)&l23;
            }
            uint32_t a0 = aph[0], a1 = aph[1], a2 = aph[2], a3 = aph[3];
            uint32_t b0 = apl[0], b1 = apl[1], b2 = apl[2], b3 = apl[3];
#pragma unroll
            for (int dg = 0; dg < 8; ++dg) {
                int row = s * 16 + rl;
                int g = 2 * dg + chh;
                uint32_t off = ASWZ(row, g);
                uint32_t v4[4];
                ldsm_x4_t(v4[0], v4[1], v4[2], v4[3], st + MTILE + off);
                float* d0 = o[2 * dg];
                float* d1 = o[2 * dg + 1];
                mma_f16(d0[0], d0[1], d0[2], d0[3], a0, a1, a2, a3, v4[0], v4[1]);
                mma_f16(d0[0], d0[1], d0[2], d0[3], b0, b1, b2, b3, v4[0], v4[1]);
                mma_f16(d1[0], d1[1], d1[2], d1[3], a0, a1, a2, a3, v4[2], v4[3]);
                mma_f16(d1[0], d1[1], d1[2], d1[3], b0, b1, b2, b3, v4[2], v4[3]);
            }
        }
        __syncthreads();
    }

    // ---- epilogue: normalize, split to fp16 hi/lo, store
    const float inv1 = 1.f / l1, inv2 = 1.f / l2;
    const int row1 = q0 + wr + r;
#pragma unroll
    for (int dt = 0; dt < 16; ++dt) {
        size_t c0 = (size_t)row1 * QDIM + h * HD + dt * 8 + c2;
        size_t c1 = c0 + (size_t)8 * QDIM;
        __half2 h01, l01;
        split2h(o[dt][0] * inv1, h01.x, l01.x);
        split2h(o[dt][1] * inv1, h01.y, l01.y);
        *(__half2*)(AOh + c0) = h01;
        *(__half2*)(AOl + c0) = l01;
        split2h(o[dt][2] * inv2, h01.x, l01.x);
        split2h(o[dt][3] * inv2, h01.y, l01.y);
        *(__half2*)(AOh + c1) = h01;
        *(__half2*)(AOl + c1) = l01;
    }
}

// ---------------- launch ----------------
extern "C" void kernel_launch(void* const* d_in, const int* in_sizes, int n_in,
                              void* d_out, int out_size)
{
    const float* hs   = (const float*)d_in[0];
    const int*   pos  = (const int*)d_in[2];
    const float* Wq   = (const float*)d_in[3];
    const float* Wk   = (const float*)d_in[4];
    const float* Wv   = (const float*)d_in[5];
    const float* Wo   = (const float*)d_in[6];
    float* out = (float*)d_out;

    float *qp, *kp, *vp;
    __half *ah, *al, *aoh, *aol, *qhp, *qlp, *khp, *vhp;
    __half *wqt, *wkt, *wvt, *wot;
    cudaGetSymbolAddress((void**)&qp,  g_Q);
    cudaGetSymbolAddress((void**)&kp,  g_K);
    cudaGetSymbolAddress((void**)&vp,  g_V);
    cudaGetSymbolAddress((void**)&ah,  g_Ah);
    cudaGetSymbolAddress((void**)&al,  g_Al);
    cudaGetSymbolAddress((void**)&aoh, g_AOh);
    cudaGetSymbolAddress((void**)&aol, g_AOl);
    cudaGetSymbolAddress((void**)&qhp, g_Qh);
    cudaGetSymbolAddress((void**)&qlp, g_Ql);
    cudaGetSymbolAddress((void**)&khp, g_Kh);
    cudaGetSymbolAddress((void**)&vhp, g_Vh);
    cudaGetSymbolAddress((void**)&wqt, g_WqT);
    cudaGetSymbolAddress((void**)&wkt, g_WkT);
    cudaGetSymbolAddress((void**)&wvt, g_WvT);
    cudaGetSymbolAddress((void**)&wot, g_WoT);

    const int gemm_smem = 3 * 3 * 128 * 32 * 2;   // 73728
    cudaFuncSetAttribute(gemm_hmma_h2, cudaFuncAttributeMaxDynamicSharedMemorySize, gemm_smem);
    const int attn_smem = 2 * 2 * 64 * 128 * 2;   // 65536
    cudaFuncSetAttribute(attn_hmma, cudaFuncAttributeMaxDynamicSharedMemorySize, attn_smem);

    // splits / converts
    split_plain_h<<<(SQ * HID / 2 + 255) / 256, 256>>>(hs, ah, al, SQ * HID / 2);
    transpose_h<<<dim3(QDIM / 32,  HID / 32), 256>>>(Wq, wqt, HID, QDIM);
    transpose_h<<<dim3(KVDIM / 32, HID / 32), 256>>>(Wk, wkt, HID, KVDIM);
    transpose_h<<<dim3(KVDIM / 32, HID / 32), 256>>>(Wv, wvt, HID, KVDIM);
    transpose_h<<<dim3(HID / 32,  QDIM / 32), 256>>>(Wo, wot, QDIM, HID);

    // QKV projections (fp16 x2)
    gemm_hmma_h2<<<dim3(QDIM / 128,  SQ / 128), 256, gemm_smem>>>(ah, al, wqt, qp, SQ, QDIM,  HID);
    gemm_hmma_h2<<<dim3(KVDIM / 128, SQ / 128), 256, gemm_smem>>>(ah, al, wkt, kp, SQ, KVDIM, HID);
    gemm_hmma_h2<<<dim3(KVDIM / 128, SQ / 128), 256, gemm_smem>>>(ah, al, wvt, vp, SQ, KVDIM, HID);

    // RoPE + split Q (hi/lo), K (fp16); convert V (fp16)
    rope_split<<<SQ, 256>>>(qp, kp, pos, qhp, qlp, khp);
    conv_h<<<(SQ * KVDIM / 2 + 255) / 256, 256>>>(vp, vhp, SQ * KVDIM / 2);

    // attention
    attn_hmma<<<dim3(SQ / 128, NH), 256, attn_smem>>>(qhp, qlp, khp, vhp, aoh, aol);

    // output projection
    gemm_hmma_h2<<<dim3(HID / 128, SQ / 128), 256, gemm_smem>>>(aoh, aol, wot, out, SQ, HID, QDIM);
}

// round 6
// speedup vs baseline: 4.3683x; 1.0217x over previous
#include <cuda_runtime.h>
#include <cuda_fp16.h>
#include <math.h>
#include <cstdint>

#define SQ    2048
#define HID   4096
#define NH    32
#define NKV   8
#define HD    128
#define QDIM  (NH*HD)    // 4096
#define KVDIM (NKV*HD)   // 1024

// ---------------- scratch (static device allocations) ----------------
__device__ float g_Q [SQ * QDIM];
__device__ float g_KV[SQ * 2 * KVDIM];   // cols 0-1023 = K, 1024-2047 = V

__device__ __half g_Ah [SQ * HID];
__device__ __half g_Al [SQ * HID];
__device__ __half g_AOh[SQ * QDIM];
__device__ __half g_AOl[SQ * QDIM];

__device__ __half g_Qh[SQ * QDIM];
__device__ __half g_Ql[SQ * QDIM];
__device__ __half g_Kh[SQ * KVDIM];
__device__ __half g_Vh[SQ * KVDIM];

__device__ __half g_WqT [QDIM * HID];
__device__ __half g_WkvT[2 * KVDIM * HID];
__device__ __half g_WoT [HID * QDIM];

// ---------------- PTX helpers (sm_80-era instructions only) ----------------
__device__ __forceinline__ uint32_t smem_u32(const void* p) {
    uint32_t a;
    asm("{ .reg .u64 t; cvta.to.shared.u64 t, %1; cvt.u32.u64 %0, t; }" : "=r"(a) : "l"(p));
    return a;
}

__device__ __forceinline__ void cpa16(uint32_t dst, const void* src) {
    asm volatile("cp.async.cg.shared.global [%0], [%1], 16;" :: "r"(dst), "l"(src) : "memory");
}
#define CP_COMMIT() asm volatile("cp.async.commit_group;" ::: "memory")
#define CP_WAIT1()  asm volatile("cp.async.wait_group 1;" ::: "memory")
#define CP_WAIT0()  asm volatile("cp.async.wait_group 0;" ::: "memory")

__device__ __forceinline__ void ldsm_x4(uint32_t& r0, uint32_t& r1, uint32_t& r2, uint32_t& r3,
                                        uint32_t addr) {
    asm volatile("ldmatrix.sync.aligned.m8n8.x4.shared.b16 {%0,%1,%2,%3}, [%4];"
                 : "=r"(r0), "=r"(r1), "=r"(r2), "=r"(r3) : "r"(addr));
}
__device__ __forceinline__ void ldsm_x4_t(uint32_t& r0, uint32_t& r1, uint32_t& r2, uint32_t& r3,
                                          uint32_t addr) {
    asm volatile("ldmatrix.sync.aligned.m8n8.x4.trans.shared.b16 {%0,%1,%2,%3}, [%4];"
                 : "=r"(r0), "=r"(r1), "=r"(r2), "=r"(r3) : "r"(addr));
}

__device__ __forceinline__ void mma_f16(float& d0, float& d1, float& d2, float& d3,
                                        uint32_t a0, uint32_t a1, uint32_t a2, uint32_t a3,
                                        uint32_t b0, uint32_t b1) {
    asm volatile("mma.sync.aligned.m16n8k16.row.col.f32.f16.f16.f32 "
                 "{%0,%1,%2,%3}, {%4,%5,%6,%7}, {%8,%9}, {%0,%1,%2,%3};"
                 : "+f"(d0), "+f"(d1), "+f"(d2), "+f"(d3)
                 : "r"(a0), "r"(a1), "r"(a2), "r"(a3), "r"(b0), "r"(b1));
}

__device__ __forceinline__ void split2h(float v, __half& h, __half& l) {
    h = __float2half_rn(v);
    l = __float2half_rn(v - __half2float(h));
}

// ---------------- fp32 -> fp16 hi/lo split (elementwise, float4) ----------------
__global__ __launch_bounds__(256) void split_plain_h(
    const float* __restrict__ X, __half* __restrict__ H,
    __half* __restrict__ L, int n4)
{
    int i = blockIdx.x * 256 + threadIdx.x;
    if (i >= n4) return;
    float4 a = ((const float4*)X)[i];
    __half2 h0, l0, h1, l1;
    split2h(a.x, h0.x, l0.x);
    split2h(a.y, h0.y, l0.y);
    split2h(a.z, h1.x, l1.x);
    split2h(a.w, h1.y, l1.y);
    ((__half2*)H)[2 * i]     = h0;
    ((__half2*)H)[2 * i + 1] = h1;
    ((__half2*)L)[2 * i]     = l0;
    ((__half2*)L)[2 * i + 1] = l1;
}

// ---------------- strided V fp32 -> fp16 convert ----------------
// V lives in g_KV[s*2048 + 1024 + j]; write contiguous Vh[s*1024 + j]
__global__ __launch_bounds__(256) void conv_v(
    const float* __restrict__ KV, __half* __restrict__ Vh)
{
    int s = blockIdx.x;
    const float* src = KV + (size_t)s * (2 * KVDIM) + KVDIM;
    __half* dst = Vh + (size_t)s * KVDIM;
#pragma unroll
    for (int it = 0; it < 1; ++it) {
        int j = threadIdx.x * 4;     // 256 threads * 4 = 1024
        float4 a = *(const float4*)(src + j);
        __half2 h0, h1;
        h0.x = __float2half_rn(a.x); h0.y = __float2half_rn(a.y);
        h1.x = __float2half_rn(a.z); h1.y = __float2half_rn(a.w);
        *(__half2*)(dst + j)     = h0;
        *(__half2*)(dst + j + 2) = h1;
    }
}

// ---------------- fp32 W[K,N] -> fp16 transposed [N,K] ----------------
__global__ __launch_bounds__(256) void transpose_h(
    const float* __restrict__ W, __half* __restrict__ HT, int K, int N)
{
    __shared__ float t[32][33];
    int n0 = blockIdx.x * 32, k0 = blockIdx.y * 32;
    int tx = threadIdx.x & 31, ty = threadIdx.x >> 5;
#pragma unroll
    for (int i = 0; i < 4; ++i) {
        int ky = ty + i * 8;
        t[ky][tx] = W[(size_t)(k0 + ky) * N + n0 + tx];
    }
    __syncthreads();
#pragma unroll
    for (int i = 0; i < 4; ++i) {
        int ny = ty + i * 8;
        HT[(size_t)(n0 + ny) * K + k0 + tx] = __float2half_rn(t[tx][ny]);
    }
}

// ---------------- HMMA fp16 x2 GEMM, CTA 128x256, warp 64x64 ----------------
// C[M,N] fp32 = (Ah+Al)[M,K] @ B[N,K]^T   (error = A*Bl ~ 2^-12)
// 8 warps arranged 2(m) x 4(n). k-chunk 32, 3-stage cp.async.
#define SWZ_OFF(r, c8) ((r) * 64 + (((c8) ^ (((r) >> 1) & 3)) << 4))

__global__ __launch_bounds__(256, 1) void gemm_hmma_h2(
    const __half* __restrict__ Ah, const __half* __restrict__ Al,
    const __half* __restrict__ B,
    float* __restrict__ C, int M, int N, int K)
{
    extern __shared__ char smem[];
    constexpr int TILE_A = 128 * 32 * 2;    // 8 KB (one A matrix)
    constexpr int TILE_B = 256 * 32 * 2;    // 16 KB
    constexpr int STAGE  = 2 * TILE_A + TILE_B;  // 32 KB
    const uint32_t sb = smem_u32(smem);

    const int tid  = threadIdx.x;
    const int wid  = tid >> 5;
    const int lane = tid & 31;
    const int m0 = blockIdx.y * 128;
    const int n0 = blockIdx.x * 256;
    const int wm = (wid >> 2) * 64;      // 0 or 64
    const int wn = (wid & 3) * 64;       // 0..192
    const int nk = K >> 5;

    const int rl = lane & 15;
    const int ch = lane >> 4;

    float acc[4][8][4];
#pragma unroll
    for (int i = 0; i < 4; ++i)
#pragma unroll
        for (int j = 0; j < 8; ++j)
#pragma unroll
            for (int q = 0; q < 4; ++q) acc[i][j][q] = 0.f;

    auto load_stage = [&](int c, int s) {
        const int kb = c * 32;
        const uint32_t st = sb + s * STAGE;
#pragma unroll
        for (int i = 0; i < 2; ++i) {     // A hi + lo: 128 rows x 64B each
            int id = tid + i * 256;
            int r = id >> 2, c8 = id & 3;
            uint32_t off = SWZ_OFF(r, c8);
            cpa16(st + off,          Ah + (size_t)(m0 + r) * K + kb + c8 * 8);
            cpa16(st + TILE_A + off, Al + (size_t)(m0 + r) * K + kb + c8 * 8);
        }
#pragma unroll
        for (int i = 0; i < 4; ++i) {     // B: 256 rows x 64B
            int id = tid + i * 256;
            int r = id >> 2, c8 = id & 3;
            uint32_t off = SWZ_OFF(r, c8);
            cpa16(st + 2 * TILE_A + off, B + (size_t)(n0 + r) * K + kb + c8 * 8);
        }
        CP_COMMIT();
    };

    load_stage(0, 0);
    if (nk > 1) load_stage(1, 1);

    for (int c = 0; c < nk; ++c) {
        if (c + 1 < nk) { CP_WAIT1(); } else { CP_WAIT0(); }
        __syncthreads();
        if (c + 2 < nk) load_stage(c + 2, (c + 2) % 3);

        const uint32_t st = sb + (c % 3) * STAGE;
#pragma unroll
        for (int ks = 0; ks < 2; ++ks) {
            uint32_t ahf[4][4], alf[4][4], bf[4][4];
#pragma unroll
            for (int mt = 0; mt < 4; ++mt) {
                int r = wm + mt * 16 + rl;
                int c8 = 2 * ks + ch;
                uint32_t off = SWZ_OFF(r, c8);
                ldsm_x4(ahf[mt][0], ahf[mt][1], ahf[mt][2], ahf[mt][3], st + off);
                ldsm_x4(alf[mt][0], alf[mt][1], alf[mt][2], alf[mt][3], st + TILE_A + off);
            }
#pragma unroll
            for (int np = 0; np < 4; ++np) {
                int r = wn + np * 16 + rl;
                int c8 = 2 * ks + ch;
                uint32_t off = SWZ_OFF(r, c8);
                ldsm_x4(bf[np][0], bf[np][1], bf[np][2], bf[np][3], st + 2 * TILE_A + off);
            }
#pragma unroll
            for (int mt = 0; mt < 4; ++mt) {
#pragma unroll
                for (int nt = 0; nt < 8; ++nt) {
                    const int np = nt >> 1, sel = nt & 1;
                    float* d = acc[mt][nt];
                    mma_f16(d[0], d[1], d[2], d[3],
                            ahf[mt][0], ahf[mt][1], ahf[mt][2], ahf[mt][3],
                            bf[np][sel], bf[np][2 + sel]);
                    mma_f16(d[0], d[1], d[2], d[3],
                            alf[mt][0], alf[mt][1], alf[mt][2], alf[mt][3],
                            bf[np][sel], bf[np][2 + sel]);
                }
            }
        }
        __syncthreads();
    }

#pragma unroll
    for (int mt = 0; mt < 4; ++mt) {
#pragma unroll
        for (int nt = 0; nt < 8; ++nt) {
            int rg = m0 + wm + mt * 16 + (lane >> 2);
            int cg = n0 + wn + nt * 8 + (lane & 3) * 2;
            float* d = acc[mt][nt];
            *(float2*)(C + (size_t)rg * N + cg)       = make_float2(d[0], d[1]);
            *(float2*)(C + (size_t)(rg + 8) * N + cg) = make_float2(d[2], d[3]);
        }
    }
}

// ---------------- RoPE + pre-scale + fp16 split ----------------
// Q (contiguous [SQ,QDIM]) -> Qh/Ql ; K (strided in g_KV) -> Kh
__global__ __launch_bounds__(256) void rope_split(
    const float* __restrict__ Q, const float* __restrict__ KV,
    const int* __restrict__ pos_ids,
    __half* __restrict__ Qh, __half* __restrict__ Ql, __half* __restrict__ Kh)
{
    const int s = blockIdx.x;
    const float scale = 0.08838834764831845f;  // 1/sqrt(128)
    __shared__ float cs[64], sn[64];
    if (threadIdx.x < 64) {
        double invf = exp(-(double)threadIdx.x * (9.210340371976184 / 64.0));
        float ang = (float)((double)pos_ids[s] * invf);
        float c, si;
        sincosf(ang, &si, &c);
        cs[threadIdx.x] = c;
        sn[threadIdx.x] = si;
    }
    __syncthreads();
#pragma unroll
    for (int it = 0; it < 8; ++it) {
        int pp = threadIdx.x + it * 256;
        int head = pp >> 6, i = pp & 63;
        size_t b = (size_t)s * QDIM + head * HD + i;
        float x0 = Q[b], x1 = Q[b + 64];
        float c = cs[i], si = sn[i];
        float y0 = (x0 * c - x1 * si) * scale;
        float y1 = (x1 * c + x0 * si) * scale;
        __half h, l;
        split2h(y0, h, l); Qh[b] = h;      Ql[b] = l;
        split2h(y1, h, l); Qh[b + 64] = h; Ql[b + 64] = l;
    }
#pragma unroll
    for (int it = 0; it < 2; ++it) {
        int pp = threadIdx.x + it * 256;
        int head = pp >> 6, i = pp & 63;
        size_t bs = (size_t)s * (2 * KVDIM) + head * HD + i;   // K in g_KV
        size_t bd = (size_t)s * KVDIM + head * HD + i;
        float x0 = KV[bs], x1 = KV[bs + 64];
        float c = cs[i], si = sn[i];
        Kh[bd]      = __float2half_rn(x0 * c - x1 * si);
        Kh[bd + 64] = __float2half_rn(x1 * c + x0 * si);
    }
}

// ---------------- HMMA flash attention (causal, fp16 x2) ----------------
#define ASWZ(row, g) ((row) * 256 + (((g) ^ ((row) & 7)) << 4))

__global__ __launch_bounds__(256) void attn_hmma(
    const __half* __restrict__ Qh, const __half* __restrict__ Ql,
    const __half* __restrict__ Kh, const __half* __restrict__ Vh,
    __half* __restrict__ AOh, __half* __restrict__ AOl)
{
    extern __shared__ char sm[];
    const uint32_t sb = smem_u32(sm);
    constexpr int MTILE = 64 * 128 * 2;     // 16 KB per matrix
    constexpr int STAGE = 2 * MTILE;        // K + V = 32 KB

    const int tid = threadIdx.x, wid = tid >> 5, lane = tid & 31;
    const int h  = blockIdx.y, kh = h >> 2;
    const int bq = gridDim.x - 1 - blockIdx.x;
    const int q0 = bq * 128;
    const int wr = wid * 16;
    const int r  = lane >> 2, c2 = (lane & 3) * 2;
    const int rl = lane & 15, chh = lane >> 4;

    uint32_t qfh[8][4], qfl[8][4];
    {
        const int row0 = q0 + wr + r;
#pragma unroll
        for (int ks = 0; ks < 8; ++ks) {
            int k2 = ks * 16 + c2;
            size_t b00 = (size_t)row0 * QDIM + h * HD + k2;
            size_t b10 = b00 + (size_t)8 * QDIM;
            qfh[ks][0] = *(const uint32_t*)(Qh + b00);
            qfh[ks][1] = *(const uint32_t*)(Qh + b10);
            qfh[ks][2] = *(const uint32_t*)(Qh + b00 + 8);
            qfh[ks][3] = *(const uint32_t*)(Qh + b10 + 8);
            qfl[ks][0] = *(const uint32_t*)(Ql + b00);
            qfl[ks][1] = *(const uint32_t*)(Ql + b10);
            qfl[ks][2] = *(const uint32_t*)(Ql + b00 + 8);
            qfl[ks][3] = *(const uint32_t*)(Ql + b10 + 8);
        }
    }

    float o[16][4];
#pragma unroll
    for (int i = 0; i < 16; ++i)
#pragma unroll
        for (int q = 0; q < 4; ++q) o[i][q] = 0.f;
    float m1 = -1e30f, m2 = -1e30f, l1 = 0.f, l2 = 0.f;

    const int ntiles = 2 * bq + 2;

    auto load_kv = [&](int kt, int s) {
        const int k0 = kt * 64;
        const uint32_t st = sb + s * STAGE;
#pragma unroll
        for (int i = 0; i < 4; ++i) {
            int id = tid + i * 256;
            int rw = id >> 4, g = id & 15;
            uint32_t off = ASWZ(rw, g);
            size_t src = (size_t)(k0 + rw) * KVDIM + kh * HD + g * 8;
            cpa16(st + off,         Kh + src);
            cpa16(st + MTILE + off, Vh + src);
        }
        CP_COMMIT();
    };

    load_kv(0, 0);

    for (int kt = 0; kt < ntiles; ++kt) {
        if (kt + 1 < ntiles) { load_kv(kt + 1, (kt + 1) & 1); CP_WAIT1(); }
        else                 { CP_WAIT0(); }
        __syncthreads();

        const uint32_t st = sb + (kt & 1) * STAGE;
        const int k0 = kt * 64;

        float sacc[8][4];
#pragma unroll
        for (int i = 0; i < 8; ++i)
#pragma unroll
            for (int q = 0; q < 4; ++q) sacc[i][q] = 0.f;

#pragma unroll
        for (int ks = 0; ks < 8; ++ks) {
            uint32_t kb[4][4];
#pragma unroll
            for (int np = 0; np < 4; ++np) {
                int row = np * 16 + rl;
                int g = 2 * ks + chh;
                uint32_t off = ASWZ(row, g);
                ldsm_x4(kb[np][0], kb[np][1], kb[np][2], kb[np][3], st + off);
            }
#pragma unroll
            for (int nt = 0; nt < 8; ++nt) {
                const int np = nt >> 1, sel = nt & 1;
                float* d = sacc[nt];
                mma_f16(d[0], d[1], d[2], d[3],
                        qfh[ks][0], qfh[ks][1], qfh[ks][2], qfh[ks][3],
                        kb[np][sel], kb[np][2 + sel]);
                mma_f16(d[0], d[1], d[2], d[3],
                        qfl[ks][0], qfl[ks][1], qfl[ks][2], qfl[ks][3],
                        kb[np][sel], kb[np][2 + sel]);
            }
        }

        if (k0 + 63 > q0 + wr) {
            const int row1 = q0 + wr + r, row2 = row1 + 8;
#pragma unroll
            for (int nt = 0; nt < 8; ++nt) {
                int col = k0 + nt * 8 + c2;
                if (col     > row1) sacc[nt][0] = -1e30f;
                if (col + 1 > row1) sacc[nt][1] = -1e30f;
                if (col     > row2) sacc[nt][2] = -1e30f;
                if (col + 1 > row2) sacc[nt][3] = -1e30f;
            }
        }

        float mx1 = -1e30f, mx2 = -1e30f;
#pragma unroll
        for (int nt = 0; nt < 8; ++nt) {
            mx1 = fmaxf(mx1, fmaxf(sacc[nt][0], sacc[nt][1]));
            mx2 = fmaxf(mx2, fmaxf(sacc[nt][2], sacc[nt][3]));
        }
        mx1 = fmaxf(mx1, __shfl_xor_sync(0xffffffffu, mx1, 1));
        mx1 = fmaxf(mx1, __shfl_xor_sync(0xffffffffu, mx1, 2));
        mx2 = fmaxf(mx2, __shfl_xor_sync(0xffffffffu, mx2, 1));
        mx2 = fmaxf(mx2, __shfl_xor_sync(0xffffffffu, mx2, 2));
        float nm1 = fmaxf(m1, mx1), nm2 = fmaxf(m2, mx2);
        float cf1 = __expf(m1 - nm1), cf2 = __expf(m2 - nm2);
        m1 = nm1; m2 = nm2;

        float ls1 = 0.f, ls2 = 0.f;
#pragma unroll
        for (int nt = 0; nt < 8; ++nt) {
            sacc[nt][0] = __expf(sacc[nt][0] - nm1);
            sacc[nt][1] = __expf(sacc[nt][1] - nm1);
            sacc[nt][2] = __expf(sacc[nt][2] - nm2);
            sacc[nt][3] = __expf(sacc[nt][3] - nm2);
            ls1 += sacc[nt][0] + sacc[nt][1];
            ls2 += sacc[nt][2] + sacc[nt][3];
        }
        ls1 += __shfl_xor_sync(0xffffffffu, ls1, 1);
        ls1 += __shfl_xor_sync(0xffffffffu, ls1, 2);
        ls2 += __shfl_xor_sync(0xffffffffu, ls2, 1);
        ls2 += __shfl_xor_sync(0xffffffffu, ls2, 2);
        l1 = l1 * cf1 + ls1;
        l2 = l2 * cf2 + ls2;
#pragma unroll
        for (int dt = 0; dt < 16; ++dt) {
            o[dt][0] *= cf1; o[dt][1] *= cf1;
            o[dt][2] *= cf2; o[dt][3] *= cf2;
        }

#pragma unroll
        for (int s = 0; s < 4; ++s) {
            uint32_t aph[4], apl[4];
#pragma unroll
            for (int half = 0; half < 2; ++half) {
                const float* sv = sacc[2 * s + half];
                __half2 h01, l01, h23, l23;
                split2h(sv[0], h01.x, l01.x);
                split2h(sv[1], h01.y, l01.y);
                split2h(sv[2], h23.x, l23.x);
                split2h(sv[3], h23.y, l23.y);
                aph[2 * half + 0] = *(uint32_t*)&h01;
                aph[2 * half + 1] = *(uint32_t*)&h23;
                apl[2 * half + 0] = *(uint32_t*)&l01;
                apl[2 * half + 1] = *(uint32_t*)&l23;
            }
            uint32_t a0 = aph[0], a1 = aph[1], a2 = aph[2], a3 = aph[3];
            uint32_t b0 = apl[0], b1 = apl[1], b2 = apl[2], b3 = apl[3];
#pragma unroll
            for (int dg = 0; dg < 8; ++dg) {
                int row = s * 16 + rl;
                int g = 2 * dg + chh;
                uint32_t off = ASWZ(row, g);
                uint32_t v4[4];
                ldsm_x4_t(v4[0], v4[1], v4[2], v4[3], st + MTILE + off);
                float* d0 = o[2 * dg];
                float* d1 = o[2 * dg + 1];
                mma_f16(d0[0], d0[1], d0[2], d0[3], a0, a1, a2, a3, v4[0], v4[1]);
                mma_f16(d0[0], d0[1], d0[2], d0[3], b0, b1, b2, b3, v4[0], v4[1]);
                mma_f16(d1[0], d1[1], d1[2], d1[3], a0, a1, a2, a3, v4[2], v4[3]);
                mma_f16(d1[0], d1[1], d1[2], d1[3], b0, b1, b2, b3, v4[2], v4[3]);
            }
        }
        __syncthreads();
    }

    const float inv1 = 1.f / l1, inv2 = 1.f / l2;
    const int row1 = q0 + wr + r;
#pragma unroll
    for (int dt = 0; dt < 16; ++dt) {
        size_t c0 = (size_t)row1 * QDIM + h * HD + dt * 8 + c2;
        size_t c1 = c0 + (size_t)8 * QDIM;
        __half2 h01, l01;
        split2h(o[dt][0] * inv1, h01.x, l01.x);
        split2h(o[dt][1] * inv1, h01.y, l01.y);
        *(__half2*)(AOh + c0) = h01;
        *(__half2*)(AOl + c0) = l01;
        split2h(o[dt][2] * inv2, h01.x, l01.x);
        split2h(o[dt][3] * inv2, h01.y, l01.y);
        *(__half2*)(AOh + c1) = h01;
        *(__half2*)(AOl + c1) = l01;
    }
}

// ---------------- launch ----------------
extern "C" void kernel_launch(void* const* d_in, const int* in_sizes, int n_in,
                              void* d_out, int out_size)
{
    const float* hs   = (const float*)d_in[0];
    const int*   pos  = (const int*)d_in[2];
    const float* Wq   = (const float*)d_in[3];
    const float* Wk   = (const float*)d_in[4];
    const float* Wv   = (const float*)d_in[5];
    const float* Wo   = (const float*)d_in[6];
    float* out = (float*)d_out;

    float *qp, *kvp;
    __half *ah, *al, *aoh, *aol, *qhp, *qlp, *khp, *vhp;
    __half *wqt, *wkvt, *wot;
    cudaGetSymbolAddress((void**)&qp,   g_Q);
    cudaGetSymbolAddress((void**)&kvp,  g_KV);
    cudaGetSymbolAddress((void**)&ah,   g_Ah);
    cudaGetSymbolAddress((void**)&al,   g_Al);
    cudaGetSymbolAddress((void**)&aoh,  g_AOh);
    cudaGetSymbolAddress((void**)&aol,  g_AOl);
    cudaGetSymbolAddress((void**)&qhp,  g_Qh);
    cudaGetSymbolAddress((void**)&qlp,  g_Ql);
    cudaGetSymbolAddress((void**)&khp,  g_Kh);
    cudaGetSymbolAddress((void**)&vhp,  g_Vh);
    cudaGetSymbolAddress((void**)&wqt,  g_WqT);
    cudaGetSymbolAddress((void**)&wkvt, g_WkvT);
    cudaGetSymbolAddress((void**)&wot,  g_WoT);

    const int gemm_smem = 3 * (2 * 128 * 32 * 2 + 256 * 32 * 2);  // 98304
    cudaFuncSetAttribute(gemm_hmma_h2, cudaFuncAttributeMaxDynamicSharedMemorySize, gemm_smem);
    const int attn_smem = 2 * 2 * 64 * 128 * 2;   // 65536
    cudaFuncSetAttribute(attn_hmma, cudaFuncAttributeMaxDynamicSharedMemorySize, attn_smem);

    // splits / converts
    split_plain_h<<<(SQ * HID / 4 + 255) / 256, 256>>>(hs, ah, al, SQ * HID / 4);
    transpose_h<<<dim3(QDIM / 32,  HID / 32), 256>>>(Wq, wqt, HID, QDIM);
    transpose_h<<<dim3(KVDIM / 32, HID / 32), 256>>>(Wk, wkvt, HID, KVDIM);
    transpose_h<<<dim3(KVDIM / 32, HID / 32), 256>>>(Wv, wkvt + (size_t)KVDIM * HID, HID, KVDIM);
    transpose_h<<<dim3(HID / 32,  QDIM / 32), 256>>>(Wo, wot, QDIM, HID);

    // projections: Q (N=4096), fused KV (N=2048)
    gemm_hmma_h2<<<dim3(QDIM / 256,     SQ / 128), 256, gemm_smem>>>(ah, al, wqt,  qp,  SQ, QDIM,      HID);
    gemm_hmma_h2<<<dim3(2*KVDIM / 256,  SQ / 128), 256, gemm_smem>>>(ah, al, wkvt, kvp, SQ, 2*KVDIM,   HID);

    // RoPE + split Q (hi/lo), K (fp16); convert V (fp16)
    rope_split<<<SQ, 256>>>(qp, kvp, pos, qhp, qlp, khp);
    conv_v<<<SQ, 256>>>(kvp, vhp);

    // attention
    attn_hmma<<<dim3(SQ / 128, NH), 256, attn_smem>>>(qhp, qlp, khp, vhp, aoh, aol);

    // output projection
    gemm_hmma_h2<<<dim3(HID / 256, SQ / 128), 256, gemm_smem>>>(aoh, aol, wot, out, SQ, HID, QDIM);
}

// round 7
// speedup vs baseline: 6.6422x; 1.5205x over previous
#include <cuda_runtime.h>
#include <cuda_fp16.h>
#include <math.h>
#include <cstdint>

#define SQ    2048
#define HID   4096
#define NH    32
#define NKV   8
#define HD    128
#define QDIM  (NH*HD)    // 4096
#define KVDIM (NKV*HD)   // 1024

// ---------------- scratch (static device allocations) ----------------
__device__ float g_Q [SQ * QDIM];
__device__ float g_KV[SQ * 2 * KVDIM];   // cols 0-1023 = K, 1024-2047 = V

__device__ __half g_Ah [SQ * HID];
__device__ __half g_AOh[SQ * QDIM];

__device__ __half g_Qh[SQ * QDIM];
__device__ __half g_Ql[SQ * QDIM];
__device__ __half g_Kh[SQ * KVDIM];
__device__ __half g_Vh[SQ * KVDIM];

__device__ __half g_WqT [QDIM * HID];
__device__ __half g_WkvT[2 * KVDIM * HID];
__device__ __half g_WoT [HID * QDIM];

// ---------------- PTX helpers (sm_80-era instructions only) ----------------
__device__ __forceinline__ uint32_t smem_u32(const void* p) {
    uint32_t a;
    asm("{ .reg .u64 t; cvta.to.shared.u64 t, %1; cvt.u32.u64 %0, t; }" : "=r"(a) : "l"(p));
    return a;
}

__device__ __forceinline__ void cpa16(uint32_t dst, const void* src) {
    asm volatile("cp.async.cg.shared.global [%0], [%1], 16;" :: "r"(dst), "l"(src) : "memory");
}
#define CP_COMMIT() asm volatile("cp.async.commit_group;" ::: "memory")
#define CP_WAIT1()  asm volatile("cp.async.wait_group 1;" ::: "memory")
#define CP_WAIT0()  asm volatile("cp.async.wait_group 0;" ::: "memory")

__device__ __forceinline__ void ldsm_x4(uint32_t& r0, uint32_t& r1, uint32_t& r2, uint32_t& r3,
                                        uint32_t addr) {
    asm volatile("ldmatrix.sync.aligned.m8n8.x4.shared.b16 {%0,%1,%2,%3}, [%4];"
                 : "=r"(r0), "=r"(r1), "=r"(r2), "=r"(r3) : "r"(addr));
}
__device__ __forceinline__ void ldsm_x4_t(uint32_t& r0, uint32_t& r1, uint32_t& r2, uint32_t& r3,
                                          uint32_t addr) {
    asm volatile("ldmatrix.sync.aligned.m8n8.x4.trans.shared.b16 {%0,%1,%2,%3}, [%4];"
                 : "=r"(r0), "=r"(r1), "=r"(r2), "=r"(r3) : "r"(addr));
}

__device__ __forceinline__ void mma_f16(float& d0, float& d1, float& d2, float& d3,
                                        uint32_t a0, uint32_t a1, uint32_t a2, uint32_t a3,
                                        uint32_t b0, uint32_t b1) {
    asm volatile("mma.sync.aligned.m16n8k16.row.col.f32.f16.f16.f32 "
                 "{%0,%1,%2,%3}, {%4,%5,%6,%7}, {%8,%9}, {%0,%1,%2,%3};"
                 : "+f"(d0), "+f"(d1), "+f"(d2), "+f"(d3)
                 : "r"(a0), "r"(a1), "r"(a2), "r"(a3), "r"(b0), "r"(b1));
}

__device__ __forceinline__ void split2h(float v, __half& h, __half& l) {
    h = __float2half_rn(v);
    l = __float2half_rn(v - __half2float(h));
}

// ---------------- fp32 -> fp16 convert (elementwise, float4) ----------------
__global__ __launch_bounds__(256) void conv_plain(
    const float* __restrict__ X, __half* __restrict__ H, int n4)
{
    int i = blockIdx.x * 256 + threadIdx.x;
    if (i >= n4) return;
    float4 a = ((const float4*)X)[i];
    __half2 h0, h1;
    h0.x = __float2half_rn(a.x); h0.y = __float2half_rn(a.y);
    h1.x = __float2half_rn(a.z); h1.y = __float2half_rn(a.w);
    ((__half2*)H)[2 * i]     = h0;
    ((__half2*)H)[2 * i + 1] = h1;
}

// ---------------- strided V fp32 -> fp16 convert ----------------
__global__ __launch_bounds__(256) void conv_v(
    const float* __restrict__ KV, __half* __restrict__ Vh)
{
    int s = blockIdx.x;
    const float* src = KV + (size_t)s * (2 * KVDIM) + KVDIM;
    __half* dst = Vh + (size_t)s * KVDIM;
    int j = threadIdx.x * 4;
    float4 a = *(const float4*)(src + j);
    __half2 h0, h1;
    h0.x = __float2half_rn(a.x); h0.y = __float2half_rn(a.y);
    h1.x = __float2half_rn(a.z); h1.y = __float2half_rn(a.w);
    *(__half2*)(dst + j)     = h0;
    *(__half2*)(dst + j + 2) = h1;
}

// ---------------- fp32 W[K,N] -> fp16 transposed [N,K] ----------------
__global__ __launch_bounds__(256) void transpose_h(
    const float* __restrict__ W, __half* __restrict__ HT, int K, int N)
{
    __shared__ float t[32][33];
    int n0 = blockIdx.x * 32, k0 = blockIdx.y * 32;
    int tx = threadIdx.x & 31, ty = threadIdx.x >> 5;
#pragma unroll
    for (int i = 0; i < 4; ++i) {
        int ky = ty + i * 8;
        t[ky][tx] = W[(size_t)(k0 + ky) * N + n0 + tx];
    }
    __syncthreads();
#pragma unroll
    for (int i = 0; i < 4; ++i) {
        int ny = ty + i * 8;
        HT[(size_t)(n0 + ny) * K + k0 + tx] = __float2half_rn(t[tx][ny]);
    }
}

// ---------------- HMMA fp16 GEMM, CTA 128x256, warp 64x64 ----------------
// C[M,N] fp32 = A[M,K] @ B[N,K]^T  (plain fp16, fp32 accum)
// 8 warps arranged 2(m) x 4(n). k-chunk 32, 3-stage cp.async.
#define SWZ_OFF(r, c8) ((r) * 64 + (((c8) ^ (((r) >> 1) & 3)) << 4))

__global__ __launch_bounds__(256, 1) void gemm_hmma_h1(
    const __half* __restrict__ A, const __half* __restrict__ B,
    float* __restrict__ C, int M, int N, int K)
{
    extern __shared__ char smem[];
    constexpr int TILE_A = 128 * 32 * 2;    // 8 KB
    constexpr int TILE_B = 256 * 32 * 2;    // 16 KB
    constexpr int STAGE  = TILE_A + TILE_B; // 24 KB
    const uint32_t sb = smem_u32(smem);

    const int tid  = threadIdx.x;
    const int wid  = tid >> 5;
    const int lane = tid & 31;
    const int m0 = blockIdx.y * 128;
    const int n0 = blockIdx.x * 256;
    const int wm = (wid >> 2) * 64;      // 0 or 64
    const int wn = (wid & 3) * 64;       // 0..192
    const int nk = K >> 5;

    const int rl = lane & 15;
    const int ch = lane >> 4;

    float acc[4][8][4];
#pragma unroll
    for (int i = 0; i < 4; ++i)
#pragma unroll
        for (int j = 0; j < 8; ++j)
#pragma unroll
            for (int q = 0; q < 4; ++q) acc[i][j][q] = 0.f;

    auto load_stage = [&](int c, int s) {
        const int kb = c * 32;
        const uint32_t st = sb + s * STAGE;
#pragma unroll
        for (int i = 0; i < 2; ++i) {     // A: 128 rows x 64B
            int id = tid + i * 256;
            int r = id >> 2, c8 = id & 3;
            uint32_t off = SWZ_OFF(r, c8);
            cpa16(st + off, A + (size_t)(m0 + r) * K + kb + c8 * 8);
        }
#pragma unroll
        for (int i = 0; i < 4; ++i) {     // B: 256 rows x 64B
            int id = tid + i * 256;
            int r = id >> 2, c8 = id & 3;
            uint32_t off = SWZ_OFF(r, c8);
            cpa16(st + TILE_A + off, B + (size_t)(n0 + r) * K + kb + c8 * 8);
        }
        CP_COMMIT();
    };

    load_stage(0, 0);
    if (nk > 1) load_stage(1, 1);

    for (int c = 0; c < nk; ++c) {
        if (c + 1 < nk) { CP_WAIT1(); } else { CP_WAIT0(); }
        __syncthreads();
        if (c + 2 < nk) load_stage(c + 2, (c + 2) % 3);

        const uint32_t st = sb + (c % 3) * STAGE;
#pragma unroll
        for (int ks = 0; ks < 2; ++ks) {
            uint32_t af[4][4], bf[4][4];
#pragma unroll
            for (int mt = 0; mt < 4; ++mt) {
                int r = wm + mt * 16 + rl;
                int c8 = 2 * ks + ch;
                uint32_t off = SWZ_OFF(r, c8);
                ldsm_x4(af[mt][0], af[mt][1], af[mt][2], af[mt][3], st + off);
            }
#pragma unroll
            for (int np = 0; np < 4; ++np) {
                int r = wn + np * 16 + rl;
                int c8 = 2 * ks + ch;
                uint32_t off = SWZ_OFF(r, c8);
                ldsm_x4(bf[np][0], bf[np][1], bf[np][2], bf[np][3], st + TILE_A + off);
            }
#pragma unroll
            for (int mt = 0; mt < 4; ++mt) {
#pragma unroll
                for (int nt = 0; nt < 8; ++nt) {
                    const int np = nt >> 1, sel = nt & 1;
                    float* d = acc[mt][nt];
                    mma_f16(d[0], d[1], d[2], d[3],
                            af[mt][0], af[mt][1], af[mt][2], af[mt][3],
                            bf[np][sel], bf[np][2 + sel]);
                }
            }
        }
        __syncthreads();
    }

#pragma unroll
    for (int mt = 0; mt < 4; ++mt) {
#pragma unroll
        for (int nt = 0; nt < 8; ++nt) {
            int rg = m0 + wm + mt * 16 + (lane >> 2);
            int cg = n0 + wn + nt * 8 + (lane & 3) * 2;
            float* d = acc[mt][nt];
            *(float2*)(C + (size_t)rg * N + cg)       = make_float2(d[0], d[1]);
            *(float2*)(C + (size_t)(rg + 8) * N + cg) = make_float2(d[2], d[3]);
        }
    }
}

// ---------------- RoPE + pre-scale + fp16 split ----------------
// Q (contiguous [SQ,QDIM]) -> Qh/Ql ; K (strided in g_KV) -> Kh
__global__ __launch_bounds__(256) void rope_split(
    const float* __restrict__ Q, const float* __restrict__ KV,
    const int* __restrict__ pos_ids,
    __half* __restrict__ Qh, __half* __restrict__ Ql, __half* __restrict__ Kh)
{
    const int s = blockIdx.x;
    const float scale = 0.08838834764831845f;  // 1/sqrt(128)
    __shared__ float cs[64], sn[64];
    if (threadIdx.x < 64) {
        double invf = exp(-(double)threadIdx.x * (9.210340371976184 / 64.0));
        float ang = (float)((double)pos_ids[s] * invf);
        float c, si;
        sincosf(ang, &si, &c);
        cs[threadIdx.x] = c;
        sn[threadIdx.x] = si;
    }
    __syncthreads();
#pragma unroll
    for (int it = 0; it < 8; ++it) {
        int pp = threadIdx.x + it * 256;
        int head = pp >> 6, i = pp & 63;
        size_t b = (size_t)s * QDIM + head * HD + i;
        float x0 = Q[b], x1 = Q[b + 64];
        float c = cs[i], si = sn[i];
        float y0 = (x0 * c - x1 * si) * scale;
        float y1 = (x1 * c + x0 * si) * scale;
        __half h, l;
        split2h(y0, h, l); Qh[b] = h;      Ql[b] = l;
        split2h(y1, h, l); Qh[b + 64] = h; Ql[b + 64] = l;
    }
#pragma unroll
    for (int it = 0; it < 2; ++it) {
        int pp = threadIdx.x + it * 256;
        int head = pp >> 6, i = pp & 63;
        size_t bs = (size_t)s * (2 * KVDIM) + head * HD + i;   // K in g_KV
        size_t bd = (size_t)s * KVDIM + head * HD + i;
        float x0 = KV[bs], x1 = KV[bs + 64];
        float c = cs[i], si = sn[i];
        Kh[bd]      = __float2half_rn(x0 * c - x1 * si);
        Kh[bd + 64] = __float2half_rn(x1 * c + x0 * si);
    }
}

// ---------------- HMMA flash attention (causal, Q/P compensated) ----------------
#define ASWZ(row, g) ((row) * 256 + (((g) ^ ((row) & 7)) << 4))

__global__ __launch_bounds__(256) void attn_hmma(
    const __half* __restrict__ Qh, const __half* __restrict__ Ql,
    const __half* __restrict__ Kh, const __half* __restrict__ Vh,
    __half* __restrict__ AOh)
{
    extern __shared__ char sm[];
    const uint32_t sb = smem_u32(sm);
    constexpr int MTILE = 64 * 128 * 2;     // 16 KB per matrix
    constexpr int STAGE = 2 * MTILE;        // K + V = 32 KB

    const int tid = threadIdx.x, wid = tid >> 5, lane = tid & 31;
    const int h  = blockIdx.y, kh = h >> 2;
    const int bq = gridDim.x - 1 - blockIdx.x;
    const int q0 = bq * 128;
    const int wr = wid * 16;
    const int r  = lane >> 2, c2 = (lane & 3) * 2;
    const int rl = lane & 15, chh = lane >> 4;

    uint32_t qfh[8][4], qfl[8][4];
    {
        const int row0 = q0 + wr + r;
#pragma unroll
        for (int ks = 0; ks < 8; ++ks) {
            int k2 = ks * 16 + c2;
            size_t b00 = (size_t)row0 * QDIM + h * HD + k2;
            size_t b10 = b00 + (size_t)8 * QDIM;
            qfh[ks][0] = *(const uint32_t*)(Qh + b00);
            qfh[ks][1] = *(const uint32_t*)(Qh + b10);
            qfh[ks][2] = *(const uint32_t*)(Qh + b00 + 8);
            qfh[ks][3] = *(const uint32_t*)(Qh + b10 + 8);
            qfl[ks][0] = *(const uint32_t*)(Ql + b00);
            qfl[ks][1] = *(const uint32_t*)(Ql + b10);
            qfl[ks][2] = *(const uint32_t*)(Ql + b00 + 8);
            qfl[ks][3] = *(const uint32_t*)(Ql + b10 + 8);
        }
    }

    float o[16][4];
#pragma unroll
    for (int i = 0; i < 16; ++i)
#pragma unroll
        for (int q = 0; q < 4; ++q) o[i][q] = 0.f;
    float m1 = -1e30f, m2 = -1e30f, l1 = 0.f, l2 = 0.f;

    const int ntiles = 2 * bq + 2;

    auto load_kv = [&](int kt, int s) {
        const int k0 = kt * 64;
        const uint32_t st = sb + s * STAGE;
#pragma unroll
        for (int i = 0; i < 4; ++i) {
            int id = tid + i * 256;
            int rw = id >> 4, g = id & 15;
            uint32_t off = ASWZ(rw, g);
            size_t src = (size_t)(k0 + rw) * KVDIM + kh * HD + g * 8;
            cpa16(st + off,         Kh + src);
            cpa16(st + MTILE + off, Vh + src);
        }
        CP_COMMIT();
    };

    load_kv(0, 0);

    for (int kt = 0; kt < ntiles; ++kt) {
        if (kt + 1 < ntiles) { load_kv(kt + 1, (kt + 1) & 1); CP_WAIT1(); }
        else                 { CP_WAIT0(); }
        __syncthreads();

        const uint32_t st = sb + (kt & 1) * STAGE;
        const int k0 = kt * 64;

        float sacc[8][4];
#pragma unroll
        for (int i = 0; i < 8; ++i)
#pragma unroll
            for (int q = 0; q < 4; ++q) sacc[i][q] = 0.f;

#pragma unroll
        for (int ks = 0; ks < 8; ++ks) {
            uint32_t kb[4][4];
#pragma unroll
            for (int np = 0; np < 4; ++np) {
                int row = np * 16 + rl;
                int g = 2 * ks + chh;
                uint32_t off = ASWZ(row, g);
                ldsm_x4(kb[np][0], kb[np][1], kb[np][2], kb[np][3], st + off);
            }
#pragma unroll
            for (int nt = 0; nt < 8; ++nt) {
                const int np = nt >> 1, sel = nt & 1;
                float* d = sacc[nt];
                mma_f16(d[0], d[1], d[2], d[3],
                        qfh[ks][0], qfh[ks][1], qfh[ks][2], qfh[ks][3],
                        kb[np][sel], kb[np][2 + sel]);
                mma_f16(d[0], d[1], d[2], d[3],
                        qfl[ks][0], qfl[ks][1], qfl[ks][2], qfl[ks][3],
                        kb[np][sel], kb[np][2 + sel]);
            }
        }

        if (k0 + 63 > q0 + wr) {
            const int row1 = q0 + wr + r, row2 = row1 + 8;
#pragma unroll
            for (int nt = 0; nt < 8; ++nt) {
                int col = k0 + nt * 8 + c2;
                if (col     > row1) sacc[nt][0] = -1e30f;
                if (col + 1 > row1) sacc[nt][1] = -1e30f;
                if (col     > row2) sacc[nt][2] = -1e30f;
                if (col + 1 > row2) sacc[nt][3] = -1e30f;
            }
        }

        float mx1 = -1e30f, mx2 = -1e30f;
#pragma unroll
        for (int nt = 0; nt < 8; ++nt) {
            mx1 = fmaxf(mx1, fmaxf(sacc[nt][0], sacc[nt][1]));
            mx2 = fmaxf(mx2, fmaxf(sacc[nt][2], sacc[nt][3]));
        }
        mx1 = fmaxf(mx1, __shfl_xor_sync(0xffffffffu, mx1, 1));
        mx1 = fmaxf(mx1, __shfl_xor_sync(0xffffffffu, mx1, 2));
        mx2 = fmaxf(mx2, __shfl_xor_sync(0xffffffffu, mx2, 1));
        mx2 = fmaxf(mx2, __shfl_xor_sync(0xffffffffu, mx2, 2));
        float nm1 = fmaxf(m1, mx1), nm2 = fmaxf(m2, mx2);
        float cf1 = __expf(m1 - nm1), cf2 = __expf(m2 - nm2);
        m1 = nm1; m2 = nm2;

        float ls1 = 0.f, ls2 = 0.f;
#pragma unroll
        for (int nt = 0; nt < 8; ++nt) {
            sacc[nt][0] = __expf(sacc[nt][0] - nm1);
            sacc[nt][1] = __expf(sacc[nt][1] - nm1);
            sacc[nt][2] = __expf(sacc[nt][2] - nm2);
            sacc[nt][3] = __expf(sacc[nt][3] - nm2);
            ls1 += sacc[nt][0] + sacc[nt][1];
            ls2 += sacc[nt][2] + sacc[nt][3];
        }
        ls1 += __shfl_xor_sync(0xffffffffu, ls1, 1);
        ls1 += __shfl_xor_sync(0xffffffffu, ls1, 2);
        ls2 += __shfl_xor_sync(0xffffffffu, ls2, 1);
        ls2 += __shfl_xor_sync(0xffffffffu, ls2, 2);
        l1 = l1 * cf1 + ls1;
        l2 = l2 * cf2 + ls2;
#pragma unroll
        for (int dt = 0; dt < 16; ++dt) {
            o[dt][0] *= cf1; o[dt][1] *= cf1;
            o[dt][2] *= cf2; o[dt][3] *= cf2;
        }

#pragma unroll
        for (int s = 0; s < 4; ++s) {
            uint32_t aph[4], apl[4];
#pragma unroll
            for (int half = 0; half < 2; ++half) {
                const float* sv = sacc[2 * s + half];
                __half2 h01, l01, h23, l23;
                split2h(sv[0], h01.x, l01.x);
                split2h(sv[1], h01.y, l01.y);
                split2h(sv[2], h23.x, l23.x);
                split2h(sv[3], h23.y, l23.y);
                aph[2 * half + 0] = *(uint32_t*)&h01;
                aph[2 * half + 1] = *(uint32_t*)&h23;
                apl[2 * half + 0] = *(uint32_t*)&l01;
                apl[2 * half + 1] = *(uint32_t*)&l23;
            }
            uint32_t a0 = aph[0], a1 = aph[1], a2 = aph[2], a3 = aph[3];
            uint32_t b0 = apl[0], b1 = apl[1], b2 = apl[2], b3 = apl[3];
#pragma unroll
            for (int dg = 0; dg < 8; ++dg) {
                int row = s * 16 + rl;
                int g = 2 * dg + chh;
                uint32_t off = ASWZ(row, g);
                uint32_t v4[4];
                ldsm_x4_t(v4[0], v4[1], v4[2], v4[3], st + MTILE + off);
                float* d0 = o[2 * dg];
                float* d1 = o[2 * dg + 1];
                mma_f16(d0[0], d0[1], d0[2], d0[3], a0, a1, a2, a3, v4[0], v4[1]);
                mma_f16(d0[0], d0[1], d0[2], d0[3], b0, b1, b2, b3, v4[0], v4[1]);
                mma_f16(d1[0], d1[1], d1[2], d1[3], a0, a1, a2, a3, v4[2], v4[3]);
                mma_f16(d1[0], d1[1], d1[2], d1[3], b0, b1, b2, b3, v4[2], v4[3]);
            }
        }
        __syncthreads();
    }

    // ---- epilogue: normalize, convert to fp16, store (single precision stream)
    const float inv1 = 1.f / l1, inv2 = 1.f / l2;
    const int row1 = q0 + wr + r;
#pragma unroll
    for (int dt = 0; dt < 16; ++dt) {
        size_t c0 = (size_t)row1 * QDIM + h * HD + dt * 8 + c2;
        size_t c1 = c0 + (size_t)8 * QDIM;
        __half2 h01;
        h01.x = __float2half_rn(o[dt][0] * inv1);
        h01.y = __float2half_rn(o[dt][1] * inv1);
        *(__half2*)(AOh + c0) = h01;
        h01.x = __float2half_rn(o[dt][2] * inv2);
        h01.y = __float2half_rn(o[dt][3] * inv2);
        *(__half2*)(AOh + c1) = h01;
    }
}

// ---------------- launch ----------------
extern "C" void kernel_launch(void* const* d_in, const int* in_sizes, int n_in,
                              void* d_out, int out_size)
{
    const float* hs   = (const float*)d_in[0];
    const int*   pos  = (const int*)d_in[2];
    const float* Wq   = (const float*)d_in[3];
    const float* Wk   = (const float*)d_in[4];
    const float* Wv   = (const float*)d_in[5];
    const float* Wo   = (const float*)d_in[6];
    float* out = (float*)d_out;

    float *qp, *kvp;
    __half *ah, *aoh, *qhp, *qlp, *khp, *vhp;
    __half *wqt, *wkvt, *wot;
    cudaGetSymbolAddress((void**)&qp,   g_Q);
    cudaGetSymbolAddress((void**)&kvp,  g_KV);
    cudaGetSymbolAddress((void**)&ah,   g_Ah);
    cudaGetSymbolAddress((void**)&aoh,  g_AOh);
    cudaGetSymbolAddress((void**)&qhp,  g_Qh);
    cudaGetSymbolAddress((void**)&qlp,  g_Ql);
    cudaGetSymbolAddress((void**)&khp,  g_Kh);
    cudaGetSymbolAddress((void**)&vhp,  g_Vh);
    cudaGetSymbolAddress((void**)&wqt,  g_WqT);
    cudaGetSymbolAddress((void**)&wkvt, g_WkvT);
    cudaGetSymbolAddress((void**)&wot,  g_WoT);

    const int gemm_smem = 3 * (128 * 32 * 2 + 256 * 32 * 2);  // 73728
    cudaFuncSetAttribute(gemm_hmma_h1, cudaFuncAttributeMaxDynamicSharedMemorySize, gemm_smem);
    const int attn_smem = 2 * 2 * 64 * 128 * 2;   // 65536
    cudaFuncSetAttribute(attn_hmma, cudaFuncAttributeMaxDynamicSharedMemorySize, attn_smem);

    // converts / transposes
    conv_plain<<<(SQ * HID / 4 + 255) / 256, 256>>>(hs, ah, SQ * HID / 4);
    transpose_h<<<dim3(QDIM / 32,  HID / 32), 256>>>(Wq, wqt, HID, QDIM);
    transpose_h<<<dim3(KVDIM / 32, HID / 32), 256>>>(Wk, wkvt, HID, KVDIM);
    transpose_h<<<dim3(KVDIM / 32, HID / 32), 256>>>(Wv, wkvt + (size_t)KVDIM * HID, HID, KVDIM);
    transpose_h<<<dim3(HID / 32,  QDIM / 32), 256>>>(Wo, wot, QDIM, HID);

    // projections: Q (N=4096), fused KV (N=2048) — plain fp16
    gemm_hmma_h1<<<dim3(QDIM / 256,    SQ / 128), 256, gemm_smem>>>(ah, wqt,  qp,  SQ, QDIM,    HID);
    gemm_hmma_h1<<<dim3(2*KVDIM / 256, SQ / 128), 256, gemm_smem>>>(ah, wkvt, kvp, SQ, 2*KVDIM, HID);

    // RoPE + split Q (hi/lo), K (fp16); convert V (fp16)
    rope_split<<<SQ, 256>>>(qp, kvp, pos, qhp, qlp, khp);
    conv_v<<<SQ, 256>>>(kvp, vhp);

    // attention (Q and P compensated; output single fp16)
    attn_hmma<<<dim3(SQ / 128, NH), 256, attn_smem>>>(qhp, qlp, khp, vhp, aoh);

    // output projection — plain fp16
    gemm_hmma_h1<<<dim3(HID / 256, SQ / 128), 256, gemm_smem>>>(aoh, wot, out, SQ, HID, QDIM);
}

// round 8
// speedup vs baseline: 7.2681x; 1.0942x over previous
#include <cuda_runtime.h>
#include <cuda_fp16.h>
#include <math.h>
#include <cstdint>

#define SQ    2048
#define HID   4096
#define NH    32
#define NKV   8
#define HD    128
#define QDIM  (NH*HD)    // 4096
#define KVDIM (NKV*HD)   // 1024
#define QKVD  (QDIM + 2*KVDIM)   // 6144

// ---------------- scratch (static device allocations) ----------------
__device__ float g_QKV[SQ * QKVD];     // cols 0-4095 Q, 4096-5119 K, 5120-6143 V

__device__ __half g_Ah [SQ * HID];
__device__ __half g_AOh[SQ * QDIM];

__device__ __half g_Qh[SQ * QDIM];
__device__ __half g_Ql[SQ * QDIM];
__device__ __half g_Kh[SQ * KVDIM];
__device__ __half g_Vh[SQ * KVDIM];

__device__ __half g_WqkvT[QKVD * HID];  // rows 0-4095 WqT, 4096-5119 WkT, 5120-6143 WvT
__device__ __half g_WoT  [HID * QDIM];

// ---------------- PTX helpers (sm_80-era instructions only) ----------------
__device__ __forceinline__ uint32_t smem_u32(const void* p) {
    uint32_t a;
    asm("{ .reg .u64 t; cvta.to.shared.u64 t, %1; cvt.u32.u64 %0, t; }" : "=r"(a) : "l"(p));
    return a;
}

__device__ __forceinline__ void cpa16(uint32_t dst, const void* src) {
    asm volatile("cp.async.cg.shared.global [%0], [%1], 16;" :: "r"(dst), "l"(src) : "memory");
}
#define CP_COMMIT() asm volatile("cp.async.commit_group;" ::: "memory")
#define CP_WAIT1()  asm volatile("cp.async.wait_group 1;" ::: "memory")
#define CP_WAIT0()  asm volatile("cp.async.wait_group 0;" ::: "memory")

__device__ __forceinline__ void ldsm_x4(uint32_t& r0, uint32_t& r1, uint32_t& r2, uint32_t& r3,
                                        uint32_t addr) {
    asm volatile("ldmatrix.sync.aligned.m8n8.x4.shared.b16 {%0,%1,%2,%3}, [%4];"
                 : "=r"(r0), "=r"(r1), "=r"(r2), "=r"(r3) : "r"(addr));
}
__device__ __forceinline__ void ldsm_x4_t(uint32_t& r0, uint32_t& r1, uint32_t& r2, uint32_t& r3,
                                          uint32_t addr) {
    asm volatile("ldmatrix.sync.aligned.m8n8.x4.trans.shared.b16 {%0,%1,%2,%3}, [%4];"
                 : "=r"(r0), "=r"(r1), "=r"(r2), "=r"(r3) : "r"(addr));
}

__device__ __forceinline__ void mma_f16(float& d0, float& d1, float& d2, float& d3,
                                        uint32_t a0, uint32_t a1, uint32_t a2, uint32_t a3,
                                        uint32_t b0, uint32_t b1) {
    asm volatile("mma.sync.aligned.m16n8k16.row.col.f32.f16.f16.f32 "
                 "{%0,%1,%2,%3}, {%4,%5,%6,%7}, {%8,%9}, {%0,%1,%2,%3};"
                 : "+f"(d0), "+f"(d1), "+f"(d2), "+f"(d3)
                 : "r"(a0), "r"(a1), "r"(a2), "r"(a3), "r"(b0), "r"(b1));
}

__device__ __forceinline__ void split2h(float v, __half& h, __half& l) {
    h = __float2half_rn(v);
    l = __float2half_rn(v - __half2float(h));
}

// ---------------- fp32 -> fp16 convert (elementwise, float4) ----------------
__global__ __launch_bounds__(256) void conv_plain(
    const float* __restrict__ X, __half* __restrict__ H, int n4)
{
    int i = blockIdx.x * 256 + threadIdx.x;
    if (i >= n4) return;
    float4 a = ((const float4*)X)[i];
    __half2 h0, h1;
    h0.x = __float2half_rn(a.x); h0.y = __float2half_rn(a.y);
    h1.x = __float2half_rn(a.z); h1.y = __float2half_rn(a.w);
    ((__half2*)H)[2 * i]     = h0;
    ((__half2*)H)[2 * i + 1] = h1;
}

// ---------------- strided V fp32 -> fp16 convert ----------------
__global__ __launch_bounds__(256) void conv_v(
    const float* __restrict__ QKV, __half* __restrict__ Vh)
{
    int s = blockIdx.x;
    const float* src = QKV + (size_t)s * QKVD + QDIM + KVDIM;
    __half* dst = Vh + (size_t)s * KVDIM;
    int j = threadIdx.x * 4;
    float4 a = *(const float4*)(src + j);
    __half2 h0, h1;
    h0.x = __float2half_rn(a.x); h0.y = __float2half_rn(a.y);
    h1.x = __float2half_rn(a.z); h1.y = __float2half_rn(a.w);
    *(__half2*)(dst + j)     = h0;
    *(__half2*)(dst + j + 2) = h1;
}

// ---------------- fused weight transposes (all 4 weights, 1 launch) ----------------
// Wq[4096,4096]->wqkv rows 0-4095; Wk[4096,1024]->rows 4096-5119;
// Wv[4096,1024]->rows 5120-6143; Wo[4096,4096]->wot.
__global__ __launch_bounds__(256) void transpose_all(
    const float* __restrict__ Wq, const float* __restrict__ Wk,
    const float* __restrict__ Wv, const float* __restrict__ Wo,
    __half* __restrict__ wqkv, __half* __restrict__ wot)
{
    int b = blockIdx.x;
    const float* W; __half* HT; int N;
    if (b < 16384)       { W = Wq; HT = wqkv;                          N = 4096; }
    else if (b < 20480)  { b -= 16384; W = Wk; HT = wqkv + (size_t)4096 * HID; N = 1024; }
    else if (b < 24576)  { b -= 20480; W = Wv; HT = wqkv + (size_t)5120 * HID; N = 1024; }
    else                 { b -= 24576; W = Wo; HT = wot;               N = 4096; }
    const int K = 4096;
    int nb = N / 32;
    int n0 = (b % nb) * 32, k0 = (b / nb) * 32;

    __shared__ float t[32][33];
    int tx = threadIdx.x & 31, ty = threadIdx.x >> 5;
#pragma unroll
    for (int i = 0; i < 4; ++i) {
        int ky = ty + i * 8;
        t[ky][tx] = W[(size_t)(k0 + ky) * N + n0 + tx];
    }
    __syncthreads();
#pragma unroll
    for (int i = 0; i < 4; ++i) {
        int ny = ty + i * 8;
        HT[(size_t)(n0 + ny) * K + k0 + tx] = __float2half_rn(t[tx][ny]);
    }
}

// ---------------- HMMA fp16 GEMM, CTA 128x256, warp 64x64, k-chunk 64 ----------------
// C[M,N] fp32 = A[M,K] @ B[N,K]^T  (plain fp16, fp32 accum). 3-stage cp.async.
// Smem rows are 128 B (64 fp16); 16B-group swizzle: g' = g ^ (row & 7).
#define SWZ64(r, c8) ((r) * 128 + (((c8) ^ ((r) & 7)) << 4))

__global__ __launch_bounds__(256, 1) void gemm_hmma_h1(
    const __half* __restrict__ A, const __half* __restrict__ B,
    float* __restrict__ C, int M, int N, int K)
{
    extern __shared__ char smem[];
    constexpr int TILE_A = 128 * 64 * 2;    // 16 KB
    constexpr int TILE_B = 256 * 64 * 2;    // 32 KB
    constexpr int STAGE  = TILE_A + TILE_B; // 48 KB
    const uint32_t sb = smem_u32(smem);

    const int tid  = threadIdx.x;
    const int wid  = tid >> 5;
    const int lane = tid & 31;
    const int m0 = blockIdx.y * 128;
    const int n0 = blockIdx.x * 256;
    const int wm = (wid >> 2) * 64;      // 0 or 64
    const int wn = (wid & 3) * 64;       // 0..192
    const int nk = K >> 6;               // K / 64

    const int rl = lane & 15;
    const int ch = lane >> 4;

    float acc[4][8][4];
#pragma unroll
    for (int i = 0; i < 4; ++i)
#pragma unroll
        for (int j = 0; j < 8; ++j)
#pragma unroll
            for (int q = 0; q < 4; ++q) acc[i][j][q] = 0.f;

    auto load_stage = [&](int c, int s) {
        const int kb = c * 64;
        const uint32_t st = sb + s * STAGE;
#pragma unroll
        for (int i = 0; i < 4; ++i) {     // A: 128 rows x 128B
            int id = tid + i * 256;
            int r = id >> 3, c8 = id & 7;
            uint32_t off = SWZ64(r, c8);
            cpa16(st + off, A + (size_t)(m0 + r) * K + kb + c8 * 8);
        }
#pragma unroll
        for (int i = 0; i < 8; ++i) {     // B: 256 rows x 128B
            int id = tid + i * 256;
            int r = id >> 3, c8 = id & 7;
            uint32_t off = SWZ64(r, c8);
            cpa16(st + TILE_A + off, B + (size_t)(n0 + r) * K + kb + c8 * 8);
        }
        CP_COMMIT();
    };

    load_stage(0, 0);
    if (nk > 1) load_stage(1, 1);

    for (int c = 0; c < nk; ++c) {
        if (c + 1 < nk) { CP_WAIT1(); } else { CP_WAIT0(); }
        __syncthreads();
        if (c + 2 < nk) load_stage(c + 2, (c + 2) % 3);

        const uint32_t st = sb + (c % 3) * STAGE;
#pragma unroll
        for (int ks = 0; ks < 4; ++ks) {
            uint32_t af[4][4], bf[4][4];
#pragma unroll
            for (int mt = 0; mt < 4; ++mt) {
                int r = wm + mt * 16 + rl;
                int c8 = 2 * ks + ch;
                uint32_t off = SWZ64(r, c8);
                ldsm_x4(af[mt][0], af[mt][1], af[mt][2], af[mt][3], st + off);
            }
#pragma unroll
            for (int np = 0; np < 4; ++np) {
                int r = wn + np * 16 + rl;
                int c8 = 2 * ks + ch;
                uint32_t off = SWZ64(r, c8);
                ldsm_x4(bf[np][0], bf[np][1], bf[np][2], bf[np][3], st + TILE_A + off);
            }
#pragma unroll
            for (int mt = 0; mt < 4; ++mt) {
#pragma unroll
                for (int nt = 0; nt < 8; ++nt) {
                    const int np = nt >> 1, sel = nt & 1;
                    float* d = acc[mt][nt];
                    mma_f16(d[0], d[1], d[2], d[3],
                            af[mt][0], af[mt][1], af[mt][2], af[mt][3],
                            bf[np][sel], bf[np][2 + sel]);
                }
            }
        }
        __syncthreads();
    }

#pragma unroll
    for (int mt = 0; mt < 4; ++mt) {
#pragma unroll
        for (int nt = 0; nt < 8; ++nt) {
            int rg = m0 + wm + mt * 16 + (lane >> 2);
            int cg = n0 + wn + nt * 8 + (lane & 3) * 2;
            float* d = acc[mt][nt];
            *(float2*)(C + (size_t)rg * N + cg)       = make_float2(d[0], d[1]);
            *(float2*)(C + (size_t)(rg + 8) * N + cg) = make_float2(d[2], d[3]);
        }
    }
}

// ---------------- RoPE + pre-scale + fp16 split ----------------
// Q (strided in g_QKV) -> Qh/Ql ; K (strided in g_QKV, col offset 4096) -> Kh
__global__ __launch_bounds__(256) void rope_split(
    const float* __restrict__ QKV, const int* __restrict__ pos_ids,
    __half* __restrict__ Qh, __half* __restrict__ Ql, __half* __restrict__ Kh)
{
    const int s = blockIdx.x;
    const float scale = 0.08838834764831845f;  // 1/sqrt(128)
    __shared__ float cs[64], sn[64];
    if (threadIdx.x < 64) {
        double invf = exp(-(double)threadIdx.x * (9.210340371976184 / 64.0));
        float ang = (float)((double)pos_ids[s] * invf);
        float c, si;
        sincosf(ang, &si, &c);
        cs[threadIdx.x] = c;
        sn[threadIdx.x] = si;
    }
    __syncthreads();
#pragma unroll
    for (int it = 0; it < 8; ++it) {
        int pp = threadIdx.x + it * 256;
        int head = pp >> 6, i = pp & 63;
        size_t bs = (size_t)s * QKVD + head * HD + i;       // Q at col 0
        size_t bd = (size_t)s * QDIM + head * HD + i;
        float x0 = QKV[bs], x1 = QKV[bs + 64];
        float c = cs[i], si = sn[i];
        float y0 = (x0 * c - x1 * si) * scale;
        float y1 = (x1 * c + x0 * si) * scale;
        __half h, l;
        split2h(y0, h, l); Qh[bd] = h;      Ql[bd] = l;
        split2h(y1, h, l); Qh[bd + 64] = h; Ql[bd + 64] = l;
    }
#pragma unroll
    for (int it = 0; it < 2; ++it) {
        int pp = threadIdx.x + it * 256;
        int head = pp >> 6, i = pp & 63;
        size_t bs = (size_t)s * QKVD + QDIM + head * HD + i;  // K at col 4096
        size_t bd = (size_t)s * KVDIM + head * HD + i;
        float x0 = QKV[bs], x1 = QKV[bs + 64];
        float c = cs[i], si = sn[i];
        Kh[bd]      = __float2half_rn(x0 * c - x1 * si);
        Kh[bd + 64] = __float2half_rn(x1 * c + x0 * si);
    }
}

// ---------------- HMMA flash attention (causal, Q/P compensated) ----------------
#define ASWZ(row, g) ((row) * 256 + (((g) ^ ((row) & 7)) << 4))

__global__ __launch_bounds__(256) void attn_hmma(
    const __half* __restrict__ Qh, const __half* __restrict__ Ql,
    const __half* __restrict__ Kh, const __half* __restrict__ Vh,
    __half* __restrict__ AOh)
{
    extern __shared__ char sm[];
    const uint32_t sb = smem_u32(sm);
    constexpr int MTILE = 64 * 128 * 2;     // 16 KB per matrix
    constexpr int STAGE = 2 * MTILE;        // K + V = 32 KB

    const int tid = threadIdx.x, wid = tid >> 5, lane = tid & 31;
    const int h  = blockIdx.y, kh = h >> 2;
    const int bq = gridDim.x - 1 - blockIdx.x;
    const int q0 = bq * 128;
    const int wr = wid * 16;
    const int r  = lane >> 2, c2 = (lane & 3) * 2;
    const int rl = lane & 15, chh = lane >> 4;

    uint32_t qfh[8][4], qfl[8][4];
    {
        const int row0 = q0 + wr + r;
#pragma unroll
        for (int ks = 0; ks < 8; ++ks) {
            int k2 = ks * 16 + c2;
            size_t b00 = (size_t)row0 * QDIM + h * HD + k2;
            size_t b10 = b00 + (size_t)8 * QDIM;
            qfh[ks][0] = *(const uint32_t*)(Qh + b00);
            qfh[ks][1] = *(const uint32_t*)(Qh + b10);
            qfh[ks][2] = *(const uint32_t*)(Qh + b00 + 8);
            qfh[ks][3] = *(const uint32_t*)(Qh + b10 + 8);
            qfl[ks][0] = *(const uint32_t*)(Ql + b00);
            qfl[ks][1] = *(const uint32_t*)(Ql + b10);
            qfl[ks][2] = *(const uint32_t*)(Ql + b00 + 8);
            qfl[ks][3] = *(const uint32_t*)(Ql + b10 + 8);
        }
    }

    float o[16][4];
#pragma unroll
    for (int i = 0; i < 16; ++i)
#pragma unroll
        for (int q = 0; q < 4; ++q) o[i][q] = 0.f;
    float m1 = -1e30f, m2 = -1e30f, l1 = 0.f, l2 = 0.f;

    const int ntiles = 2 * bq + 2;

    auto load_kv = [&](int kt, int s) {
        const int k0 = kt * 64;
        const uint32_t st = sb + s * STAGE;
#pragma unroll
        for (int i = 0; i < 4; ++i) {
            int id = tid + i * 256;
            int rw = id >> 4, g = id & 15;
            uint32_t off = ASWZ(rw, g);
            size_t src = (size_t)(k0 + rw) * KVDIM + kh * HD + g * 8;
            cpa16(st + off,         Kh + src);
            cpa16(st + MTILE + off, Vh + src);
        }
        CP_COMMIT();
    };

    load_kv(0, 0);

    for (int kt = 0; kt < ntiles; ++kt) {
        if (kt + 1 < ntiles) { load_kv(kt + 1, (kt + 1) & 1); CP_WAIT1(); }
        else                 { CP_WAIT0(); }
        __syncthreads();

        const uint32_t st = sb + (kt & 1) * STAGE;
        const int k0 = kt * 64;

        float sacc[8][4];
#pragma unroll
        for (int i = 0; i < 8; ++i)
#pragma unroll
            for (int q = 0; q < 4; ++q) sacc[i][q] = 0.f;

#pragma unroll
        for (int ks = 0; ks < 8; ++ks) {
            uint32_t kb[4][4];
#pragma unroll
            for (int np = 0; np < 4; ++np) {
                int row = np * 16 + rl;
                int g = 2 * ks + chh;
                uint32_t off = ASWZ(row, g);
                ldsm_x4(kb[np][0], kb[np][1], kb[np][2], kb[np][3], st + off);
            }
#pragma unroll
            for (int nt = 0; nt < 8; ++nt) {
                const int np = nt >> 1, sel = nt & 1;
                float* d = sacc[nt];
                mma_f16(d[0], d[1], d[2], d[3],
                        qfh[ks][0], qfh[ks][1], qfh[ks][2], qfh[ks][3],
                        kb[np][sel], kb[np][2 + sel]);
                mma_f16(d[0], d[1], d[2], d[3],
                        qfl[ks][0], qfl[ks][1], qfl[ks][2], qfl[ks][3],
                        kb[np][sel], kb[np][2 + sel]);
            }
        }

        if (k0 + 63 > q0 + wr) {
            const int row1 = q0 + wr + r, row2 = row1 + 8;
#pragma unroll
            for (int nt = 0; nt < 8; ++nt) {
                int col = k0 + nt * 8 + c2;
                if (col     > row1) sacc[nt][0] = -1e30f;
                if (col + 1 > row1) sacc[nt][1] = -1e30f;
                if (col     > row2) sacc[nt][2] = -1e30f;
                if (col + 1 > row2) sacc[nt][3] = -1e30f;
            }
        }

        float mx1 = -1e30f, mx2 = -1e30f;
#pragma unroll
        for (int nt = 0; nt < 8; ++nt) {
            mx1 = fmaxf(mx1, fmaxf(sacc[nt][0], sacc[nt][1]));
            mx2 = fmaxf(mx2, fmaxf(sacc[nt][2], sacc[nt][3]));
        }
        mx1 = fmaxf(mx1, __shfl_xor_sync(0xffffffffu, mx1, 1));
        mx1 = fmaxf(mx1, __shfl_xor_sync(0xffffffffu, mx1, 2));
        mx2 = fmaxf(mx2, __shfl_xor_sync(0xffffffffu, mx2, 1));
        mx2 = fmaxf(mx2, __shfl_xor_sync(0xffffffffu, mx2, 2));
        float nm1 = fmaxf(m1, mx1), nm2 = fmaxf(m2, mx2);
        float cf1 = __expf(m1 - nm1), cf2 = __expf(m2 - nm2);
        m1 = nm1; m2 = nm2;

        float ls1 = 0.f, ls2 = 0.f;
#pragma unroll
        for (int nt = 0; nt < 8; ++nt) {
            sacc[nt][0] = __expf(sacc[nt][0] - nm1);
            sacc[nt][1] = __expf(sacc[nt][1] - nm1);
            sacc[nt][2] = __expf(sacc[nt][2] - nm2);
            sacc[nt][3] = __expf(sacc[nt][3] - nm2);
            ls1 += sacc[nt][0] + sacc[nt][1];
            ls2 += sacc[nt][2] + sacc[nt][3];
        }
        ls1 += __shfl_xor_sync(0xffffffffu, ls1, 1);
        ls1 += __shfl_xor_sync(0xffffffffu, ls1, 2);
        ls2 += __shfl_xor_sync(0xffffffffu, ls2, 1);
        ls2 += __shfl_xor_sync(0xffffffffu, ls2, 2);
        l1 = l1 * cf1 + ls1;
        l2 = l2 * cf2 + ls2;
#pragma unroll
        for (int dt = 0; dt < 16; ++dt) {
            o[dt][0] *= cf1; o[dt][1] *= cf1;
            o[dt][2] *= cf2; o[dt][3] *= cf2;
        }

#pragma unroll
        for (int s = 0; s < 4; ++s) {
            uint32_t aph[4], apl[4];
#pragma unroll
            for (int half = 0; half < 2; ++half) {
                const float* sv = sacc[2 * s + half];
                __half2 h01, l01, h23, l23;
                split2h(sv[0], h01.x, l01.x);
                split2h(sv[1], h01.y, l01.y);
                split2h(sv[2], h23.x, l23.x);
                split2h(sv[3], h23.y, l23.y);
                aph[2 * half + 0] = *(uint32_t*)&h01;
                aph[2 * half + 1] = *(uint32_t*)&h23;
                apl[2 * half + 0] = *(uint32_t*)&l01;
                apl[2 * half + 1] = *(uint32_t*)&l23;
            }
            uint32_t a0 = aph[0], a1 = aph[1], a2 = aph[2], a3 = aph[3];
            uint32_t b0 = apl[0], b1 = apl[1], b2 = apl[2], b3 = apl[3];
#pragma unroll
            for (int dg = 0; dg < 8; ++dg) {
                int row = s * 16 + rl;
                int g = 2 * dg + chh;
                uint32_t off = ASWZ(row, g);
                uint32_t v4[4];
                ldsm_x4_t(v4[0], v4[1], v4[2], v4[3], st + MTILE + off);
                float* d0 = o[2 * dg];
                float* d1 = o[2 * dg + 1];
                mma_f16(d0[0], d0[1], d0[2], d0[3], a0, a1, a2, a3, v4[0], v4[1]);
                mma_f16(d0[0], d0[1], d0[2], d0[3], b0, b1, b2, b3, v4[0], v4[1]);
                mma_f16(d1[0], d1[1], d1[2], d1[3], a0, a1, a2, a3, v4[2], v4[3]);
                mma_f16(d1[0], d1[1], d1[2], d1[3], b0, b1, b2, b3, v4[2], v4[3]);
            }
        }
        __syncthreads();
    }

    const float inv1 = 1.f / l1, inv2 = 1.f / l2;
    const int row1 = q0 + wr + r;
#pragma unroll
    for (int dt = 0; dt < 16; ++dt) {
        size_t c0 = (size_t)row1 * QDIM + h * HD + dt * 8 + c2;
        size_t c1 = c0 + (size_t)8 * QDIM;
        __half2 h01;
        h01.x = __float2half_rn(o[dt][0] * inv1);
        h01.y = __float2half_rn(o[dt][1] * inv1);
        *(__half2*)(AOh + c0) = h01;
        h01.x = __float2half_rn(o[dt][2] * inv2);
        h01.y = __float2half_rn(o[dt][3] * inv2);
        *(__half2*)(AOh + c1) = h01;
    }
}

// ---------------- launch ----------------
extern "C" void kernel_launch(void* const* d_in, const int* in_sizes, int n_in,
                              void* d_out, int out_size)
{
    const float* hs   = (const float*)d_in[0];
    const int*   pos  = (const int*)d_in[2];
    const float* Wq   = (const float*)d_in[3];
    const float* Wk   = (const float*)d_in[4];
    const float* Wv   = (const float*)d_in[5];
    const float* Wo   = (const float*)d_in[6];
    float* out = (float*)d_out;

    float* qkvp;
    __half *ah, *aoh, *qhp, *qlp, *khp, *vhp, *wqkvt, *wot;
    cudaGetSymbolAddress((void**)&qkvp,  g_QKV);
    cudaGetSymbolAddress((void**)&ah,    g_Ah);
    cudaGetSymbolAddress((void**)&aoh,   g_AOh);
    cudaGetSymbolAddress((void**)&qhp,   g_Qh);
    cudaGetSymbolAddress((void**)&qlp,   g_Ql);
    cudaGetSymbolAddress((void**)&khp,   g_Kh);
    cudaGetSymbolAddress((void**)&vhp,   g_Vh);
    cudaGetSymbolAddress((void**)&wqkvt, g_WqkvT);
    cudaGetSymbolAddress((void**)&wot,   g_WoT);

    const int gemm_smem = 3 * (128 * 64 * 2 + 256 * 64 * 2);  // 147456
    cudaFuncSetAttribute(gemm_hmma_h1, cudaFuncAttributeMaxDynamicSharedMemorySize, gemm_smem);
    const int attn_smem = 2 * 2 * 64 * 128 * 2;   // 65536
    cudaFuncSetAttribute(attn_hmma, cudaFuncAttributeMaxDynamicSharedMemorySize, attn_smem);

    // converts / transposes
    conv_plain<<<(SQ * HID / 4 + 255) / 256, 256>>>(hs, ah, SQ * HID / 4);
    transpose_all<<<40960, 256>>>(Wq, Wk, Wv, Wo, wqkvt, wot);

    // fused QKV projection (N=6144)
    gemm_hmma_h1<<<dim3(QKVD / 256, SQ / 128), 256, gemm_smem>>>(ah, wqkvt, qkvp, SQ, QKVD, HID);

    // RoPE + split Q (hi/lo), K (fp16); convert V (fp16)
    rope_split<<<SQ, 256>>>(qkvp, pos, qhp, qlp, khp);
    conv_v<<<SQ, 256>>>(qkvp, vhp);

    // attention (Q and P compensated; output single fp16)
    attn_hmma<<<dim3(SQ / 128, NH), 256, attn_smem>>>(qhp, qlp, khp, vhp, aoh);

    // output projection
    gemm_hmma_h1<<<dim3(HID / 256, SQ / 128), 256, gemm_smem>>>(aoh, wot, out, SQ, HID, QDIM);
}

// round 9
// speedup vs baseline: 8.0919x; 1.1133x over previous
#include <cuda_runtime.h>
#include <cuda_fp16.h>
#include <math.h>
#include <cstdint>

#define SQ    2048
#define HID   4096
#define NH    32
#define NKV   8
#define HD    128
#define QDIM  (NH*HD)    // 4096
#define KVDIM (NKV*HD)   // 1024
#define QKVD  (QDIM + 2*KVDIM)   // 6144

// ---------------- scratch (static device allocations) ----------------
__device__ float g_QKV[SQ * QKVD];     // cols 0-4095 Q, 4096-5119 K, 5120-6143 V

__device__ __half g_Ah [SQ * HID];
__device__ __half g_AOh[SQ * QDIM];

__device__ __half g_Qh[SQ * QDIM];
__device__ __half g_Kh[SQ * KVDIM];
__device__ __half g_Vh[SQ * KVDIM];

__device__ __half g_WqkvT[QKVD * HID];
__device__ __half g_WoT  [HID * QDIM];

// ---------------- PTX helpers (sm_80-era instructions only) ----------------
__device__ __forceinline__ uint32_t smem_u32(const void* p) {
    uint32_t a;
    asm("{ .reg .u64 t; cvta.to.shared.u64 t, %1; cvt.u32.u64 %0, t; }" : "=r"(a) : "l"(p));
    return a;
}

__device__ __forceinline__ void cpa16(uint32_t dst, const void* src) {
    asm volatile("cp.async.cg.shared.global [%0], [%1], 16;" :: "r"(dst), "l"(src) : "memory");
}
#define CP_COMMIT() asm volatile("cp.async.commit_group;" ::: "memory")
#define CP_WAIT1()  asm volatile("cp.async.wait_group 1;" ::: "memory")
#define CP_WAIT0()  asm volatile("cp.async.wait_group 0;" ::: "memory")

__device__ __forceinline__ void ldsm_x4(uint32_t& r0, uint32_t& r1, uint32_t& r2, uint32_t& r3,
                                        uint32_t addr) {
    asm volatile("ldmatrix.sync.aligned.m8n8.x4.shared.b16 {%0,%1,%2,%3}, [%4];"
                 : "=r"(r0), "=r"(r1), "=r"(r2), "=r"(r3) : "r"(addr));
}
__device__ __forceinline__ void ldsm_x4_t(uint32_t& r0, uint32_t& r1, uint32_t& r2, uint32_t& r3,
                                          uint32_t addr) {
    asm volatile("ldmatrix.sync.aligned.m8n8.x4.trans.shared.b16 {%0,%1,%2,%3}, [%4];"
                 : "=r"(r0), "=r"(r1), "=r"(r2), "=r"(r3) : "r"(addr));
}

__device__ __forceinline__ void mma_f16(float& d0, float& d1, float& d2, float& d3,
                                        uint32_t a0, uint32_t a1, uint32_t a2, uint32_t a3,
                                        uint32_t b0, uint32_t b1) {
    asm volatile("mma.sync.aligned.m16n8k16.row.col.f32.f16.f16.f32 "
                 "{%0,%1,%2,%3}, {%4,%5,%6,%7}, {%8,%9}, {%0,%1,%2,%3};"
                 : "+f"(d0), "+f"(d1), "+f"(d2), "+f"(d3)
                 : "r"(a0), "r"(a1), "r"(a2), "r"(a3), "r"(b0), "r"(b1));
}

// ---------------- fp32 -> fp16 convert (elementwise, float4) ----------------
__global__ __launch_bounds__(256) void conv_plain(
    const float* __restrict__ X, __half* __restrict__ H, int n4)
{
    int i = blockIdx.x * 256 + threadIdx.x;
    if (i >= n4) return;
    float4 a = ((const float4*)X)[i];
    __half2 h0, h1;
    h0.x = __float2half_rn(a.x); h0.y = __float2half_rn(a.y);
    h1.x = __float2half_rn(a.z); h1.y = __float2half_rn(a.w);
    ((__half2*)H)[2 * i]     = h0;
    ((__half2*)H)[2 * i + 1] = h1;
}

// ---------------- fused weight transposes (all 4 weights, 1 launch) ----------------
__global__ __launch_bounds__(256) void transpose_all(
    const float* __restrict__ Wq, const float* __restrict__ Wk,
    const float* __restrict__ Wv, const float* __restrict__ Wo,
    __half* __restrict__ wqkv, __half* __restrict__ wot)
{
    int b = blockIdx.x;
    const float* W; __half* HT; int N;
    if (b < 16384)       { W = Wq; HT = wqkv;                          N = 4096; }
    else if (b < 20480)  { b -= 16384; W = Wk; HT = wqkv + (size_t)4096 * HID; N = 1024; }
    else if (b < 24576)  { b -= 20480; W = Wv; HT = wqkv + (size_t)5120 * HID; N = 1024; }
    else                 { b -= 24576; W = Wo; HT = wot;               N = 4096; }
    const int K = 4096;
    int nb = N / 32;
    int n0 = (b % nb) * 32, k0 = (b / nb) * 32;

    __shared__ float t[32][33];
    int tx = threadIdx.x & 31, ty = threadIdx.x >> 5;
#pragma unroll
    for (int i = 0; i < 4; ++i) {
        int ky = ty + i * 8;
        t[ky][tx] = W[(size_t)(k0 + ky) * N + n0 + tx];
    }
    __syncthreads();
#pragma unroll
    for (int i = 0; i < 4; ++i) {
        int ny = ty + i * 8;
        HT[(size_t)(n0 + ny) * K + k0 + tx] = __float2half_rn(t[tx][ny]);
    }
}

// ---------------- HMMA fp16 GEMM, CTA 128x256, warp 64x64, k-chunk 64 ----------------
#define SWZ64(r, c8) ((r) * 128 + (((c8) ^ ((r) & 7)) << 4))

__global__ __launch_bounds__(256, 1) void gemm_hmma_h1(
    const __half* __restrict__ A, const __half* __restrict__ B,
    float* __restrict__ C, int M, int N, int K)
{
    extern __shared__ char smem[];
    constexpr int TILE_A = 128 * 64 * 2;    // 16 KB
    constexpr int TILE_B = 256 * 64 * 2;    // 32 KB
    constexpr int STAGE  = TILE_A + TILE_B; // 48 KB
    const uint32_t sb = smem_u32(smem);

    const int tid  = threadIdx.x;
    const int wid  = tid >> 5;
    const int lane = tid & 31;
    const int m0 = blockIdx.y * 128;
    const int n0 = blockIdx.x * 256;
    const int wm = (wid >> 2) * 64;
    const int wn = (wid & 3) * 64;
    const int nk = K >> 6;

    const int rl = lane & 15;
    const int ch = lane >> 4;

    float acc[4][8][4];
#pragma unroll
    for (int i = 0; i < 4; ++i)
#pragma unroll
        for (int j = 0; j < 8; ++j)
#pragma unroll
            for (int q = 0; q < 4; ++q) acc[i][j][q] = 0.f;

    auto load_stage = [&](int c, int s) {
        const int kb = c * 64;
        const uint32_t st = sb + s * STAGE;
#pragma unroll
        for (int i = 0; i < 4; ++i) {
            int id = tid + i * 256;
            int r = id >> 3, c8 = id & 7;
            uint32_t off = SWZ64(r, c8);
            cpa16(st + off, A + (size_t)(m0 + r) * K + kb + c8 * 8);
        }
#pragma unroll
        for (int i = 0; i < 8; ++i) {
            int id = tid + i * 256;
            int r = id >> 3, c8 = id & 7;
            uint32_t off = SWZ64(r, c8);
            cpa16(st + TILE_A + off, B + (size_t)(n0 + r) * K + kb + c8 * 8);
        }
        CP_COMMIT();
    };

    load_stage(0, 0);
    if (nk > 1) load_stage(1, 1);

    for (int c = 0; c < nk; ++c) {
        if (c + 1 < nk) { CP_WAIT1(); } else { CP_WAIT0(); }
        __syncthreads();
        if (c + 2 < nk) load_stage(c + 2, (c + 2) % 3);

        const uint32_t st = sb + (c % 3) * STAGE;
#pragma unroll
        for (int ks = 0; ks < 4; ++ks) {
            uint32_t af[4][4], bf[4][4];
#pragma unroll
            for (int mt = 0; mt < 4; ++mt) {
                int r = wm + mt * 16 + rl;
                int c8 = 2 * ks + ch;
                uint32_t off = SWZ64(r, c8);
                ldsm_x4(af[mt][0], af[mt][1], af[mt][2], af[mt][3], st + off);
            }
#pragma unroll
            for (int np = 0; np < 4; ++np) {
                int r = wn + np * 16 + rl;
                int c8 = 2 * ks + ch;
                uint32_t off = SWZ64(r, c8);
                ldsm_x4(bf[np][0], bf[np][1], bf[np][2], bf[np][3], st + TILE_A + off);
            }
#pragma unroll
            for (int mt = 0; mt < 4; ++mt) {
#pragma unroll
                for (int nt = 0; nt < 8; ++nt) {
                    const int np = nt >> 1, sel = nt & 1;
                    float* d = acc[mt][nt];
                    mma_f16(d[0], d[1], d[2], d[3],
                            af[mt][0], af[mt][1], af[mt][2], af[mt][3],
                            bf[np][sel], bf[np][2 + sel]);
                }
            }
        }
        __syncthreads();
    }

#pragma unroll
    for (int mt = 0; mt < 4; ++mt) {
#pragma unroll
        for (int nt = 0; nt < 8; ++nt) {
            int rg = m0 + wm + mt * 16 + (lane >> 2);
            int cg = n0 + wn + nt * 8 + (lane & 3) * 2;
            float* d = acc[mt][nt];
            *(float2*)(C + (size_t)rg * N + cg)       = make_float2(d[0], d[1]);
            *(float2*)(C + (size_t)(rg + 8) * N + cg) = make_float2(d[2], d[3]);
        }
    }
}

// ---------------- RoPE + pre-scale + fp16 convert; V convert fused ----------------
// Q (strided in g_QKV) -> Qh ; K -> Kh ; V -> Vh
__global__ __launch_bounds__(256) void rope_conv(
    const float* __restrict__ QKV, const int* __restrict__ pos_ids,
    __half* __restrict__ Qh, __half* __restrict__ Kh, __half* __restrict__ Vh)
{
    const int s = blockIdx.x;
    const float scale = 0.08838834764831845f;  // 1/sqrt(128)
    __shared__ float cs[64], sn[64];
    if (threadIdx.x < 64) {
        double invf = exp(-(double)threadIdx.x * (9.210340371976184 / 64.0));
        float ang = (float)((double)pos_ids[s] * invf);
        float c, si;
        sincosf(ang, &si, &c);
        cs[threadIdx.x] = c;
        sn[threadIdx.x] = si;
    }
    __syncthreads();
    // Q: 2048 pairs
#pragma unroll
    for (int it = 0; it < 8; ++it) {
        int pp = threadIdx.x + it * 256;
        int head = pp >> 6, i = pp & 63;
        size_t bs = (size_t)s * QKVD + head * HD + i;
        size_t bd = (size_t)s * QDIM + head * HD + i;
        float x0 = QKV[bs], x1 = QKV[bs + 64];
        float c = cs[i], si = sn[i];
        Qh[bd]      = __float2half_rn((x0 * c - x1 * si) * scale);
        Qh[bd + 64] = __float2half_rn((x1 * c + x0 * si) * scale);
    }
    // K: 512 pairs
#pragma unroll
    for (int it = 0; it < 2; ++it) {
        int pp = threadIdx.x + it * 256;
        int head = pp >> 6, i = pp & 63;
        size_t bs = (size_t)s * QKVD + QDIM + head * HD + i;
        size_t bd = (size_t)s * KVDIM + head * HD + i;
        float x0 = QKV[bs], x1 = QKV[bs + 64];
        float c = cs[i], si = sn[i];
        Kh[bd]      = __float2half_rn(x0 * c - x1 * si);
        Kh[bd + 64] = __float2half_rn(x1 * c + x0 * si);
    }
    // V: plain convert (1024 floats)
    {
        const float* src = QKV + (size_t)s * QKVD + QDIM + KVDIM;
        __half* dst = Vh + (size_t)s * KVDIM;
        int j = threadIdx.x * 4;
        float4 a = *(const float4*)(src + j);
        __half2 h0, h1;
        h0.x = __float2half_rn(a.x); h0.y = __float2half_rn(a.y);
        h1.x = __float2half_rn(a.z); h1.y = __float2half_rn(a.w);
        *(__half2*)(dst + j)     = h0;
        *(__half2*)(dst + j + 2) = h1;
    }
}

// ---------------- HMMA flash attention (causal, plain fp16) ----------------
#define ASWZ(row, g) ((row) * 256 + (((g) ^ ((row) & 7)) << 4))

__global__ __launch_bounds__(256) void attn_hmma(
    const __half* __restrict__ Qh, const __half* __restrict__ Kh,
    const __half* __restrict__ Vh, __half* __restrict__ AOh)
{
    extern __shared__ char sm[];
    const uint32_t sb = smem_u32(sm);
    constexpr int MTILE = 64 * 128 * 2;     // 16 KB per matrix
    constexpr int STAGE = 2 * MTILE;        // K + V = 32 KB

    const int tid = threadIdx.x, wid = tid >> 5, lane = tid & 31;
    const int h  = blockIdx.y, kh = h >> 2;
    const int bq = gridDim.x - 1 - blockIdx.x;
    const int q0 = bq * 128;
    const int wr = wid * 16;
    const int r  = lane >> 2, c2 = (lane & 3) * 2;
    const int rl = lane & 15, chh = lane >> 4;

    // Q fragments (fp16), resident in registers
    uint32_t qf[8][4];
    {
        const int row0 = q0 + wr + r;
#pragma unroll
        for (int ks = 0; ks < 8; ++ks) {
            int k2 = ks * 16 + c2;
            size_t b00 = (size_t)row0 * QDIM + h * HD + k2;
            size_t b10 = b00 + (size_t)8 * QDIM;
            qf[ks][0] = *(const uint32_t*)(Qh + b00);
            qf[ks][1] = *(const uint32_t*)(Qh + b10);
            qf[ks][2] = *(const uint32_t*)(Qh + b00 + 8);
            qf[ks][3] = *(const uint32_t*)(Qh + b10 + 8);
        }
    }

    float o[16][4];
#pragma unroll
    for (int i = 0; i < 16; ++i)
#pragma unroll
        for (int q = 0; q < 4; ++q) o[i][q] = 0.f;
    float m1 = -1e30f, m2 = -1e30f, l1 = 0.f, l2 = 0.f;

    const int ntiles = 2 * bq + 2;

    auto load_kv = [&](int kt, int s) {
        const int k0 = kt * 64;
        const uint32_t st = sb + s * STAGE;
#pragma unroll
        for (int i = 0; i < 4; ++i) {
            int id = tid + i * 256;
            int rw = id >> 4, g = id & 15;
            uint32_t off = ASWZ(rw, g);
            size_t src = (size_t)(k0 + rw) * KVDIM + kh * HD + g * 8;
            cpa16(st + off,         Kh + src);
            cpa16(st + MTILE + off, Vh + src);
        }
        CP_COMMIT();
    };

    load_kv(0, 0);

    for (int kt = 0; kt < ntiles; ++kt) {
        if (kt + 1 < ntiles) { load_kv(kt + 1, (kt + 1) & 1); CP_WAIT1(); }
        else                 { CP_WAIT0(); }
        __syncthreads();

        const uint32_t st = sb + (kt & 1) * STAGE;
        const int k0 = kt * 64;

        // ---- S = Q @ K^T
        float sacc[8][4];
#pragma unroll
        for (int i = 0; i < 8; ++i)
#pragma unroll
            for (int q = 0; q < 4; ++q) sacc[i][q] = 0.f;

#pragma unroll
        for (int ks = 0; ks < 8; ++ks) {
            uint32_t kb[4][4];
#pragma unroll
            for (int np = 0; np < 4; ++np) {
                int row = np * 16 + rl;
                int g = 2 * ks + chh;
                uint32_t off = ASWZ(row, g);
                ldsm_x4(kb[np][0], kb[np][1], kb[np][2], kb[np][3], st + off);
            }
#pragma unroll
            for (int nt = 0; nt < 8; ++nt) {
                const int np = nt >> 1, sel = nt & 1;
                float* d = sacc[nt];
                mma_f16(d[0], d[1], d[2], d[3],
                        qf[ks][0], qf[ks][1], qf[ks][2], qf[ks][3],
                        kb[np][sel], kb[np][2 + sel]);
            }
        }

        // ---- analytic causal mask
        if (k0 + 63 > q0 + wr) {
            const int row1 = q0 + wr + r, row2 = row1 + 8;
#pragma unroll
            for (int nt = 0; nt < 8; ++nt) {
                int col = k0 + nt * 8 + c2;
                if (col     > row1) sacc[nt][0] = -1e30f;
                if (col + 1 > row1) sacc[nt][1] = -1e30f;
                if (col     > row2) sacc[nt][2] = -1e30f;
                if (col + 1 > row2) sacc[nt][3] = -1e30f;
            }
        }

        // ---- online softmax
        float mx1 = -1e30f, mx2 = -1e30f;
#pragma unroll
        for (int nt = 0; nt < 8; ++nt) {
            mx1 = fmaxf(mx1, fmaxf(sacc[nt][0], sacc[nt][1]));
            mx2 = fmaxf(mx2, fmaxf(sacc[nt][2], sacc[nt][3]));
        }
        mx1 = fmaxf(mx1, __shfl_xor_sync(0xffffffffu, mx1, 1));
        mx1 = fmaxf(mx1, __shfl_xor_sync(0xffffffffu, mx1, 2));
        mx2 = fmaxf(mx2, __shfl_xor_sync(0xffffffffu, mx2, 1));
        mx2 = fmaxf(mx2, __shfl_xor_sync(0xffffffffu, mx2, 2));
        float nm1 = fmaxf(m1, mx1), nm2 = fmaxf(m2, mx2);
        float cf1 = __expf(m1 - nm1), cf2 = __expf(m2 - nm2);
        m1 = nm1; m2 = nm2;

        float ls1 = 0.f, ls2 = 0.f;
#pragma unroll
        for (int nt = 0; nt < 8; ++nt) {
            sacc[nt][0] = __expf(sacc[nt][0] - nm1);
            sacc[nt][1] = __expf(sacc[nt][1] - nm1);
            sacc[nt][2] = __expf(sacc[nt][2] - nm2);
            sacc[nt][3] = __expf(sacc[nt][3] - nm2);
            ls1 += sacc[nt][0] + sacc[nt][1];
            ls2 += sacc[nt][2] + sacc[nt][3];
        }
        ls1 += __shfl_xor_sync(0xffffffffu, ls1, 1);
        ls1 += __shfl_xor_sync(0xffffffffu, ls1, 2);
        ls2 += __shfl_xor_sync(0xffffffffu, ls2, 1);
        ls2 += __shfl_xor_sync(0xffffffffu, ls2, 2);
        l1 = l1 * cf1 + ls1;
        l2 = l2 * cf2 + ls2;
#pragma unroll
        for (int dt = 0; dt < 16; ++dt) {
            o[dt][0] *= cf1; o[dt][1] *= cf1;
            o[dt][2] *= cf2; o[dt][3] *= cf2;
        }

        // ---- O += P @ V (plain fp16 P), V via ldmatrix.trans
#pragma unroll
        for (int s = 0; s < 4; ++s) {
            uint32_t ap[4];
#pragma unroll
            for (int half = 0; half < 2; ++half) {
                const float* sv = sacc[2 * s + half];
                __half2 h01, h23;
                h01.x = __float2half_rn(sv[0]);
                h01.y = __float2half_rn(sv[1]);
                h23.x = __float2half_rn(sv[2]);
                h23.y = __float2half_rn(sv[3]);
                ap[2 * half + 0] = *(uint32_t*)&h01;
                ap[2 * half + 1] = *(uint32_t*)&h23;
            }
#pragma unroll
            for (int dg = 0; dg < 8; ++dg) {
                int row = s * 16 + rl;
                int g = 2 * dg + chh;
                uint32_t off = ASWZ(row, g);
                uint32_t v4[4];
                ldsm_x4_t(v4[0], v4[1], v4[2], v4[3], st + MTILE + off);
                float* d0 = o[2 * dg];
                float* d1 = o[2 * dg + 1];
                mma_f16(d0[0], d0[1], d0[2], d0[3], ap[0], ap[1], ap[2], ap[3], v4[0], v4[1]);
                mma_f16(d1[0], d1[1], d1[2], d1[3], ap[0], ap[1], ap[2], ap[3], v4[2], v4[3]);
            }
        }
        __syncthreads();
    }

    // ---- epilogue: normalize, convert to fp16, store
    const float inv1 = 1.f / l1, inv2 = 1.f / l2;
    const int row1 = q0 + wr + r;
#pragma unroll
    for (int dt = 0; dt < 16; ++dt) {
        size_t c0 = (size_t)row1 * QDIM + h * HD + dt * 8 + c2;
        size_t c1 = c0 + (size_t)8 * QDIM;
        __half2 h01;
        h01.x = __float2half_rn(o[dt][0] * inv1);
        h01.y = __float2half_rn(o[dt][1] * inv1);
        *(__half2*)(AOh + c0) = h01;
        h01.x = __float2half_rn(o[dt][2] * inv2);
        h01.y = __float2half_rn(o[dt][3] * inv2);
        *(__half2*)(AOh + c1) = h01;
    }
}

// ---------------- launch ----------------
extern "C" void kernel_launch(void* const* d_in, const int* in_sizes, int n_in,
                              void* d_out, int out_size)
{
    const float* hs   = (const float*)d_in[0];
    const int*   pos  = (const int*)d_in[2];
    const float* Wq   = (const float*)d_in[3];
    const float* Wk   = (const float*)d_in[4];
    const float* Wv   = (const float*)d_in[5];
    const float* Wo   = (const float*)d_in[6];
    float* out = (float*)d_out;

    float* qkvp;
    __half *ah, *aoh, *qhp, *khp, *vhp, *wqkvt, *wot;
    cudaGetSymbolAddress((void**)&qkvp,  g_QKV);
    cudaGetSymbolAddress((void**)&ah,    g_Ah);
    cudaGetSymbolAddress((void**)&aoh,   g_AOh);
    cudaGetSymbolAddress((void**)&qhp,   g_Qh);
    cudaGetSymbolAddress((void**)&khp,   g_Kh);
    cudaGetSymbolAddress((void**)&vhp,   g_Vh);
    cudaGetSymbolAddress((void**)&wqkvt, g_WqkvT);
    cudaGetSymbolAddress((void**)&wot,   g_WoT);

    const int gemm_smem = 3 * (128 * 64 * 2 + 256 * 64 * 2);  // 147456
    cudaFuncSetAttribute(gemm_hmma_h1, cudaFuncAttributeMaxDynamicSharedMemorySize, gemm_smem);
    const int attn_smem = 2 * 2 * 64 * 128 * 2;   // 65536
    cudaFuncSetAttribute(attn_hmma, cudaFuncAttributeMaxDynamicSharedMemorySize, attn_smem);

    // converts / transposes
    conv_plain<<<(SQ * HID / 4 + 255) / 256, 256>>>(hs, ah, SQ * HID / 4);
    transpose_all<<<40960, 256>>>(Wq, Wk, Wv, Wo, wqkvt, wot);

    // fused QKV projection (N=6144)
    gemm_hmma_h1<<<dim3(QKVD / 256, SQ / 128), 256, gemm_smem>>>(ah, wqkvt, qkvp, SQ, QKVD, HID);

    // RoPE + convert Q/K/V to fp16 (single kernel)
    rope_conv<<<SQ, 256>>>(qkvp, pos, qhp, khp, vhp);

    // attention (plain fp16 operands, fp32 softmax/accum)
    attn_hmma<<<dim3(SQ / 128, NH), 256, attn_smem>>>(qhp, khp, vhp, aoh);

    // output projection
    gemm_hmma_h1<<<dim3(HID / 256, SQ / 128), 256, gemm_smem>>>(aoh, wot, out, SQ, HID, QDIM);
}

// round 10
// speedup vs baseline: 9.3056x; 1.1500x over previous
#include <cuda_runtime.h>
#include <cuda_fp16.h>
#include <math.h>
#include <cstdint>

#define SQ    2048
#define HID   4096
#define NH    32
#define NKV   8
#define HD    128
#define QDIM  (NH*HD)    // 4096
#define KVDIM (NKV*HD)   // 1024
#define QKVD  (QDIM + 2*KVDIM)   // 6144

// ---------------- scratch (static device allocations) ----------------
__device__ float g_QKV[SQ * QKVD];     // cols 0-4095 Q, 4096-5119 K, 5120-6143 V

__device__ __half g_Ah [SQ * HID];
__device__ __half g_AOh[SQ * QDIM];

__device__ __half g_Qh[SQ * QDIM];
__device__ __half g_Kh[SQ * KVDIM];
__device__ __half g_Vh[SQ * KVDIM];

__device__ __half g_Wqkv[HID * QKVD];   // [K=4096, N=6144] natural layout, fp16
__device__ __half g_Wo16[HID * QDIM];   // [K=4096, N=4096] natural layout, fp16

// ---------------- PTX helpers (sm_80-era instructions only) ----------------
__device__ __forceinline__ uint32_t smem_u32(const void* p) {
    uint32_t a;
    asm("{ .reg .u64 t; cvta.to.shared.u64 t, %1; cvt.u32.u64 %0, t; }" : "=r"(a) : "l"(p));
    return a;
}

__device__ __forceinline__ void cpa16(uint32_t dst, const void* src) {
    asm volatile("cp.async.cg.shared.global [%0], [%1], 16;" :: "r"(dst), "l"(src) : "memory");
}
#define CP_COMMIT() asm volatile("cp.async.commit_group;" ::: "memory")
#define CP_WAIT2()  asm volatile("cp.async.wait_group 2;" ::: "memory")
#define CP_WAIT1()  asm volatile("cp.async.wait_group 1;" ::: "memory")
#define CP_WAIT0()  asm volatile("cp.async.wait_group 0;" ::: "memory")

__device__ __forceinline__ void ldsm_x4(uint32_t& r0, uint32_t& r1, uint32_t& r2, uint32_t& r3,
                                        uint32_t addr) {
    asm volatile("ldmatrix.sync.aligned.m8n8.x4.shared.b16 {%0,%1,%2,%3}, [%4];"
                 : "=r"(r0), "=r"(r1), "=r"(r2), "=r"(r3) : "r"(addr));
}
__device__ __forceinline__ void ldsm_x4_t(uint32_t& r0, uint32_t& r1, uint32_t& r2, uint32_t& r3,
                                          uint32_t addr) {
    asm volatile("ldmatrix.sync.aligned.m8n8.x4.trans.shared.b16 {%0,%1,%2,%3}, [%4];"
                 : "=r"(r0), "=r"(r1), "=r"(r2), "=r"(r3) : "r"(addr));
}

__device__ __forceinline__ void mma_f16(float& d0, float& d1, float& d2, float& d3,
                                        uint32_t a0, uint32_t a1, uint32_t a2, uint32_t a3,
                                        uint32_t b0, uint32_t b1) {
    asm volatile("mma.sync.aligned.m16n8k16.row.col.f32.f16.f16.f32 "
                 "{%0,%1,%2,%3}, {%4,%5,%6,%7}, {%8,%9}, {%0,%1,%2,%3};"
                 : "+f"(d0), "+f"(d1), "+f"(d2), "+f"(d3)
                 : "r"(a0), "r"(a1), "r"(a2), "r"(a3), "r"(b0), "r"(b1));
}

// ---------------- fp32 -> fp16 convert (elementwise, float4) ----------------
__global__ __launch_bounds__(256) void conv_plain(
    const float* __restrict__ X, __half* __restrict__ H, int n4)
{
    int i = blockIdx.x * 256 + threadIdx.x;
    if (i >= n4) return;
    float4 a = ((const float4*)X)[i];
    __half2 h0, h1;
    h0.x = __float2half_rn(a.x); h0.y = __float2half_rn(a.y);
    h1.x = __float2half_rn(a.z); h1.y = __float2half_rn(a.w);
    ((__half2*)H)[2 * i]     = h0;
    ((__half2*)H)[2 * i + 1] = h1;
}

// ---------------- fused weight converts: fp32 [K,N] -> fp16, packed ----------------
// Wq -> g_Wqkv cols 0-4095; Wk -> cols 4096-5119; Wv -> cols 5120-6143; Wo -> g_Wo16.
__global__ __launch_bounds__(256) void conv_w(
    const float* __restrict__ Wq, const float* __restrict__ Wk,
    const float* __restrict__ Wv, const float* __restrict__ Wo,
    __half* __restrict__ wqkv, __half* __restrict__ wo16)
{
    int b = blockIdx.x;
    const float* W; __half* D; int N, coff, stride;
    if (b < 16384)       { W = Wq; D = wqkv; N = 4096; coff = 0;    stride = QKVD; }
    else if (b < 20480)  { b -= 16384; W = Wk; D = wqkv; N = 1024; coff = 4096; stride = QKVD; }
    else if (b < 24576)  { b -= 20480; W = Wv; D = wqkv; N = 1024; coff = 5120; stride = QKVD; }
    else                 { b -= 24576; W = Wo; D = wo16; N = 4096; coff = 0;    stride = 4096; }

    int idx = b * 256 + threadIdx.x;        // float4 index within this weight
    int nq = N >> 2;
    int k = idx / nq, nc = (idx - k * nq) << 2;
    float4 a = *(const float4*)(W + (size_t)k * N + nc);
    __half2 h0, h1;
    h0.x = __float2half_rn(a.x); h0.y = __float2half_rn(a.y);
    h1.x = __float2half_rn(a.z); h1.y = __float2half_rn(a.w);
    __half* dst = D + (size_t)k * stride + coff + nc;
    *(__half2*)dst       = h0;
    *(__half2*)(dst + 2) = h1;
}

// ---------------- HMMA fp16 GEMM ----------------
// C[M,N] fp32 = A[M,K] @ B[K,N]  (A row-major K-contig, B row-major N-contig).
// CTA 128x256, 8 warps 2(m) x 4(n), k-chunk 64, 4-stage cp.async, trans-ldsm for B.
#define SWZ64(r, c8) ((r) * 128 + (((c8) ^ ((r) & 7)) << 4))
#define SWZB(r, g)   ((r) * 512 + (((g) ^ ((r) & 7)) << 4))

__global__ __launch_bounds__(256, 1) void gemm_hmma_h1(
    const __half* __restrict__ A, const __half* __restrict__ B,
    float* __restrict__ C, int M, int N, int K)
{
    extern __shared__ char smem[];
    constexpr int TILE_A = 128 * 64 * 2;    // 16 KB
    constexpr int TILE_B = 64 * 256 * 2;    // 32 KB  (64 k-rows x 512B)
    constexpr int STAGE  = TILE_A + TILE_B; // 48 KB
    const uint32_t sb = smem_u32(smem);

    const int tid  = threadIdx.x;
    const int wid  = tid >> 5;
    const int lane = tid & 31;
    const int m0 = blockIdx.y * 128;
    const int n0 = blockIdx.x * 256;
    const int wm = (wid >> 2) * 64;
    const int wn = (wid & 3) * 64;
    const int nk = K >> 6;

    const int rl  = lane & 15;
    const int ch  = lane >> 4;

    float acc[4][8][4];
#pragma unroll
    for (int i = 0; i < 4; ++i)
#pragma unroll
        for (int j = 0; j < 8; ++j)
#pragma unroll
            for (int q = 0; q < 4; ++q) acc[i][j][q] = 0.f;

    auto load_stage = [&](int c, int s) {
        const int kb = c * 64;
        const uint32_t st = sb + s * STAGE;
#pragma unroll
        for (int i = 0; i < 4; ++i) {     // A: 128 rows x 128B, K-contig
            int id = tid + i * 256;
            int r = id >> 3, c8 = id & 7;
            cpa16(st + SWZ64(r, c8), A + (size_t)(m0 + r) * K + kb + c8 * 8);
        }
#pragma unroll
        for (int i = 0; i < 8; ++i) {     // B: 64 k-rows x 512B, N-contig
            int id = tid + i * 256;
            int r = id >> 5, g = id & 31;
            cpa16(st + TILE_A + SWZB(r, g), B + (size_t)(kb + r) * N + n0 + g * 8);
        }
        CP_COMMIT();
    };

    load_stage(0, 0);
    if (nk > 1) load_stage(1, 1);
    if (nk > 2) load_stage(2, 2);

    for (int c = 0; c < nk; ++c) {
        if (c + 2 < nk)      { CP_WAIT2(); }
        else if (c + 1 < nk) { CP_WAIT1(); }
        else                 { CP_WAIT0(); }
        __syncthreads();
        if (c + 3 < nk) load_stage(c + 3, (c + 3) & 3);

        const uint32_t st = sb + (c & 3) * STAGE;
        const uint32_t stb = st + TILE_A;
        const int gb0 = wn >> 3;
#pragma unroll
        for (int ks = 0; ks < 4; ++ks) {
            uint32_t af[4][4];
#pragma unroll
            for (int mt = 0; mt < 4; ++mt) {
                int r = wm + mt * 16 + rl;
                ldsm_x4(af[mt][0], af[mt][1], af[mt][2], af[mt][3],
                        st + SWZ64(r, 2 * ks + ch));
            }
#pragma unroll
            for (int np = 0; np < 4; ++np) {
                uint32_t b0, b1, b2, b3;
                ldsm_x4_t(b0, b1, b2, b3,
                          stb + SWZB(ks * 16 + rl, gb0 + np * 2 + ch));
#pragma unroll
                for (int mt = 0; mt < 4; ++mt) {
                    float* d0 = acc[mt][np * 2];
                    float* d1 = acc[mt][np * 2 + 1];
                    mma_f16(d0[0], d0[1], d0[2], d0[3],
                            af[mt][0], af[mt][1], af[mt][2], af[mt][3], b0, b1);
                    mma_f16(d1[0], d1[1], d1[2], d1[3],
                            af[mt][0], af[mt][1], af[mt][2], af[mt][3], b2, b3);
                }
            }
        }
        // no bottom sync: next overwrite of any stage is ordered by the top barrier
    }

#pragma unroll
    for (int mt = 0; mt < 4; ++mt) {
#pragma unroll
        for (int nt = 0; nt < 8; ++nt) {
            int rg = m0 + wm + mt * 16 + (lane >> 2);
            int cg = n0 + wn + nt * 8 + (lane & 3) * 2;
            float* d = acc[mt][nt];
            *(float2*)(C + (size_t)rg * N + cg)       = make_float2(d[0], d[1]);
            *(float2*)(C + (size_t)(rg + 8) * N + cg) = make_float2(d[2], d[3]);
        }
    }
}

// ---------------- RoPE + pre-scale + fp16 convert; V convert fused ----------------
__global__ __launch_bounds__(256) void rope_conv(
    const float* __restrict__ QKV, const int* __restrict__ pos_ids,
    __half* __restrict__ Qh, __half* __restrict__ Kh, __half* __restrict__ Vh)
{
    const int s = blockIdx.x;
    const float scale = 0.08838834764831845f;  // 1/sqrt(128)
    __shared__ float cs[64], sn[64];
    if (threadIdx.x < 64) {
        double invf = exp(-(double)threadIdx.x * (9.210340371976184 / 64.0));
        float ang = (float)((double)pos_ids[s] * invf);
        float c, si;
        sincosf(ang, &si, &c);
        cs[threadIdx.x] = c;
        sn[threadIdx.x] = si;
    }
    __syncthreads();
#pragma unroll
    for (int it = 0; it < 8; ++it) {
        int pp = threadIdx.x + it * 256;
        int head = pp >> 6, i = pp & 63;
        size_t bs = (size_t)s * QKVD + head * HD + i;
        size_t bd = (size_t)s * QDIM + head * HD + i;
        float x0 = QKV[bs], x1 = QKV[bs + 64];
        float c = cs[i], si = sn[i];
        Qh[bd]      = __float2half_rn((x0 * c - x1 * si) * scale);
        Qh[bd + 64] = __float2half_rn((x1 * c + x0 * si) * scale);
    }
#pragma unroll
    for (int it = 0; it < 2; ++it) {
        int pp = threadIdx.x + it * 256;
        int head = pp >> 6, i = pp & 63;
        size_t bs = (size_t)s * QKVD + QDIM + head * HD + i;
        size_t bd = (size_t)s * KVDIM + head * HD + i;
        float x0 = QKV[bs], x1 = QKV[bs + 64];
        float c = cs[i], si = sn[i];
        Kh[bd]      = __float2half_rn(x0 * c - x1 * si);
        Kh[bd + 64] = __float2half_rn(x1 * c + x0 * si);
    }
    {
        const float* src = QKV + (size_t)s * QKVD + QDIM + KVDIM;
        __half* dst = Vh + (size_t)s * KVDIM;
        int j = threadIdx.x * 4;
        float4 a = *(const float4*)(src + j);
        __half2 h0, h1;
        h0.x = __float2half_rn(a.x); h0.y = __float2half_rn(a.y);
        h1.x = __float2half_rn(a.z); h1.y = __float2half_rn(a.w);
        *(__half2*)(dst + j)     = h0;
        *(__half2*)(dst + j + 2) = h1;
    }
}

// ---------------- HMMA flash attention (causal, k-tile 128) ----------------
#define ASWZ(row, g) ((row) * 256 + (((g) ^ ((row) & 7)) << 4))

__global__ __launch_bounds__(256) void attn_hmma(
    const __half* __restrict__ Qh, const __half* __restrict__ Kh,
    const __half* __restrict__ Vh, __half* __restrict__ AOh)
{
    extern __shared__ char sm[];
    const uint32_t sb = smem_u32(sm);
    constexpr int MTILE = 128 * 128 * 2;    // 32 KB per matrix (128 kv-rows x 256B)
    constexpr int STAGE = 2 * MTILE;        // K + V = 64 KB

    const int tid = threadIdx.x, wid = tid >> 5, lane = tid & 31;
    const int h  = blockIdx.y, kh = h >> 2;
    const int bq = gridDim.x - 1 - blockIdx.x;
    const int q0 = bq * 128;
    const int wr = wid * 16;
    const int r  = lane >> 2, c2 = (lane & 3) * 2;
    const int rl = lane & 15, chh = lane >> 4;

    // Q fragments (fp16), resident in registers
    uint32_t qf[8][4];
    {
        const int row0 = q0 + wr + r;
#pragma unroll
        for (int ks = 0; ks < 8; ++ks) {
            int k2 = ks * 16 + c2;
            size_t b00 = (size_t)row0 * QDIM + h * HD + k2;
            size_t b10 = b00 + (size_t)8 * QDIM;
            qf[ks][0] = *(const uint32_t*)(Qh + b00);
            qf[ks][1] = *(const uint32_t*)(Qh + b10);
            qf[ks][2] = *(const uint32_t*)(Qh + b00 + 8);
            qf[ks][3] = *(const uint32_t*)(Qh + b10 + 8);
        }
    }

    float o[16][4];
#pragma unroll
    for (int i = 0; i < 16; ++i)
#pragma unroll
        for (int q = 0; q < 4; ++q) o[i][q] = 0.f;
    float m1 = -1e30f, m2 = -1e30f, l1 = 0.f, l2 = 0.f;

    const int ntiles = bq + 1;

    auto load_kv = [&](int kt, int s) {
        const int k0 = kt * 128;
        const uint32_t st = sb + s * STAGE;
#pragma unroll
        for (int i = 0; i < 8; ++i) {
            int id = tid + i * 256;             // 2048 chunks of 16B
            int rw = id >> 4, g = id & 15;
            uint32_t off = ASWZ(rw, g);
            size_t src = (size_t)(k0 + rw) * KVDIM + kh * HD + g * 8;
            cpa16(st + off,         Kh + src);
            cpa16(st + MTILE + off, Vh + src);
        }
        CP_COMMIT();
    };

    load_kv(0, 0);

    for (int kt = 0; kt < ntiles; ++kt) {
        if (kt + 1 < ntiles) { load_kv(kt + 1, (kt + 1) & 1); CP_WAIT1(); }
        else                 { CP_WAIT0(); }
        __syncthreads();

        const uint32_t st = sb + (kt & 1) * STAGE;
        const int k0 = kt * 128;

        // ---- S = Q @ K^T  (128 kv columns)
        float sacc[16][4];
#pragma unroll
        for (int i = 0; i < 16; ++i)
#pragma unroll
            for (int q = 0; q < 4; ++q) sacc[i][q] = 0.f;

#pragma unroll
        for (int ks = 0; ks < 8; ++ks) {
#pragma unroll
            for (int np = 0; np < 8; ++np) {
                uint32_t b0, b1, b2, b3;
                ldsm_x4(b0, b1, b2, b3, st + ASWZ(np * 16 + rl, 2 * ks + chh));
                float* d0 = sacc[np * 2];
                float* d1 = sacc[np * 2 + 1];
                mma_f16(d0[0], d0[1], d0[2], d0[3],
                        qf[ks][0], qf[ks][1], qf[ks][2], qf[ks][3], b0, b2);
                mma_f16(d1[0], d1[1], d1[2], d1[3],
                        qf[ks][0], qf[ks][1], qf[ks][2], qf[ks][3], b1, b3);
            }
        }

        // ---- analytic causal mask (only the last tile crosses the diagonal)
        if (k0 + 127 > q0 + wr) {
            const int row1 = q0 + wr + r, row2 = row1 + 8;
#pragma unroll
            for (int nt = 0; nt < 16; ++nt) {
                int col = k0 + nt * 8 + c2;
                if (col     > row1) sacc[nt][0] = -1e30f;
                if (col + 1 > row1) sacc[nt][1] = -1e30f;
                if (col     > row2) sacc[nt][2] = -1e30f;
                if (col + 1 > row2) sacc[nt][3] = -1e30f;
            }
        }

        // ---- online softmax
        float mx1 = -1e30f, mx2 = -1e30f;
#pragma unroll
        for (int nt = 0; nt < 16; ++nt) {
            mx1 = fmaxf(mx1, fmaxf(sacc[nt][0], sacc[nt][1]));
            mx2 = fmaxf(mx2, fmaxf(sacc[nt][2], sacc[nt][3]));
        }
        mx1 = fmaxf(mx1, __shfl_xor_sync(0xffffffffu, mx1, 1));
        mx1 = fmaxf(mx1, __shfl_xor_sync(0xffffffffu, mx1, 2));
        mx2 = fmaxf(mx2, __shfl_xor_sync(0xffffffffu, mx2, 1));
        mx2 = fmaxf(mx2, __shfl_xor_sync(0xffffffffu, mx2, 2));
        float nm1 = fmaxf(m1, mx1), nm2 = fmaxf(m2, mx2);
        float cf1 = __expf(m1 - nm1), cf2 = __expf(m2 - nm2);
        m1 = nm1; m2 = nm2;

        float ls1 = 0.f, ls2 = 0.f;
#pragma unroll
        for (int nt = 0; nt < 16; ++nt) {
            sacc[nt][0] = __expf(sacc[nt][0] - nm1);
            sacc[nt][1] = __expf(sacc[nt][1] - nm1);
            sacc[nt][2] = __expf(sacc[nt][2] - nm2);
            sacc[nt][3] = __expf(sacc[nt][3] - nm2);
            ls1 += sacc[nt][0] + sacc[nt][1];
            ls2 += sacc[nt][2] + sacc[nt][3];
        }
        ls1 += __shfl_xor_sync(0xffffffffu, ls1, 1);
        ls1 += __shfl_xor_sync(0xffffffffu, ls1, 2);
        ls2 += __shfl_xor_sync(0xffffffffu, ls2, 1);
        ls2 += __shfl_xor_sync(0xffffffffu, ls2, 2);
        l1 = l1 * cf1 + ls1;
        l2 = l2 * cf2 + ls2;
#pragma unroll
        for (int dt = 0; dt < 16; ++dt) {
            o[dt][0] *= cf1; o[dt][1] *= cf1;
            o[dt][2] *= cf2; o[dt][3] *= cf2;
        }

        // ---- O += P @ V, V via ldmatrix.trans  (128 kv rows = 8 k-groups)
#pragma unroll
        for (int s = 0; s < 8; ++s) {
            uint32_t ap[4];
#pragma unroll
            for (int half = 0; half < 2; ++half) {
                const float* sv = sacc[2 * s + half];
                __half2 h01, h23;
                h01.x = __float2half_rn(sv[0]);
                h01.y = __float2half_rn(sv[1]);
                h23.x = __float2half_rn(sv[2]);
                h23.y = __float2half_rn(sv[3]);
                ap[2 * half + 0] = *(uint32_t*)&h01;
                ap[2 * half + 1] = *(uint32_t*)&h23;
            }
#pragma unroll
            for (int dg = 0; dg < 8; ++dg) {
                uint32_t v0, v1, v2, v3;
                ldsm_x4_t(v0, v1, v2, v3,
                          st + MTILE + ASWZ(s * 16 + rl, 2 * dg + chh));
                float* d0 = o[2 * dg];
                float* d1 = o[2 * dg + 1];
                mma_f16(d0[0], d0[1], d0[2], d0[3], ap[0], ap[1], ap[2], ap[3], v0, v1);
                mma_f16(d1[0], d1[1], d1[2], d1[3], ap[0], ap[1], ap[2], ap[3], v2, v3);
            }
        }
        __syncthreads();
    }

    // ---- epilogue: normalize, convert to fp16, store
    const float inv1 = 1.f / l1, inv2 = 1.f / l2;
    const int row1 = q0 + wr + r;
#pragma unroll
    for (int dt = 0; dt < 16; ++dt) {
        size_t c0 = (size_t)row1 * QDIM + h * HD + dt * 8 + c2;
        size_t c1 = c0 + (size_t)8 * QDIM;
        __half2 h01;
        h01.x = __float2half_rn(o[dt][0] * inv1);
        h01.y = __float2half_rn(o[dt][1] * inv1);
        *(__half2*)(AOh + c0) = h01;
        h01.x = __float2half_rn(o[dt][2] * inv2);
        h01.y = __float2half_rn(o[dt][3] * inv2);
        *(__half2*)(AOh + c1) = h01;
    }
}

// ---------------- launch ----------------
extern "C" void kernel_launch(void* const* d_in, const int* in_sizes, int n_in,
                              void* d_out, int out_size)
{
    const float* hs   = (const float*)d_in[0];
    const int*   pos  = (const int*)d_in[2];
    const float* Wq   = (const float*)d_in[3];
    const float* Wk   = (const float*)d_in[4];
    const float* Wv   = (const float*)d_in[5];
    const float* Wo   = (const float*)d_in[6];
    float* out = (float*)d_out;

    float* qkvp;
    __half *ah, *aoh, *qhp, *khp, *vhp, *wqkv, *wo16;
    cudaGetSymbolAddress((void**)&qkvp, g_QKV);
    cudaGetSymbolAddress((void**)&ah,   g_Ah);
    cudaGetSymbolAddress((void**)&aoh,  g_AOh);
    cudaGetSymbolAddress((void**)&qhp,  g_Qh);
    cudaGetSymbolAddress((void**)&khp,  g_Kh);
    cudaGetSymbolAddress((void**)&vhp,  g_Vh);
    cudaGetSymbolAddress((void**)&wqkv, g_Wqkv);
    cudaGetSymbolAddress((void**)&wo16, g_Wo16);

    const int gemm_smem = 4 * (128 * 64 * 2 + 64 * 256 * 2);  // 196608
    cudaFuncSetAttribute(gemm_hmma_h1, cudaFuncAttributeMaxDynamicSharedMemorySize, gemm_smem);
    const int attn_smem = 2 * 2 * 128 * 128 * 2;   // 131072
    cudaFuncSetAttribute(attn_hmma, cudaFuncAttributeMaxDynamicSharedMemorySize, attn_smem);

    // converts (no transposes needed anymore)
    conv_plain<<<(SQ * HID / 4 + 255) / 256, 256>>>(hs, ah, SQ * HID / 4);
    conv_w<<<40960, 256>>>(Wq, Wk, Wv, Wo, wqkv, wo16);

    // fused QKV projection (N=6144)
    gemm_hmma_h1<<<dim3(QKVD / 256, SQ / 128), 256, gemm_smem>>>(ah, wqkv, qkvp, SQ, QKVD, HID);

    // RoPE + convert Q/K/V to fp16 (single kernel)
    rope_conv<<<SQ, 256>>>(qkvp, pos, qhp, khp, vhp);

    // attention (plain fp16 operands, fp32 softmax/accum, k-tile 128)
    attn_hmma<<<dim3(SQ / 128, NH), 256, attn_smem>>>(qhp, khp, vhp, aoh);

    // output projection
    gemm_hmma_h1<<<dim3(HID / 256, SQ / 128), 256, gemm_smem>>>(aoh, wo16, out, SQ, HID, QDIM);
}

// round 11
// speedup vs baseline: 9.4205x; 1.0123x over previous
#include <cuda_runtime.h>
#include <cuda_fp16.h>
#include <math.h>
#include <cstdint>

#define SQ    2048
#define HID   4096
#define NH    32
#define NKV   8
#define HD    128
#define QDIM  (NH*HD)    // 4096
#define KVDIM (NKV*HD)   // 1024
#define QKVD  (QDIM + 2*KVDIM)   // 6144

// ---------------- scratch (static device allocations) ----------------
__device__ float g_QKV[SQ * QKVD];     // cols 0-4095 Q, 4096-5119 K, 5120-6143 V

__device__ __half g_Ah [SQ * HID];
__device__ __half g_AOh[SQ * QDIM];

__device__ __half g_Qh[SQ * QDIM];
__device__ __half g_Kh[SQ * KVDIM];
__device__ __half g_Vh[SQ * KVDIM];

__device__ __half g_Wqkv[HID * QKVD];   // [K=4096, N=6144] natural layout, fp16
__device__ __half g_Wo16[HID * QDIM];   // [K=4096, N=4096] natural layout, fp16

// ---------------- PTX helpers (sm_80-era instructions only) ----------------
__device__ __forceinline__ uint32_t smem_u32(const void* p) {
    uint32_t a;
    asm("{ .reg .u64 t; cvta.to.shared.u64 t, %1; cvt.u32.u64 %0, t; }" : "=r"(a) : "l"(p));
    return a;
}

__device__ __forceinline__ void cpa16(uint32_t dst, const void* src) {
    asm volatile("cp.async.cg.shared.global [%0], [%1], 16;" :: "r"(dst), "l"(src) : "memory");
}
#define CP_COMMIT() asm volatile("cp.async.commit_group;" ::: "memory")
#define CP_WAIT2()  asm volatile("cp.async.wait_group 2;" ::: "memory")
#define CP_WAIT1()  asm volatile("cp.async.wait_group 1;" ::: "memory")
#define CP_WAIT0()  asm volatile("cp.async.wait_group 0;" ::: "memory")

__device__ __forceinline__ void ldsm_x4(uint32_t& r0, uint32_t& r1, uint32_t& r2, uint32_t& r3,
                                        uint32_t addr) {
    asm volatile("ldmatrix.sync.aligned.m8n8.x4.shared.b16 {%0,%1,%2,%3}, [%4];"
                 : "=r"(r0), "=r"(r1), "=r"(r2), "=r"(r3) : "r"(addr));
}
__device__ __forceinline__ void ldsm_x4_t(uint32_t& r0, uint32_t& r1, uint32_t& r2, uint32_t& r3,
                                          uint32_t addr) {
    asm volatile("ldmatrix.sync.aligned.m8n8.x4.trans.shared.b16 {%0,%1,%2,%3}, [%4];"
                 : "=r"(r0), "=r"(r1), "=r"(r2), "=r"(r3) : "r"(addr));
}

__device__ __forceinline__ void mma_f16(float& d0, float& d1, float& d2, float& d3,
                                        uint32_t a0, uint32_t a1, uint32_t a2, uint32_t a3,
                                        uint32_t b0, uint32_t b1) {
    asm volatile("mma.sync.aligned.m16n8k16.row.col.f32.f16.f16.f32 "
                 "{%0,%1,%2,%3}, {%4,%5,%6,%7}, {%8,%9}, {%0,%1,%2,%3};"
                 : "+f"(d0), "+f"(d1), "+f"(d2), "+f"(d3)
                 : "r"(a0), "r"(a1), "r"(a2), "r"(a3), "r"(b0), "r"(b1));
}

__device__ __forceinline__ uint32_t pack2h(float a, float b) {
    __half2 h;
    h.x = __float2half_rn(a);
    h.y = __float2half_rn(b);
    return *(uint32_t*)&h;
}

// ---------------- fp32 -> fp16 convert: 32B load / 16B store per thread ----------------
__global__ __launch_bounds__(256) void conv_plain(
    const float* __restrict__ X, __half* __restrict__ H, int n8)
{
    int i = blockIdx.x * 256 + threadIdx.x;
    if (i >= n8) return;
    float4 a = ((const float4*)X)[2 * i];
    float4 b = ((const float4*)X)[2 * i + 1];
    uint4 o;
    o.x = pack2h(a.x, a.y);
    o.y = pack2h(a.z, a.w);
    o.z = pack2h(b.x, b.y);
    o.w = pack2h(b.z, b.w);
    ((uint4*)H)[i] = o;
}

// ---------------- fused weight converts: fp32 [K,N] -> fp16 packed, 16B stores ----------------
// grid layout (blocks): Wq 8192 | Wk 2048 | Wv 2048 | Wo 8192  (each thread = 8 floats)
__global__ __launch_bounds__(256) void conv_w(
    const float* __restrict__ Wq, const float* __restrict__ Wk,
    const float* __restrict__ Wv, const float* __restrict__ Wo,
    __half* __restrict__ wqkv, __half* __restrict__ wo16)
{
    int b = blockIdx.x;
    const float* W; __half* D; int nq, coff, stride;
    if (b < 8192)        { W = Wq; D = wqkv; nq = 4096 / 8; coff = 0;    stride = QKVD; }
    else if (b < 10240)  { b -= 8192;  W = Wk; D = wqkv; nq = 1024 / 8; coff = 4096; stride = QKVD; }
    else if (b < 12288)  { b -= 10240; W = Wv; D = wqkv; nq = 1024 / 8; coff = 5120; stride = QKVD; }
    else                 { b -= 12288; W = Wo; D = wo16; nq = 4096 / 8; coff = 0;    stride = 4096; }

    int idx = b * 256 + threadIdx.x;        // 8-float chunk index
    int k = idx / nq, nc = (idx - k * nq) << 3;
    const float* src = W + (size_t)k * (nq << 3) + nc;
    float4 a = *(const float4*)src;
    float4 c = *(const float4*)(src + 4);
    uint4 o;
    o.x = pack2h(a.x, a.y);
    o.y = pack2h(a.z, a.w);
    o.z = pack2h(c.x, c.y);
    o.w = pack2h(c.z, c.w);
    *(uint4*)(D + (size_t)k * stride + coff + nc) = o;
}

// ---------------- HMMA fp16 GEMM ----------------
// C[M,N] fp32 = A[M,K] @ B[K,N]  (A row-major K-contig, B row-major N-contig).
// CTA 128x256, 8 warps 2(m) x 4(n), k-chunk 64, 4-stage cp.async, trans-ldsm for B.
#define SWZ64(r, c8) ((r) * 128 + (((c8) ^ ((r) & 7)) << 4))
#define SWZB(r, g)   ((r) * 512 + (((g) ^ ((r) & 7)) << 4))

__global__ __launch_bounds__(256, 1) void gemm_hmma_h1(
    const __half* __restrict__ A, const __half* __restrict__ B,
    float* __restrict__ C, int M, int N, int K)
{
    extern __shared__ char smem[];
    constexpr int TILE_A = 128 * 64 * 2;    // 16 KB
    constexpr int TILE_B = 64 * 256 * 2;    // 32 KB
    constexpr int STAGE  = TILE_A + TILE_B; // 48 KB
    const uint32_t sb = smem_u32(smem);

    const int tid  = threadIdx.x;
    const int wid  = tid >> 5;
    const int lane = tid & 31;
    const int m0 = blockIdx.y * 128;
    const int n0 = blockIdx.x * 256;
    const int wm = (wid >> 2) * 64;
    const int wn = (wid & 3) * 64;
    const int nk = K >> 6;

    const int rl  = lane & 15;
    const int ch  = lane >> 4;

    float acc[4][8][4];
#pragma unroll
    for (int i = 0; i < 4; ++i)
#pragma unroll
        for (int j = 0; j < 8; ++j)
#pragma unroll
            for (int q = 0; q < 4; ++q) acc[i][j][q] = 0.f;

    auto load_stage = [&](int c, int s) {
        const int kb = c * 64;
        const uint32_t st = sb + s * STAGE;
#pragma unroll
        for (int i = 0; i < 4; ++i) {
            int id = tid + i * 256;
            int r = id >> 3, c8 = id & 7;
            cpa16(st + SWZ64(r, c8), A + (size_t)(m0 + r) * K + kb + c8 * 8);
        }
#pragma unroll
        for (int i = 0; i < 8; ++i) {
            int id = tid + i * 256;
            int r = id >> 5, g = id & 31;
            cpa16(st + TILE_A + SWZB(r, g), B + (size_t)(kb + r) * N + n0 + g * 8);
        }
        CP_COMMIT();
    };

    load_stage(0, 0);
    if (nk > 1) load_stage(1, 1);
    if (nk > 2) load_stage(2, 2);

    for (int c = 0; c < nk; ++c) {
        if (c + 2 < nk)      { CP_WAIT2(); }
        else if (c + 1 < nk) { CP_WAIT1(); }
        else                 { CP_WAIT0(); }
        __syncthreads();
        if (c + 3 < nk) load_stage(c + 3, (c + 3) & 3);

        const uint32_t st = sb + (c & 3) * STAGE;
        const uint32_t stb = st + TILE_A;
        const int gb0 = wn >> 3;
#pragma unroll
        for (int ks = 0; ks < 4; ++ks) {
            uint32_t af[4][4];
#pragma unroll
            for (int mt = 0; mt < 4; ++mt) {
                int r = wm + mt * 16 + rl;
                ldsm_x4(af[mt][0], af[mt][1], af[mt][2], af[mt][3],
                        st + SWZ64(r, 2 * ks + ch));
            }
#pragma unroll
            for (int np = 0; np < 4; ++np) {
                uint32_t b0, b1, b2, b3;
                ldsm_x4_t(b0, b1, b2, b3,
                          stb + SWZB(ks * 16 + rl, gb0 + np * 2 + ch));
#pragma unroll
                for (int mt = 0; mt < 4; ++mt) {
                    float* d0 = acc[mt][np * 2];
                    float* d1 = acc[mt][np * 2 + 1];
                    mma_f16(d0[0], d0[1], d0[2], d0[3],
                            af[mt][0], af[mt][1], af[mt][2], af[mt][3], b0, b1);
                    mma_f16(d1[0], d1[1], d1[2], d1[3],
                            af[mt][0], af[mt][1], af[mt][2], af[mt][3], b2, b3);
                }
            }
        }
    }

#pragma unroll
    for (int mt = 0; mt < 4; ++mt) {
#pragma unroll
        for (int nt = 0; nt < 8; ++nt) {
            int rg = m0 + wm + mt * 16 + (lane >> 2);
            int cg = n0 + wn + nt * 8 + (lane & 3) * 2;
            float* d = acc[mt][nt];
            *(float2*)(C + (size_t)rg * N + cg)       = make_float2(d[0], d[1]);
            *(float2*)(C + (size_t)(rg + 8) * N + cg) = make_float2(d[2], d[3]);
        }
    }
}

// ---------------- RoPE + pre-scale + fp16 convert; wide loads/stores ----------------
// thread item = 4 consecutive freqs of one head: 2x float4 loads, 2x 8B stores.
__global__ __launch_bounds__(256) void rope_conv(
    const float* __restrict__ QKV, const int* __restrict__ pos_ids,
    __half* __restrict__ Qh, __half* __restrict__ Kh, __half* __restrict__ Vh)
{
    const int s = blockIdx.x;
    const float scale = 0.08838834764831845f;  // 1/sqrt(128)
    __shared__ float cs[64], sn[64];
    if (threadIdx.x < 64) {
        double invf = exp(-(double)threadIdx.x * (9.210340371976184 / 64.0));
        float ang = (float)((double)pos_ids[s] * invf);
        float c, si;
        sincosf(ang, &si, &c);
        cs[threadIdx.x] = c;
        sn[threadIdx.x] = si;
    }
    __syncthreads();

    // Q: 32 heads x 16 quads = 512 items
#pragma unroll
    for (int it = 0; it < 2; ++it) {
        int item = threadIdx.x + it * 256;
        int head = item >> 4, q4 = (item & 15) << 2;
        size_t bs = (size_t)s * QKVD + head * HD + q4;
        size_t bd = (size_t)s * QDIM + head * HD + q4;
        float4 x0 = *(const float4*)(QKV + bs);
        float4 x1 = *(const float4*)(QKV + bs + 64);
        float c0 = cs[q4], c1 = cs[q4 + 1], c2 = cs[q4 + 2], c3 = cs[q4 + 3];
        float s0 = sn[q4], s1 = sn[q4 + 1], s2 = sn[q4 + 2], s3 = sn[q4 + 3];
        uint2 lo, hi;
        lo.x = pack2h((x0.x * c0 - x1.x * s0) * scale, (x0.y * c1 - x1.y * s1) * scale);
        lo.y = pack2h((x0.z * c2 - x1.z * s2) * scale, (x0.w * c3 - x1.w * s3) * scale);
        hi.x = pack2h((x1.x * c0 + x0.x * s0) * scale, (x1.y * c1 + x0.y * s1) * scale);
        hi.y = pack2h((x1.z * c2 + x0.z * s2) * scale, (x1.w * c3 + x0.w * s3) * scale);
        *(uint2*)(Qh + bd)      = lo;
        *(uint2*)(Qh + bd + 64) = hi;
    }

    // K: 8 heads x 16 quads = 128 items
    if (threadIdx.x < 128) {
        int item = threadIdx.x;
        int head = item >> 4, q4 = (item & 15) << 2;
        size_t bs = (size_t)s * QKVD + QDIM + head * HD + q4;
        size_t bd = (size_t)s * KVDIM + head * HD + q4;
        float4 x0 = *(const float4*)(QKV + bs);
        float4 x1 = *(const float4*)(QKV + bs + 64);
        float c0 = cs[q4], c1 = cs[q4 + 1], c2 = cs[q4 + 2], c3 = cs[q4 + 3];
        float s0 = sn[q4], s1 = sn[q4 + 1], s2 = sn[q4 + 2], s3 = sn[q4 + 3];
        uint2 lo, hi;
        lo.x = pack2h(x0.x * c0 - x1.x * s0, x0.y * c1 - x1.y * s1);
        lo.y = pack2h(x0.z * c2 - x1.z * s2, x0.w * c3 - x1.w * s3);
        hi.x = pack2h(x1.x * c0 + x0.x * s0, x1.y * c1 + x0.y * s1);
        hi.y = pack2h(x1.z * c2 + x0.z * s2, x1.w * c3 + x0.w * s3);
        *(uint2*)(Kh + bd)      = lo;
        *(uint2*)(Kh + bd + 64) = hi;
    }

    // V: 1024 floats, 256 threads x float4 -> 8B store
    {
        const float* src = QKV + (size_t)s * QKVD + QDIM + KVDIM;
        __half* dst = Vh + (size_t)s * KVDIM;
        int j = threadIdx.x * 4;
        float4 a = *(const float4*)(src + j);
        uint2 o;
        o.x = pack2h(a.x, a.y);
        o.y = pack2h(a.z, a.w);
        *(uint2*)(dst + j) = o;
    }
}

// ---------------- HMMA flash attention (causal, k-tile 128) ----------------
#define ASWZ(row, g) ((row) * 256 + (((g) ^ ((row) & 7)) << 4))

__global__ __launch_bounds__(256) void attn_hmma(
    const __half* __restrict__ Qh, const __half* __restrict__ Kh,
    const __half* __restrict__ Vh, __half* __restrict__ AOh)
{
    extern __shared__ char sm[];
    const uint32_t sb = smem_u32(sm);
    constexpr int MTILE = 128 * 128 * 2;    // 32 KB per matrix
    constexpr int STAGE = 2 * MTILE;        // K + V = 64 KB

    const int tid = threadIdx.x, wid = tid >> 5, lane = tid & 31;
    const int h  = blockIdx.y, kh = h >> 2;
    const int bq = gridDim.x - 1 - blockIdx.x;
    const int q0 = bq * 128;
    const int wr = wid * 16;
    const int r  = lane >> 2, c2 = (lane & 3) * 2;
    const int rl = lane & 15, chh = lane >> 4;

    uint32_t qf[8][4];
    {
        const int row0 = q0 + wr + r;
#pragma unroll
        for (int ks = 0; ks < 8; ++ks) {
            int k2 = ks * 16 + c2;
            size_t b00 = (size_t)row0 * QDIM + h * HD + k2;
            size_t b10 = b00 + (size_t)8 * QDIM;
            qf[ks][0] = *(const uint32_t*)(Qh + b00);
            qf[ks][1] = *(const uint32_t*)(Qh + b10);
            qf[ks][2] = *(const uint32_t*)(Qh + b00 + 8);
            qf[ks][3] = *(const uint32_t*)(Qh + b10 + 8);
        }
    }

    float o[16][4];
#pragma unroll
    for (int i = 0; i < 16; ++i)
#pragma unroll
        for (int q = 0; q < 4; ++q) o[i][q] = 0.f;
    float m1 = -1e30f, m2 = -1e30f, l1 = 0.f, l2 = 0.f;

    const int ntiles = bq + 1;

    auto load_kv = [&](int kt, int s) {
        const int k0 = kt * 128;
        const uint32_t st = sb + s * STAGE;
#pragma unroll
        for (int i = 0; i < 8; ++i) {
            int id = tid + i * 256;
            int rw = id >> 4, g = id & 15;
            uint32_t off = ASWZ(rw, g);
            size_t src = (size_t)(k0 + rw) * KVDIM + kh * HD + g * 8;
            cpa16(st + off,         Kh + src);
            cpa16(st + MTILE + off, Vh + src);
        }
        CP_COMMIT();
    };

    load_kv(0, 0);

    for (int kt = 0; kt < ntiles; ++kt) {
        if (kt + 1 < ntiles) { load_kv(kt + 1, (kt + 1) & 1); CP_WAIT1(); }
        else                 { CP_WAIT0(); }
        __syncthreads();

        const uint32_t st = sb + (kt & 1) * STAGE;
        const int k0 = kt * 128;

        float sacc[16][4];
#pragma unroll
        for (int i = 0; i < 16; ++i)
#pragma unroll
            for (int q = 0; q < 4; ++q) sacc[i][q] = 0.f;

#pragma unroll
        for (int ks = 0; ks < 8; ++ks) {
#pragma unroll
            for (int np = 0; np < 8; ++np) {
                uint32_t b0, b1, b2, b3;
                ldsm_x4(b0, b1, b2, b3, st + ASWZ(np * 16 + rl, 2 * ks + chh));
                float* d0 = sacc[np * 2];
                float* d1 = sacc[np * 2 + 1];
                mma_f16(d0[0], d0[1], d0[2], d0[3],
                        qf[ks][0], qf[ks][1], qf[ks][2], qf[ks][3], b0, b2);
                mma_f16(d1[0], d1[1], d1[2], d1[3],
                        qf[ks][0], qf[ks][1], qf[ks][2], qf[ks][3], b1, b3);
            }
        }

        if (k0 + 127 > q0 + wr) {
            const int row1 = q0 + wr + r, row2 = row1 + 8;
#pragma unroll
            for (int nt = 0; nt < 16; ++nt) {
                int col = k0 + nt * 8 + c2;
                if (col     > row1) sacc[nt][0] = -1e30f;
                if (col + 1 > row1) sacc[nt][1] = -1e30f;
                if (col     > row2) sacc[nt][2] = -1e30f;
                if (col + 1 > row2) sacc[nt][3] = -1e30f;
            }
        }

        float mx1 = -1e30f, mx2 = -1e30f;
#pragma unroll
        for (int nt = 0; nt < 16; ++nt) {
            mx1 = fmaxf(mx1, fmaxf(sacc[nt][0], sacc[nt][1]));
            mx2 = fmaxf(mx2, fmaxf(sacc[nt][2], sacc[nt][3]));
        }
        mx1 = fmaxf(mx1, __shfl_xor_sync(0xffffffffu, mx1, 1));
        mx1 = fmaxf(mx1, __shfl_xor_sync(0xffffffffu, mx1, 2));
        mx2 = fmaxf(mx2, __shfl_xor_sync(0xffffffffu, mx2, 1));
        mx2 = fmaxf(mx2, __shfl_xor_sync(0xffffffffu, mx2, 2));
        float nm1 = fmaxf(m1, mx1), nm2 = fmaxf(m2, mx2);
        float cf1 = __expf(m1 - nm1), cf2 = __expf(m2 - nm2);
        m1 = nm1; m2 = nm2;

        float ls1 = 0.f, ls2 = 0.f;
#pragma unroll
        for (int nt = 0; nt < 16; ++nt) {
            sacc[nt][0] = __expf(sacc[nt][0] - nm1);
            sacc[nt][1] = __expf(sacc[nt][1] - nm1);
            sacc[nt][2] = __expf(sacc[nt][2] - nm2);
            sacc[nt][3] = __expf(sacc[nt][3] - nm2);
            ls1 += sacc[nt][0] + sacc[nt][1];
            ls2 += sacc[nt][2] + sacc[nt][3];
        }
        ls1 += __shfl_xor_sync(0xffffffffu, ls1, 1);
        ls1 += __shfl_xor_sync(0xffffffffu, ls1, 2);
        ls2 += __shfl_xor_sync(0xffffffffu, ls2, 1);
        ls2 += __shfl_xor_sync(0xffffffffu, ls2, 2);
        l1 = l1 * cf1 + ls1;
        l2 = l2 * cf2 + ls2;
#pragma unroll
        for (int dt = 0; dt < 16; ++dt) {
            o[dt][0] *= cf1; o[dt][1] *= cf1;
            o[dt][2] *= cf2; o[dt][3] *= cf2;
        }

#pragma unroll
        for (int s = 0; s < 8; ++s) {
            uint32_t ap[4];
#pragma unroll
            for (int half = 0; half < 2; ++half) {
                const float* sv = sacc[2 * s + half];
                ap[2 * half + 0] = pack2h(sv[0], sv[1]);
                ap[2 * half + 1] = pack2h(sv[2], sv[3]);
            }
#pragma unroll
            for (int dg = 0; dg < 8; ++dg) {
                uint32_t v0, v1, v2, v3;
                ldsm_x4_t(v0, v1, v2, v3,
                          st + MTILE + ASWZ(s * 16 + rl, 2 * dg + chh));
                float* d0 = o[2 * dg];
                float* d1 = o[2 * dg + 1];
                mma_f16(d0[0], d0[1], d0[2], d0[3], ap[0], ap[1], ap[2], ap[3], v0, v1);
                mma_f16(d1[0], d1[1], d1[2], d1[3], ap[0], ap[1], ap[2], ap[3], v2, v3);
            }
        }
        __syncthreads();
    }

    const float inv1 = 1.f / l1, inv2 = 1.f / l2;
    const int row1 = q0 + wr + r;
#pragma unroll
    for (int dt = 0; dt < 16; ++dt) {
        size_t c0 = (size_t)row1 * QDIM + h * HD + dt * 8 + c2;
        size_t c1 = c0 + (size_t)8 * QDIM;
        *(uint32_t*)(AOh + c0) = pack2h(o[dt][0] * inv1, o[dt][1] * inv1);
        *(uint32_t*)(AOh + c1) = pack2h(o[dt][2] * inv2, o[dt][3] * inv2);
    }
}

// ---------------- launch ----------------
extern "C" void kernel_launch(void* const* d_in, const int* in_sizes, int n_in,
                              void* d_out, int out_size)
{
    const float* hs   = (const float*)d_in[0];
    const int*   pos  = (const int*)d_in[2];
    const float* Wq   = (const float*)d_in[3];
    const float* Wk   = (const float*)d_in[4];
    const float* Wv   = (const float*)d_in[5];
    const float* Wo   = (const float*)d_in[6];
    float* out = (float*)d_out;

    float* qkvp;
    __half *ah, *aoh, *qhp, *khp, *vhp, *wqkv, *wo16;
    cudaGetSymbolAddress((void**)&qkvp, g_QKV);
    cudaGetSymbolAddress((void**)&ah,   g_Ah);
    cudaGetSymbolAddress((void**)&aoh,  g_AOh);
    cudaGetSymbolAddress((void**)&qhp,  g_Qh);
    cudaGetSymbolAddress((void**)&khp,  g_Kh);
    cudaGetSymbolAddress((void**)&vhp,  g_Vh);
    cudaGetSymbolAddress((void**)&wqkv, g_Wqkv);
    cudaGetSymbolAddress((void**)&wo16, g_Wo16);

    const int gemm_smem = 4 * (128 * 64 * 2 + 64 * 256 * 2);  // 196608
    cudaFuncSetAttribute(gemm_hmma_h1, cudaFuncAttributeMaxDynamicSharedMemorySize, gemm_smem);
    const int attn_smem = 2 * 2 * 128 * 128 * 2;   // 131072
    cudaFuncSetAttribute(attn_hmma, cudaFuncAttributeMaxDynamicSharedMemorySize, attn_smem);

    // converts (wide stores)
    conv_plain<<<SQ * HID / 8 / 256, 256>>>(hs, ah, SQ * HID / 8);
    conv_w<<<20480, 256>>>(Wq, Wk, Wv, Wo, wqkv, wo16);

    // fused QKV projection (N=6144)
    gemm_hmma_h1<<<dim3(QKVD / 256, SQ / 128), 256, gemm_smem>>>(ah, wqkv, qkvp, SQ, QKVD, HID);

    // RoPE + convert Q/K/V to fp16 (single kernel, wide stores)
    rope_conv<<<SQ, 256>>>(qkvp, pos, qhp, khp, vhp);

    // attention (plain fp16 operands, fp32 softmax/accum, k-tile 128)
    attn_hmma<<<dim3(SQ / 128, NH), 256, attn_smem>>>(qhp, khp, vhp, aoh);

    // output projection
    gemm_hmma_h1<<<dim3(HID / 256, SQ / 128), 256, gemm_smem>>>(aoh, wo16, out, SQ, HID, QDIM);
}